// round 7
// baseline (speedup 1.0000x reference)
#include <cuda_runtime.h>
#include <cuda_bf16.h>

// ---------------------------------------------------------------------------
// BasicTransformerBlock (SD-style): self-attn + cross-attn + GEGLU, fp32.
// B=2, S=4096, T=77, DIM=512, H=8, D=64.
// ---------------------------------------------------------------------------

#define BATCH 2
#define SEQ   4096
#define CTXT  77
#define DIM   512
#define NH    8
#define HD    64
#define ROWS  (BATCH * SEQ)      // 8192
#define CROWS (BATCH * CTXT)     // 154

// -------------------------- scratch (static, no allocs) --------------------
__device__ float g_xn[ROWS * DIM];
__device__ float g_q [ROWS * DIM];
__device__ float g_k [ROWS * DIM];
__device__ float g_v [ROWS * DIM];
__device__ float g_at[ROWS * DIM];
__device__ float g_h [ROWS * DIM];
__device__ float g_gg[(size_t)ROWS * 4096];
__device__ float g_ff[(size_t)ROWS * 2048];

// ------------------------------ LayerNorm ----------------------------------
// one block per row, 256 threads, 2 elems/thread (DIM=512)
__global__ void ln_kernel(const float* __restrict__ in,
                          const float* __restrict__ gw,
                          const float* __restrict__ bw,
                          float* __restrict__ out) {
    const int row = blockIdx.x;
    const float* x = in + (size_t)row * DIM;
    const int t = threadIdx.x;

    float v0 = x[t];
    float v1 = x[t + 256];
    float s  = v0 + v1;
    float sq = v0 * v0 + v1 * v1;

    #pragma unroll
    for (int off = 16; off; off >>= 1) {
        s  += __shfl_xor_sync(0xffffffffu, s,  off);
        sq += __shfl_xor_sync(0xffffffffu, sq, off);
    }
    __shared__ float ss[8], sqs[8];
    if ((t & 31) == 0) { ss[t >> 5] = s; sqs[t >> 5] = sq; }
    __syncthreads();
    float S = 0.f, SQ = 0.f;
    #pragma unroll
    for (int w = 0; w < 8; w++) { S += ss[w]; SQ += sqs[w]; }

    const float mean = S * (1.0f / DIM);
    const float var  = SQ * (1.0f / DIM) - mean * mean;
    const float inv  = rsqrtf(var + 1e-5f);

    float* o = out + (size_t)row * DIM;
    o[t]       = (v0 - mean) * inv * gw[t]       + bw[t];
    o[t + 256] = (v1 - mean) * inv * gw[t + 256] + bw[t + 256];
}

// ------------------------------ SGEMM --------------------------------------
// C[M,N] = A[M,K] @ B[K,N]  (+ bias[n]) (+ Res[m,n])
// 128x128 tile, BK=16, 256 threads, 8x8 per thread (strided ownership).
template <bool HAS_BIAS, bool HAS_RES>
__global__ void __launch_bounds__(256)
sgemm_kernel(const float* __restrict__ A, const float* __restrict__ B,
             const float* __restrict__ bias, const float* __restrict__ Res,
             float* __restrict__ C, int M, int N, int K) {
    __shared__ float As[16][132];   // [k][m]  (transposed on store)
    __shared__ float Bs[16][128];   // [k][n]

    const int tid = threadIdx.x;
    const int tx = tid & 15;        // col group
    const int ty = tid >> 4;        // row group
    const int rowBase = blockIdx.y * 128;
    const int colBase = blockIdx.x * 128;

    // A loader mapping: 2 float4 per thread along K
    const int aRow  = tid >> 2;          // 0..63
    const int aCol4 = (tid & 3) << 2;    // 0,4,8,12
    // B loader mapping: 2 float4 per thread along N
    const int bRow  = tid >> 5;          // 0..7
    const int bCol4 = (tid & 31) << 2;   // 0..124

    float acc[8][8];
    #pragma unroll
    for (int r = 0; r < 8; r++)
        #pragma unroll
        for (int c = 0; c < 8; c++) acc[r][c] = 0.f;

    for (int k0 = 0; k0 < K; k0 += 16) {
        // load A tile (transpose to [k][m]), M-guarded
        #pragma unroll
        for (int rr = 0; rr < 2; rr++) {
            const int row = rowBase + aRow + 64 * rr;
            float4 av = make_float4(0.f, 0.f, 0.f, 0.f);
            if (row < M)
                av = *(const float4*)&A[(size_t)row * K + k0 + aCol4];
            As[aCol4 + 0][aRow + 64 * rr] = av.x;
            As[aCol4 + 1][aRow + 64 * rr] = av.y;
            As[aCol4 + 2][aRow + 64 * rr] = av.z;
            As[aCol4 + 3][aRow + 64 * rr] = av.w;
        }
        // load B tile (direct), K%16==0 and N%128==0 guaranteed by launches
        #pragma unroll
        for (int rr = 0; rr < 2; rr++) {
            const int kr = bRow + 8 * rr;
            *(float4*)&Bs[kr][bCol4] =
                *(const float4*)&B[(size_t)(k0 + kr) * N + colBase + bCol4];
        }
        __syncthreads();

        #pragma unroll
        for (int k = 0; k < 16; k++) {
            float a[8], b[8];
            #pragma unroll
            for (int r = 0; r < 8; r++) a[r] = As[k][ty + 16 * r];
            #pragma unroll
            for (int c = 0; c < 8; c++) b[c] = Bs[k][tx + 16 * c];
            #pragma unroll
            for (int r = 0; r < 8; r++)
                #pragma unroll
                for (int c = 0; c < 8; c++)
                    acc[r][c] = fmaf(a[r], b[c], acc[r][c]);
        }
        __syncthreads();
    }

    #pragma unroll
    for (int r = 0; r < 8; r++) {
        const int row = rowBase + ty + 16 * r;
        if (row >= M) continue;
        #pragma unroll
        for (int c = 0; c < 8; c++) {
            const int col = colBase + tx + 16 * c;
            float v = acc[r][c];
            if (HAS_BIAS) v += bias[col];
            if (HAS_RES)  v += Res[(size_t)row * N + col];
            C[(size_t)row * N + col] = v;
        }
    }
}

// --------------------------- Flash self-attention --------------------------
// grid (SEQ/64, B*H), 256 threads. Tile: 64 queries x 64 keys, D=64.
// Dynamic smem: Qt/Kt (d-major, stride 65), Vs (row-major, stride 65), Ps.
__global__ void __launch_bounds__(256)
flash_self_kernel(const float* __restrict__ Q, const float* __restrict__ K,
                  const float* __restrict__ V, float* __restrict__ O) {
    extern __shared__ float smem[];
    float* Qt = smem;                 // [64][65] : Qt[d][i]
    float* Kt = Qt + 64 * 65;         // [64][65] : Kt[d][j]
    float* Vs = Kt + 64 * 65;         // [64][65] : Vs[j][d]
    float* Ps = Vs + 64 * 65;         // [64][65] : Ps[i][j]

    const int bh = blockIdx.y;
    const int b = bh >> 3, h = bh & 7;
    const int q0 = blockIdx.x * 64;
    const int tid = threadIdx.x;
    const int tx = tid & 15, ty = tid >> 4;

    // loader mapping: 4 threads per row, each thread loads 4 float4 (full d=64)
    const int li  = tid >> 2;         // row within tile (0..63)
    const int ldb = (tid & 3) << 2;   // base d (0,4,8,12); chunks add 16

    // load Q tile transposed (coalesced float4 along d) — full 64x64 tile
    {
        const float* qrow = &Q[((size_t)(b * SEQ + q0 + li)) * DIM + h * HD];
        #pragma unroll
        for (int c = 0; c < 4; c++) {
            const int d4 = ldb + 16 * c;
            const float4 qv = *(const float4*)&qrow[d4];
            Qt[(d4 + 0) * 65 + li] = qv.x;
            Qt[(d4 + 1) * 65 + li] = qv.y;
            Qt[(d4 + 2) * 65 + li] = qv.z;
            Qt[(d4 + 3) * 65 + li] = qv.w;
        }
    }

    float m[4], l[4], o[4][4];
    #pragma unroll
    for (int r = 0; r < 4; r++) {
        m[r] = -1e30f; l[r] = 0.f;
        #pragma unroll
        for (int c = 0; c < 4; c++) o[r][c] = 0.f;
    }
    const float scale = 0.125f;   // 1/sqrt(64)

    for (int kt = 0; kt < SEQ; kt += 64) {
        __syncthreads();   // previous iter's GEMM2 done reading Kt/Vs/Ps
        {
            const size_t base = ((size_t)(b * SEQ + kt + li)) * DIM + h * HD;
            #pragma unroll
            for (int c = 0; c < 4; c++) {
                const int d4 = ldb + 16 * c;
                const float4 kv = *(const float4*)&K[base + d4];
                Kt[(d4 + 0) * 65 + li] = kv.x;
                Kt[(d4 + 1) * 65 + li] = kv.y;
                Kt[(d4 + 2) * 65 + li] = kv.z;
                Kt[(d4 + 3) * 65 + li] = kv.w;
                const float4 vv = *(const float4*)&V[base + d4];
                // NOTE: scalar stores — Vs row stride is 65 floats, so a
                // float4 store would be misaligned for odd rows.
                Vs[li * 65 + d4 + 0] = vv.x;
                Vs[li * 65 + d4 + 1] = vv.y;
                Vs[li * 65 + d4 + 2] = vv.z;
                Vs[li * 65 + d4 + 3] = vv.w;
            }
        }
        __syncthreads();

        // GEMM1: S = Q K^T  (4x4 per thread, strided ownership)
        float s[4][4];
        #pragma unroll
        for (int r = 0; r < 4; r++)
            #pragma unroll
            for (int c = 0; c < 4; c++) s[r][c] = 0.f;
        #pragma unroll 16
        for (int d = 0; d < 64; d++) {
            float a[4], bb[4];
            #pragma unroll
            for (int r = 0; r < 4; r++) a[r]  = Qt[d * 65 + ty + 16 * r];
            #pragma unroll
            for (int c = 0; c < 4; c++) bb[c] = Kt[d * 65 + tx + 16 * c];
            #pragma unroll
            for (int r = 0; r < 4; r++)
                #pragma unroll
                for (int c = 0; c < 4; c++)
                    s[r][c] = fmaf(a[r], bb[c], s[r][c]);
        }

        // online softmax per owned row (reduce across tx = lane bits 0..3)
        #pragma unroll
        for (int r = 0; r < 4; r++) {
            float mx = -1e30f;
            #pragma unroll
            for (int c = 0; c < 4; c++) mx = fmaxf(mx, s[r][c] * scale);
            #pragma unroll
            for (int off = 8; off; off >>= 1)
                mx = fmaxf(mx, __shfl_xor_sync(0xffffffffu, mx, off));
            const float mnew  = fmaxf(m[r], mx);
            const float alpha = __expf(m[r] - mnew);
            float rs = 0.f;
            float p[4];
            #pragma unroll
            for (int c = 0; c < 4; c++) {
                p[c] = __expf(s[r][c] * scale - mnew);
                rs += p[c];
            }
            #pragma unroll
            for (int off = 8; off; off >>= 1)
                rs += __shfl_xor_sync(0xffffffffu, rs, off);
            l[r] = l[r] * alpha + rs;
            m[r] = mnew;
            #pragma unroll
            for (int c = 0; c < 4; c++) {
                o[r][c] *= alpha;
                Ps[(ty + 16 * r) * 65 + tx + 16 * c] = p[c];
            }
        }
        __syncthreads();

        // GEMM2: O += P V
        #pragma unroll 16
        for (int j = 0; j < 64; j++) {
            float pp[4], vv[4];
            #pragma unroll
            for (int r = 0; r < 4; r++) pp[r] = Ps[(ty + 16 * r) * 65 + j];
            #pragma unroll
            for (int c = 0; c < 4; c++) vv[c] = Vs[j * 65 + tx + 16 * c];
            #pragma unroll
            for (int r = 0; r < 4; r++)
                #pragma unroll
                for (int c = 0; c < 4; c++)
                    o[r][c] = fmaf(pp[r], vv[c], o[r][c]);
        }
    }

    #pragma unroll
    for (int r = 0; r < 4; r++) {
        const float inv = 1.0f / l[r];
        const int qi = q0 + ty + 16 * r;
        #pragma unroll
        for (int c = 0; c < 4; c++)
            O[((size_t)(b * SEQ + qi)) * DIM + h * HD + tx + 16 * c] = o[r][c] * inv;
    }
}

// --------------------------- Cross attention (T=77) ------------------------
// grid (SEQ/64, B*H), 256 threads = 8 warps; whole K/V for (b,h) in smem;
// each warp handles 8 queries sequentially.
__global__ void __launch_bounds__(256)
cross_attn_kernel(const float* __restrict__ Q, const float* __restrict__ K,
                  const float* __restrict__ V, float* __restrict__ O) {
    __shared__ float Ks[CTXT][65];
    __shared__ float Vs[CTXT][65];

    const int bh = blockIdx.y;
    const int b = bh >> 3, h = bh & 7;
    const int warp = threadIdx.x >> 5, lane = threadIdx.x & 31;

    for (int idx = threadIdx.x; idx < CTXT * HD; idx += 256) {
        const int j = idx >> 6, d = idx & 63;
        const size_t base = ((size_t)(b * CTXT + j)) * DIM + h * HD + d;
        Ks[j][d] = K[base];
        Vs[j][d] = V[base];
    }
    __syncthreads();

    const float scale = 0.125f;
    const int q_base = blockIdx.x * 64 + warp * 8;

    for (int qq = 0; qq < 8; qq++) {
        const int qi = q_base + qq;
        const float* qp = &Q[((size_t)(b * SEQ + qi)) * DIM + h * HD];
        const float q0v = qp[lane];
        const float q1v = qp[lane + 32];

        const int j0 = lane, j1 = lane + 32, j2 = lane + 64;
        float s0 = 0.f, s1 = 0.f, s2 = 0.f;
        #pragma unroll
        for (int d = 0; d < 32; d++) {
            const float qd = __shfl_sync(0xffffffffu, q0v, d);
            s0 = fmaf(qd, Ks[j0][d], s0);
            s1 = fmaf(qd, Ks[j1][d], s1);
            if (j2 < CTXT) s2 = fmaf(qd, Ks[j2][d], s2);
        }
        #pragma unroll
        for (int d = 0; d < 32; d++) {
            const float qd = __shfl_sync(0xffffffffu, q1v, d);
            s0 = fmaf(qd, Ks[j0][d + 32], s0);
            s1 = fmaf(qd, Ks[j1][d + 32], s1);
            if (j2 < CTXT) s2 = fmaf(qd, Ks[j2][d + 32], s2);
        }
        s0 *= scale; s1 *= scale;
        s2 = (j2 < CTXT) ? s2 * scale : -1e30f;

        float mx = fmaxf(fmaxf(s0, s1), s2);
        #pragma unroll
        for (int off = 16; off; off >>= 1)
            mx = fmaxf(mx, __shfl_xor_sync(0xffffffffu, mx, off));

        const float p0 = __expf(s0 - mx);
        const float p1 = __expf(s1 - mx);
        const float p2 = (j2 < CTXT) ? __expf(s2 - mx) : 0.f;
        float sum = p0 + p1 + p2;
        #pragma unroll
        for (int off = 16; off; off >>= 1)
            sum += __shfl_xor_sync(0xffffffffu, sum, off);

        float o0 = 0.f, o1 = 0.f;
        #pragma unroll
        for (int ll = 0; ll < 32; ll++) {
            const float pj = __shfl_sync(0xffffffffu, p0, ll);
            o0 = fmaf(pj, Vs[ll][lane],      o0);
            o1 = fmaf(pj, Vs[ll][lane + 32], o1);
        }
        #pragma unroll
        for (int ll = 0; ll < 32; ll++) {
            const float pj = __shfl_sync(0xffffffffu, p1, ll);
            o0 = fmaf(pj, Vs[32 + ll][lane],      o0);
            o1 = fmaf(pj, Vs[32 + ll][lane + 32], o1);
        }
        #pragma unroll
        for (int ll = 0; ll < 13; ll++) {
            const float pj = __shfl_sync(0xffffffffu, p2, ll);
            o0 = fmaf(pj, Vs[64 + ll][lane],      o0);
            o1 = fmaf(pj, Vs[64 + ll][lane + 32], o1);
        }

        const float inv = 1.0f / sum;
        float* op = &O[((size_t)(b * SEQ + qi)) * DIM + h * HD];
        op[lane]      = o0 * inv;
        op[lane + 32] = o1 * inv;
    }
}

// ------------------------------ GEGLU --------------------------------------
__global__ void geglu_kernel(const float* __restrict__ gg, float* __restrict__ ff) {
    const size_t idx = (size_t)blockIdx.x * 256 + threadIdx.x;   // ROWS*2048 total
    const size_t mrow = idx >> 11;
    const int    n    = (int)(idx & 2047);
    const float y    = gg[mrow * 4096 + n];
    const float gate = gg[mrow * 4096 + 2048 + n];
    const float t = tanhf(gate * 0.7978845608f * (1.0f + 0.044715f * gate * gate));
    ff[idx] = y * 0.5f * gate * (1.0f + t);
}

// ------------------------------ launch -------------------------------------
extern "C" void kernel_launch(void* const* d_in, const int* in_sizes, int n_in,
                              void* d_out, int out_size) {
    (void)in_sizes; (void)n_in; (void)out_size;
    const float* x       = (const float*)d_in[0];
    const float* context = (const float*)d_in[1];
    const float* ln1_g   = (const float*)d_in[2];
    const float* ln1_b   = (const float*)d_in[3];
    const float* wq1     = (const float*)d_in[4];
    const float* wk1     = (const float*)d_in[5];
    const float* wv1     = (const float*)d_in[6];
    const float* wo1     = (const float*)d_in[7];
    const float* bo1     = (const float*)d_in[8];
    const float* ln2_g   = (const float*)d_in[9];
    const float* ln2_b   = (const float*)d_in[10];
    const float* wq2     = (const float*)d_in[11];
    const float* wk2     = (const float*)d_in[12];
    const float* wv2     = (const float*)d_in[13];
    const float* wo2     = (const float*)d_in[14];
    const float* bo2     = (const float*)d_in[15];
    const float* ln3_g   = (const float*)d_in[16];
    const float* ln3_b   = (const float*)d_in[17];
    const float* geglu_w = (const float*)d_in[18];
    const float* geglu_b = (const float*)d_in[19];
    const float* out_w   = (const float*)d_in[20];
    const float* out_b   = (const float*)d_in[21];
    float* out = (float*)d_out;

    float *xn, *q, *k, *v, *at, *h, *gg, *ff;
    cudaGetSymbolAddress((void**)&xn, g_xn);
    cudaGetSymbolAddress((void**)&q,  g_q);
    cudaGetSymbolAddress((void**)&k,  g_k);
    cudaGetSymbolAddress((void**)&v,  g_v);
    cudaGetSymbolAddress((void**)&at, g_at);
    cudaGetSymbolAddress((void**)&h,  g_h);
    cudaGetSymbolAddress((void**)&gg, g_gg);
    cudaGetSymbolAddress((void**)&ff, g_ff);

    const size_t fa_smem = 4 * 64 * 65 * sizeof(float);   // 66,560 B
    cudaFuncSetAttribute(flash_self_kernel,
                         cudaFuncAttributeMaxDynamicSharedMemorySize, (int)fa_smem);

    const dim3 blk(256);
    const dim3 g512(DIM / 128, ROWS / 128);      // (4, 64)
    const dim3 g4096(4096 / 128, ROWS / 128);    // (32, 64)
    const dim3 gctx(DIM / 128, (CROWS + 127) / 128);  // (4, 2)
    const dim3 gattn(SEQ / 64, BATCH * NH);      // (64, 16)

    // ---- stage 1: self-attention ----
    ln_kernel<<<ROWS, blk>>>(x, ln1_g, ln1_b, xn);
    sgemm_kernel<false, false><<<g512, blk>>>(xn, wq1, nullptr, nullptr, q, ROWS, DIM, DIM);
    sgemm_kernel<false, false><<<g512, blk>>>(xn, wk1, nullptr, nullptr, k, ROWS, DIM, DIM);
    sgemm_kernel<false, false><<<g512, blk>>>(xn, wv1, nullptr, nullptr, v, ROWS, DIM, DIM);
    flash_self_kernel<<<gattn, blk, fa_smem>>>(q, k, v, at);
    sgemm_kernel<true, true><<<g512, blk>>>(at, wo1, bo1, x, h, ROWS, DIM, DIM);

    // ---- stage 2: cross-attention ----
    ln_kernel<<<ROWS, blk>>>(h, ln2_g, ln2_b, xn);
    sgemm_kernel<false, false><<<g512, blk>>>(xn, wq2, nullptr, nullptr, q, ROWS, DIM, DIM);
    sgemm_kernel<false, false><<<gctx, blk>>>(context, wk2, nullptr, nullptr, k, CROWS, DIM, DIM);
    sgemm_kernel<false, false><<<gctx, blk>>>(context, wv2, nullptr, nullptr, v, CROWS, DIM, DIM);
    cross_attn_kernel<<<gattn, blk>>>(q, k, v, at);
    sgemm_kernel<true, true><<<g512, blk>>>(at, wo2, bo2, h, h, ROWS, DIM, DIM);

    // ---- stage 3: GEGLU FFN ----
    ln_kernel<<<ROWS, blk>>>(h, ln3_g, ln3_b, xn);
    sgemm_kernel<true, false><<<g4096, blk>>>(xn, geglu_w, geglu_b, nullptr, gg, ROWS, 4096, DIM);
    geglu_kernel<<<(ROWS * 2048) / 256, blk>>>(gg, ff);
    sgemm_kernel<true, true><<<g512, blk>>>(ff, out_w, out_b, h, out, ROWS, DIM, 2048);
}

// round 8
// speedup vs baseline: 1.2986x; 1.2986x over previous
#include <cuda_runtime.h>
#include <cuda_bf16.h>

// ---------------------------------------------------------------------------
// BasicTransformerBlock (SD-style): self-attn + cross-attn + GEGLU, fp32.
// B=2, S=4096, T=77, DIM=512, H=8, D=64.
// ---------------------------------------------------------------------------

#define BATCH 2
#define SEQ   4096
#define CTXT  77
#define DIM   512
#define NH    8
#define HD    64
#define ROWS  (BATCH * SEQ)      // 8192
#define CROWS (BATCH * CTXT)     // 154

// -------------------------- scratch (static, no allocs) --------------------
__device__ float g_xn[ROWS * DIM];
__device__ float g_q [ROWS * DIM];
__device__ float g_k [ROWS * DIM];
__device__ float g_v [ROWS * DIM];
__device__ float g_at[ROWS * DIM];
__device__ float g_h [ROWS * DIM];
__device__ float g_gg[(size_t)ROWS * 4096];
__device__ float g_ff[(size_t)ROWS * 2048];

// ------------------------------ LayerNorm ----------------------------------
__global__ void ln_kernel(const float* __restrict__ in,
                          const float* __restrict__ gw,
                          const float* __restrict__ bw,
                          float* __restrict__ out) {
    const int row = blockIdx.x;
    const float* x = in + (size_t)row * DIM;
    const int t = threadIdx.x;

    float v0 = x[t];
    float v1 = x[t + 256];
    float s  = v0 + v1;
    float sq = v0 * v0 + v1 * v1;

    #pragma unroll
    for (int off = 16; off; off >>= 1) {
        s  += __shfl_xor_sync(0xffffffffu, s,  off);
        sq += __shfl_xor_sync(0xffffffffu, sq, off);
    }
    __shared__ float ss[8], sqs[8];
    if ((t & 31) == 0) { ss[t >> 5] = s; sqs[t >> 5] = sq; }
    __syncthreads();
    float S = 0.f, SQ = 0.f;
    #pragma unroll
    for (int w = 0; w < 8; w++) { S += ss[w]; SQ += sqs[w]; }

    const float mean = S * (1.0f / DIM);
    const float var  = SQ * (1.0f / DIM) - mean * mean;
    const float inv  = rsqrtf(var + 1e-5f);

    float* o = out + (size_t)row * DIM;
    o[t]       = (v0 - mean) * inv * gw[t]       + bw[t];
    o[t + 256] = (v1 - mean) * inv * gw[t + 256] + bw[t + 256];
}

// ------------------------------ SGEMM --------------------------------------
// C[M,N] = A[M,K] @ B[K,N] (+ bias[n]) (+ Res[m,n])
// 128x128 tile, BK=16, 256 threads, 8x8 per thread (blocked 4+4 ownership),
// float4 LDS, 2-stage smem double buffering (one __syncthreads per k-tile).
template <bool HAS_BIAS, bool HAS_RES>
__global__ void __launch_bounds__(256)
sgemm_kernel(const float* __restrict__ A, const float* __restrict__ B,
             const float* __restrict__ bias, const float* __restrict__ Res,
             float* __restrict__ C, int M, int N, int K) {
    __shared__ float As[2][16][132];   // [buf][k][m] (transposed on store)
    __shared__ float Bs[2][16][128];   // [buf][k][n]

    const int tid = threadIdx.x;
    const int rx = tid & 15;           // col group (4+4 cols at rx*4, rx*4+64)
    const int ry = tid >> 4;           // row group (4+4 rows at ry*4, ry*4+64)
    const int rowBase = blockIdx.y * 128;
    const int colBase = blockIdx.x * 128;

    const int aRow = tid >> 2;         // 0..63 (+64 for rr=1)
    const int aCol = (tid & 3) << 2;   // 0,4,8,12
    const int bRow = tid >> 5;         // 0..7 (+8 for rr=1)
    const int bCol = (tid & 31) << 2;  // 0..124

    const int T = K >> 4;

    float4 a_st[2], b_st[2];

    // ---- stage tile 0 ----
    #pragma unroll
    for (int rr = 0; rr < 2; rr++) {
        const int row = rowBase + aRow + 64 * rr;
        a_st[rr] = (row < M) ? *(const float4*)&A[(size_t)row * K + aCol]
                             : make_float4(0.f, 0.f, 0.f, 0.f);
        b_st[rr] = *(const float4*)&B[(size_t)(bRow + 8 * rr) * N + colBase + bCol];
    }
    #pragma unroll
    for (int rr = 0; rr < 2; rr++) {
        As[0][aCol + 0][aRow + 64 * rr] = a_st[rr].x;
        As[0][aCol + 1][aRow + 64 * rr] = a_st[rr].y;
        As[0][aCol + 2][aRow + 64 * rr] = a_st[rr].z;
        As[0][aCol + 3][aRow + 64 * rr] = a_st[rr].w;
        *(float4*)&Bs[0][bRow + 8 * rr][bCol] = b_st[rr];
    }
    __syncthreads();

    float acc[8][8];
    #pragma unroll
    for (int i = 0; i < 8; i++)
        #pragma unroll
        for (int j = 0; j < 8; j++) acc[i][j] = 0.f;

    for (int t = 0; t < T; t++) {
        const int buf = t & 1;
        if (t + 1 < T) {
            const int k0 = (t + 1) << 4;
            #pragma unroll
            for (int rr = 0; rr < 2; rr++) {
                const int row = rowBase + aRow + 64 * rr;
                a_st[rr] = (row < M) ? *(const float4*)&A[(size_t)row * K + k0 + aCol]
                                     : make_float4(0.f, 0.f, 0.f, 0.f);
                b_st[rr] = *(const float4*)&B[(size_t)(k0 + bRow + 8 * rr) * N + colBase + bCol];
            }
        }

        #pragma unroll
        for (int k = 0; k < 16; k++) {
            const float4 a0 = *(const float4*)&As[buf][k][ry * 4];
            const float4 a1 = *(const float4*)&As[buf][k][ry * 4 + 64];
            const float4 b0 = *(const float4*)&Bs[buf][k][rx * 4];
            const float4 b1 = *(const float4*)&Bs[buf][k][rx * 4 + 64];
            const float a[8] = {a0.x, a0.y, a0.z, a0.w, a1.x, a1.y, a1.z, a1.w};
            const float b[8] = {b0.x, b0.y, b0.z, b0.w, b1.x, b1.y, b1.z, b1.w};
            #pragma unroll
            for (int i = 0; i < 8; i++)
                #pragma unroll
                for (int j = 0; j < 8; j++)
                    acc[i][j] = fmaf(a[i], b[j], acc[i][j]);
        }

        if (t + 1 < T) {
            const int nb = buf ^ 1;
            #pragma unroll
            for (int rr = 0; rr < 2; rr++) {
                As[nb][aCol + 0][aRow + 64 * rr] = a_st[rr].x;
                As[nb][aCol + 1][aRow + 64 * rr] = a_st[rr].y;
                As[nb][aCol + 2][aRow + 64 * rr] = a_st[rr].z;
                As[nb][aCol + 3][aRow + 64 * rr] = a_st[rr].w;
                *(float4*)&Bs[nb][bRow + 8 * rr][bCol] = b_st[rr];
            }
            __syncthreads();
        }
    }

    // ---- epilogue (float4 stores) ----
    #pragma unroll
    for (int ii = 0; ii < 2; ii++) {
        #pragma unroll
        for (int i = 0; i < 4; i++) {
            const int row = rowBase + ry * 4 + i + 64 * ii;
            if (row >= M) continue;
            #pragma unroll
            for (int jj = 0; jj < 2; jj++) {
                const int col = colBase + rx * 4 + 64 * jj;
                float4 v = make_float4(acc[4 * ii + i][4 * jj + 0],
                                       acc[4 * ii + i][4 * jj + 1],
                                       acc[4 * ii + i][4 * jj + 2],
                                       acc[4 * ii + i][4 * jj + 3]);
                if (HAS_BIAS) {
                    const float4 bv = *(const float4*)&bias[col];
                    v.x += bv.x; v.y += bv.y; v.z += bv.z; v.w += bv.w;
                }
                if (HAS_RES) {
                    const float4 rv = *(const float4*)&Res[(size_t)row * N + col];
                    v.x += rv.x; v.y += rv.y; v.z += rv.z; v.w += rv.w;
                }
                *(float4*)&C[(size_t)row * N + col] = v;
            }
        }
    }
}

// --------------------------- Flash self-attention --------------------------
// grid (SEQ/128, B*H), 256 threads. Tile: 128 queries x 64 keys, D=64.
// Microtile 8(q)x4(k) -> 2.67 FMA per smem float (vs 2.0 before).
// smem: Qt[d][i] s=132, Kt[d][j] s=68, Vs[j][d] s=68, Ps[i][j] s=68. 103.4 KB.
__global__ void __launch_bounds__(256)
flash_self_kernel(const float* __restrict__ Q, const float* __restrict__ K,
                  const float* __restrict__ V, float* __restrict__ O) {
    extern __shared__ float smem[];
    float* Qt = smem;                  // [64][132] : Qt[d][i], i in 0..127
    float* Kt = Qt + 64 * 132;         // [64][68]  : Kt[d][j]
    float* Vs = Kt + 64 * 68;          // [64][68]  : Vs[j][d]
    float* Ps = Vs + 64 * 68;          // [128][68] : Ps[i][j]

    const int bh = blockIdx.y;
    const int b = bh >> 3, h = bh & 7;
    const int q0 = blockIdx.x * 128;
    const int tid = threadIdx.x;
    const int tx = tid & 15, ty = tid >> 4;

    // ---- load Q tile (128 rows), transposed, scale folded in ----
    {
        const int li = tid >> 1;              // 0..127
        const int db = (tid & 1) * 32;        // 0 or 32
        const float* qrow = &Q[((size_t)(b * SEQ + q0 + li)) * DIM + h * HD];
        #pragma unroll
        for (int c = 0; c < 8; c++) {
            const int d4 = db + 4 * c;
            const float4 qv = *(const float4*)&qrow[d4];
            Qt[(d4 + 0) * 132 + li] = qv.x * 0.125f;
            Qt[(d4 + 1) * 132 + li] = qv.y * 0.125f;
            Qt[(d4 + 2) * 132 + li] = qv.z * 0.125f;
            Qt[(d4 + 3) * 132 + li] = qv.w * 0.125f;
        }
    }

    float m[8], l[8], o[8][4];
    #pragma unroll
    for (int r = 0; r < 8; r++) {
        m[r] = -1e30f; l[r] = 0.f;
        #pragma unroll
        for (int c = 0; c < 4; c++) o[r][c] = 0.f;
    }

    for (int kt = 0; kt < SEQ; kt += 64) {
        __syncthreads();    // previous iter's GEMM2 done with Kt/Vs/Ps
        // ---- load K/V tile (64 rows) ----
        {
            const int li = tid >> 2;           // 0..63
            const int db = (tid & 3) << 2;     // 0,4,8,12
            const size_t base = ((size_t)(b * SEQ + kt + li)) * DIM + h * HD;
            #pragma unroll
            for (int c = 0; c < 4; c++) {
                const int d4 = db + 16 * c;
                const float4 kv = *(const float4*)&K[base + d4];
                Kt[(d4 + 0) * 68 + li] = kv.x;
                Kt[(d4 + 1) * 68 + li] = kv.y;
                Kt[(d4 + 2) * 68 + li] = kv.z;
                Kt[(d4 + 3) * 68 + li] = kv.w;
                const float4 vv = *(const float4*)&V[base + d4];
                *(float4*)&Vs[li * 68 + d4] = vv;   // 68*4=272 B ≡ 0 mod 16 ✓
            }
        }
        __syncthreads();

        // ---- GEMM1: S = (Q*scale) K^T, 8x4 per thread ----
        float s[8][4];
        #pragma unroll
        for (int r = 0; r < 8; r++)
            #pragma unroll
            for (int c = 0; c < 4; c++) s[r][c] = 0.f;

        #pragma unroll 16
        for (int d = 0; d < 64; d++) {
            const float4 a0 = *(const float4*)&Qt[d * 132 + ty * 4];
            const float4 a1 = *(const float4*)&Qt[d * 132 + ty * 4 + 64];
            const float4 bb = *(const float4*)&Kt[d * 68 + tx * 4];
            const float a[8] = {a0.x, a0.y, a0.z, a0.w, a1.x, a1.y, a1.z, a1.w};
            #pragma unroll
            for (int r = 0; r < 8; r++) {
                s[r][0] = fmaf(a[r], bb.x, s[r][0]);
                s[r][1] = fmaf(a[r], bb.y, s[r][1]);
                s[r][2] = fmaf(a[r], bb.z, s[r][2]);
                s[r][3] = fmaf(a[r], bb.w, s[r][3]);
            }
        }

        // ---- online softmax (reduce across tx = 16-lane half-warps) ----
        #pragma unroll
        for (int r = 0; r < 8; r++) {
            float mx = fmaxf(fmaxf(s[r][0], s[r][1]), fmaxf(s[r][2], s[r][3]));
            #pragma unroll
            for (int off = 8; off; off >>= 1)
                mx = fmaxf(mx, __shfl_xor_sync(0xffffffffu, mx, off));
            const float mnew  = fmaxf(m[r], mx);
            const float alpha = __expf(m[r] - mnew);
            float p0 = __expf(s[r][0] - mnew);
            float p1 = __expf(s[r][1] - mnew);
            float p2 = __expf(s[r][2] - mnew);
            float p3 = __expf(s[r][3] - mnew);
            float rs = p0 + p1 + p2 + p3;
            #pragma unroll
            for (int off = 8; off; off >>= 1)
                rs += __shfl_xor_sync(0xffffffffu, rs, off);
            l[r] = l[r] * alpha + rs;
            m[r] = mnew;
            o[r][0] *= alpha; o[r][1] *= alpha; o[r][2] *= alpha; o[r][3] *= alpha;
            const int i = ty * 4 + ((r < 4) ? r : (60 + r));   // rows ty*4+0..3, +64..67
            *(float4*)&Ps[i * 68 + tx * 4] = make_float4(p0, p1, p2, p3);
        }
        __syncthreads();

        // ---- GEMM2: O += P V, thread owns d-cols tx*4..tx*4+3 ----
        #pragma unroll 8
        for (int j = 0; j < 64; j++) {
            const float4 vv = *(const float4*)&Vs[j * 68 + tx * 4];
            float p[8];
            #pragma unroll
            for (int r = 0; r < 8; r++) {
                const int i = ty * 4 + ((r < 4) ? r : (60 + r));
                p[r] = Ps[i * 68 + j];
            }
            #pragma unroll
            for (int r = 0; r < 8; r++) {
                o[r][0] = fmaf(p[r], vv.x, o[r][0]);
                o[r][1] = fmaf(p[r], vv.y, o[r][1]);
                o[r][2] = fmaf(p[r], vv.z, o[r][2]);
                o[r][3] = fmaf(p[r], vv.w, o[r][3]);
            }
        }
    }

    // ---- epilogue ----
    #pragma unroll
    for (int r = 0; r < 8; r++) {
        const float inv = 1.0f / l[r];
        const int i = ty * 4 + ((r < 4) ? r : (60 + r));
        float4 ov = make_float4(o[r][0] * inv, o[r][1] * inv,
                                o[r][2] * inv, o[r][3] * inv);
        *(float4*)&O[((size_t)(b * SEQ + q0 + i)) * DIM + h * HD + tx * 4] = ov;
    }
}

// --------------------------- Cross attention (T=77) ------------------------
__global__ void __launch_bounds__(256)
cross_attn_kernel(const float* __restrict__ Q, const float* __restrict__ K,
                  const float* __restrict__ V, float* __restrict__ O) {
    __shared__ float Ks[CTXT][65];
    __shared__ float Vs[CTXT][65];

    const int bh = blockIdx.y;
    const int b = bh >> 3, h = bh & 7;
    const int warp = threadIdx.x >> 5, lane = threadIdx.x & 31;

    for (int idx = threadIdx.x; idx < CTXT * HD; idx += 256) {
        const int j = idx >> 6, d = idx & 63;
        const size_t base = ((size_t)(b * CTXT + j)) * DIM + h * HD + d;
        Ks[j][d] = K[base];
        Vs[j][d] = V[base];
    }
    __syncthreads();

    const float scale = 0.125f;
    const int q_base = blockIdx.x * 64 + warp * 8;

    for (int qq = 0; qq < 8; qq++) {
        const int qi = q_base + qq;
        const float* qp = &Q[((size_t)(b * SEQ + qi)) * DIM + h * HD];
        const float q0v = qp[lane];
        const float q1v = qp[lane + 32];

        const int j0 = lane, j1 = lane + 32, j2 = lane + 64;
        float s0 = 0.f, s1 = 0.f, s2 = 0.f;
        #pragma unroll
        for (int d = 0; d < 32; d++) {
            const float qd = __shfl_sync(0xffffffffu, q0v, d);
            s0 = fmaf(qd, Ks[j0][d], s0);
            s1 = fmaf(qd, Ks[j1][d], s1);
            if (j2 < CTXT) s2 = fmaf(qd, Ks[j2][d], s2);
        }
        #pragma unroll
        for (int d = 0; d < 32; d++) {
            const float qd = __shfl_sync(0xffffffffu, q1v, d);
            s0 = fmaf(qd, Ks[j0][d + 32], s0);
            s1 = fmaf(qd, Ks[j1][d + 32], s1);
            if (j2 < CTXT) s2 = fmaf(qd, Ks[j2][d + 32], s2);
        }
        s0 *= scale; s1 *= scale;
        s2 = (j2 < CTXT) ? s2 * scale : -1e30f;

        float mx = fmaxf(fmaxf(s0, s1), s2);
        #pragma unroll
        for (int off = 16; off; off >>= 1)
            mx = fmaxf(mx, __shfl_xor_sync(0xffffffffu, mx, off));

        const float p0 = __expf(s0 - mx);
        const float p1 = __expf(s1 - mx);
        const float p2 = (j2 < CTXT) ? __expf(s2 - mx) : 0.f;
        float sum = p0 + p1 + p2;
        #pragma unroll
        for (int off = 16; off; off >>= 1)
            sum += __shfl_xor_sync(0xffffffffu, sum, off);

        float o0 = 0.f, o1 = 0.f;
        #pragma unroll
        for (int ll = 0; ll < 32; ll++) {
            const float pj = __shfl_sync(0xffffffffu, p0, ll);
            o0 = fmaf(pj, Vs[ll][lane],      o0);
            o1 = fmaf(pj, Vs[ll][lane + 32], o1);
        }
        #pragma unroll
        for (int ll = 0; ll < 32; ll++) {
            const float pj = __shfl_sync(0xffffffffu, p1, ll);
            o0 = fmaf(pj, Vs[32 + ll][lane],      o0);
            o1 = fmaf(pj, Vs[32 + ll][lane + 32], o1);
        }
        #pragma unroll
        for (int ll = 0; ll < 13; ll++) {
            const float pj = __shfl_sync(0xffffffffu, p2, ll);
            o0 = fmaf(pj, Vs[64 + ll][lane],      o0);
            o1 = fmaf(pj, Vs[64 + ll][lane + 32], o1);
        }

        const float inv = 1.0f / sum;
        float* op = &O[((size_t)(b * SEQ + qi)) * DIM + h * HD];
        op[lane]      = o0 * inv;
        op[lane + 32] = o1 * inv;
    }
}

// ------------------------------ GEGLU --------------------------------------
__global__ void geglu_kernel(const float* __restrict__ gg, float* __restrict__ ff) {
    const size_t idx = (size_t)blockIdx.x * 256 + threadIdx.x;   // ROWS*2048 total
    const size_t mrow = idx >> 11;
    const int    n    = (int)(idx & 2047);
    const float y    = gg[mrow * 4096 + n];
    const float gate = gg[mrow * 4096 + 2048 + n];
    const float t = tanhf(gate * 0.7978845608f * (1.0f + 0.044715f * gate * gate));
    ff[idx] = y * 0.5f * gate * (1.0f + t);
}

// ------------------------------ launch -------------------------------------
extern "C" void kernel_launch(void* const* d_in, const int* in_sizes, int n_in,
                              void* d_out, int out_size) {
    (void)in_sizes; (void)n_in; (void)out_size;
    const float* x       = (const float*)d_in[0];
    const float* context = (const float*)d_in[1];
    const float* ln1_g   = (const float*)d_in[2];
    const float* ln1_b   = (const float*)d_in[3];
    const float* wq1     = (const float*)d_in[4];
    const float* wk1     = (const float*)d_in[5];
    const float* wv1     = (const float*)d_in[6];
    const float* wo1     = (const float*)d_in[7];
    const float* bo1     = (const float*)d_in[8];
    const float* ln2_g   = (const float*)d_in[9];
    const float* ln2_b   = (const float*)d_in[10];
    const float* wq2     = (const float*)d_in[11];
    const float* wk2     = (const float*)d_in[12];
    const float* wv2     = (const float*)d_in[13];
    const float* wo2     = (const float*)d_in[14];
    const float* bo2     = (const float*)d_in[15];
    const float* ln3_g   = (const float*)d_in[16];
    const float* ln3_b   = (const float*)d_in[17];
    const float* geglu_w = (const float*)d_in[18];
    const float* geglu_b = (const float*)d_in[19];
    const float* out_w   = (const float*)d_in[20];
    const float* out_b   = (const float*)d_in[21];
    float* out = (float*)d_out;

    float *xn, *q, *k, *v, *at, *h, *gg, *ff;
    cudaGetSymbolAddress((void**)&xn, g_xn);
    cudaGetSymbolAddress((void**)&q,  g_q);
    cudaGetSymbolAddress((void**)&k,  g_k);
    cudaGetSymbolAddress((void**)&v,  g_v);
    cudaGetSymbolAddress((void**)&at, g_at);
    cudaGetSymbolAddress((void**)&h,  g_h);
    cudaGetSymbolAddress((void**)&gg, g_gg);
    cudaGetSymbolAddress((void**)&ff, g_ff);

    // Qt 64*132 + Kt 64*68 + Vs 64*68 + Ps 128*68 = 25856 floats = 103424 B
    const size_t fa_smem = (64 * 132 + 64 * 68 + 64 * 68 + 128 * 68) * sizeof(float);
    cudaFuncSetAttribute(flash_self_kernel,
                         cudaFuncAttributeMaxDynamicSharedMemorySize, (int)fa_smem);

    const dim3 blk(256);
    const dim3 g512(DIM / 128, ROWS / 128);          // (4, 64)
    const dim3 g4096(4096 / 128, ROWS / 128);        // (32, 64)
    const dim3 gctx(DIM / 128, (CROWS + 127) / 128); // (4, 2)
    const dim3 gattn(SEQ / 128, BATCH * NH);         // (32, 16)
    const dim3 gxattn(SEQ / 64, BATCH * NH);         // (64, 16)

    // ---- stage 1: self-attention ----
    ln_kernel<<<ROWS, blk>>>(x, ln1_g, ln1_b, xn);
    sgemm_kernel<false, false><<<g512, blk>>>(xn, wq1, nullptr, nullptr, q, ROWS, DIM, DIM);
    sgemm_kernel<false, false><<<g512, blk>>>(xn, wk1, nullptr, nullptr, k, ROWS, DIM, DIM);
    sgemm_kernel<false, false><<<g512, blk>>>(xn, wv1, nullptr, nullptr, v, ROWS, DIM, DIM);
    flash_self_kernel<<<gattn, blk, fa_smem>>>(q, k, v, at);
    sgemm_kernel<true, true><<<g512, blk>>>(at, wo1, bo1, x, h, ROWS, DIM, DIM);

    // ---- stage 2: cross-attention ----
    ln_kernel<<<ROWS, blk>>>(h, ln2_g, ln2_b, xn);
    sgemm_kernel<false, false><<<g512, blk>>>(xn, wq2, nullptr, nullptr, q, ROWS, DIM, DIM);
    sgemm_kernel<false, false><<<gctx, blk>>>(context, wk2, nullptr, nullptr, k, CROWS, DIM, DIM);
    sgemm_kernel<false, false><<<gctx, blk>>>(context, wv2, nullptr, nullptr, v, CROWS, DIM, DIM);
    cross_attn_kernel<<<gxattn, blk>>>(q, k, v, at);
    sgemm_kernel<true, true><<<g512, blk>>>(at, wo2, bo2, h, h, ROWS, DIM, DIM);

    // ---- stage 3: GEGLU FFN ----
    ln_kernel<<<ROWS, blk>>>(h, ln3_g, ln3_b, xn);
    sgemm_kernel<true, false><<<g4096, blk>>>(xn, geglu_w, geglu_b, nullptr, gg, ROWS, 4096, DIM);
    geglu_kernel<<<(ROWS * 2048) / 256, blk>>>(gg, ff);
    sgemm_kernel<true, true><<<g512, blk>>>(ff, out_w, out_b, h, out, ROWS, DIM, 2048);
}

// round 9
// speedup vs baseline: 1.5953x; 1.2284x over previous
#include <cuda_runtime.h>
#include <cuda_bf16.h>
#include <cstdint>

// ---------------------------------------------------------------------------
// BasicTransformerBlock (SD-style): self-attn + cross-attn + GEGLU.
// Dense GEMMs on tensor cores (tf32 mma.sync, fp32 accum); attention fp32.
// B=2, S=4096, T=77, DIM=512, H=8, D=64.
// ---------------------------------------------------------------------------

#define BATCH 2
#define SEQ   4096
#define CTXT  77
#define DIM   512
#define NH    8
#define HD    64
#define ROWS  (BATCH * SEQ)      // 8192
#define CROWS (BATCH * CTXT)     // 154

// -------------------------- scratch (static, no allocs) --------------------
__device__ float g_xn[ROWS * DIM];
__device__ float g_q [ROWS * DIM];
__device__ float g_k [ROWS * DIM];
__device__ float g_v [ROWS * DIM];
__device__ float g_at[ROWS * DIM];
__device__ float g_h [ROWS * DIM];
__device__ float g_gg[(size_t)ROWS * 4096];
__device__ float g_ff[(size_t)ROWS * 2048];

// ------------------------------ LayerNorm ----------------------------------
__global__ void ln_kernel(const float* __restrict__ in,
                          const float* __restrict__ gw,
                          const float* __restrict__ bw,
                          float* __restrict__ out) {
    const int row = blockIdx.x;
    const float* x = in + (size_t)row * DIM;
    const int t = threadIdx.x;

    float v0 = x[t];
    float v1 = x[t + 256];
    float s  = v0 + v1;
    float sq = v0 * v0 + v1 * v1;

    #pragma unroll
    for (int off = 16; off; off >>= 1) {
        s  += __shfl_xor_sync(0xffffffffu, s,  off);
        sq += __shfl_xor_sync(0xffffffffu, sq, off);
    }
    __shared__ float ss[8], sqs[8];
    if ((t & 31) == 0) { ss[t >> 5] = s; sqs[t >> 5] = sq; }
    __syncthreads();
    float S = 0.f, SQ = 0.f;
    #pragma unroll
    for (int w = 0; w < 8; w++) { S += ss[w]; SQ += sqs[w]; }

    const float mean = S * (1.0f / DIM);
    const float var  = SQ * (1.0f / DIM) - mean * mean;
    const float inv  = rsqrtf(var + 1e-5f);

    float* o = out + (size_t)row * DIM;
    o[t]       = (v0 - mean) * inv * gw[t]       + bw[t];
    o[t + 256] = (v1 - mean) * inv * gw[t + 256] + bw[t + 256];
}

// ---------------------- TF32 tensor-core GEMM ------------------------------
// C[M,N] = A[M,K] @ B[K,N] (+ bias[n]) (+ Res[m,n])
// 128x128x32 tile, 256 threads = 8 warps (2 row x 4 col), warp tile 64x32,
// mma.sync.m16n8k8.tf32, double-buffered smem, conflict-free frag loads.
__device__ __forceinline__ uint32_t f2tf32(float x) {
    uint32_t r;
    asm("cvt.rna.tf32.f32 %0, %1;" : "=r"(r) : "f"(x));
    return r;
}

#define APAD 36    // bank = 4*g + tg  -> 32 distinct banks
#define BPAD 136   // bank = 8*tg + g  -> 32 distinct banks

template <bool HAS_BIAS, bool HAS_RES>
__global__ void __launch_bounds__(256)
tgemm_kernel(const float* __restrict__ A, const float* __restrict__ B,
             const float* __restrict__ bias, const float* __restrict__ Res,
             float* __restrict__ C, int M, int N, int K) {
    __shared__ uint32_t As[2][128 * APAD];   // [m][k], tf32 bit patterns
    __shared__ uint32_t Bs[2][32 * BPAD];    // [k][n]

    const int tid  = threadIdx.x;
    const int lane = tid & 31;
    const int wid  = tid >> 5;
    const int wr   = wid >> 2;       // warp row 0..1 (64 rows each)
    const int wc   = wid & 3;        // warp col 0..3 (32 cols each)
    const int g    = lane >> 2;      // group id 0..7
    const int tg   = lane & 3;       // thread-in-group 0..3

    const int rowBase = blockIdx.y * 128;
    const int colBase = blockIdx.x * 128;

    // loaders: A row = tid>>1 (0..127), 16 cols at (tid&1)*16
    const int aRow = tid >> 1;
    const int aCol = (tid & 1) << 4;
    // B: k-row = tid>>3 (0..31), 16 cols at (tid&7)*16
    const int bRow = tid >> 3;
    const int bCol = (tid & 7) << 4;

    const int T = K >> 5;

    float4 a_st[4], b_st[4];

    // ---- stage tile 0 ----
    {
        const int grow = rowBase + aRow;
        #pragma unroll
        for (int i = 0; i < 4; i++) {
            a_st[i] = (grow < M) ? *(const float4*)&A[(size_t)grow * K + aCol + 4 * i]
                                 : make_float4(0.f, 0.f, 0.f, 0.f);
            b_st[i] = *(const float4*)&B[(size_t)bRow * N + colBase + bCol + 4 * i];
        }
        #pragma unroll
        for (int i = 0; i < 4; i++) {
            uint4 av = make_uint4(f2tf32(a_st[i].x), f2tf32(a_st[i].y),
                                  f2tf32(a_st[i].z), f2tf32(a_st[i].w));
            *(uint4*)&As[0][aRow * APAD + aCol + 4 * i] = av;
            uint4 bv = make_uint4(f2tf32(b_st[i].x), f2tf32(b_st[i].y),
                                  f2tf32(b_st[i].z), f2tf32(b_st[i].w));
            *(uint4*)&Bs[0][bRow * BPAD + bCol + 4 * i] = bv;
        }
    }
    __syncthreads();

    float acc[4][4][4];   // [mf][nf][c]
    #pragma unroll
    for (int mf = 0; mf < 4; mf++)
        #pragma unroll
        for (int nf = 0; nf < 4; nf++)
            #pragma unroll
            for (int c = 0; c < 4; c++) acc[mf][nf][c] = 0.f;

    for (int t = 0; t < T; t++) {
        const int buf = t & 1;
        if (t + 1 < T) {
            const int k0 = (t + 1) << 5;
            const int grow = rowBase + aRow;
            #pragma unroll
            for (int i = 0; i < 4; i++) {
                a_st[i] = (grow < M) ? *(const float4*)&A[(size_t)grow * K + k0 + aCol + 4 * i]
                                     : make_float4(0.f, 0.f, 0.f, 0.f);
                b_st[i] = *(const float4*)&B[(size_t)(k0 + bRow) * N + colBase + bCol + 4 * i];
            }
        }

        const uint32_t* as = &As[buf][0];
        const uint32_t* bs = &Bs[buf][0];

        #pragma unroll
        for (int ks = 0; ks < 4; ks++) {
            const int k0 = ks * 8;
            uint32_t afr[4][4], bfr[4][2];
            #pragma unroll
            for (int mf = 0; mf < 4; mf++) {
                const int r0 = (wr * 64 + mf * 16 + g) * APAD + k0 + tg;
                afr[mf][0] = as[r0];
                afr[mf][1] = as[r0 + 8 * APAD];
                afr[mf][2] = as[r0 + 4];
                afr[mf][3] = as[r0 + 8 * APAD + 4];
            }
            #pragma unroll
            for (int nf = 0; nf < 4; nf++) {
                const int c0 = (k0 + tg) * BPAD + wc * 32 + nf * 8 + g;
                bfr[nf][0] = bs[c0];
                bfr[nf][1] = bs[c0 + 4 * BPAD];
            }
            #pragma unroll
            for (int mf = 0; mf < 4; mf++)
                #pragma unroll
                for (int nf = 0; nf < 4; nf++) {
                    asm volatile(
                        "mma.sync.aligned.m16n8k8.row.col.f32.tf32.tf32.f32 "
                        "{%0,%1,%2,%3}, {%4,%5,%6,%7}, {%8,%9}, {%0,%1,%2,%3};\n"
                        : "+f"(acc[mf][nf][0]), "+f"(acc[mf][nf][1]),
                          "+f"(acc[mf][nf][2]), "+f"(acc[mf][nf][3])
                        : "r"(afr[mf][0]), "r"(afr[mf][1]),
                          "r"(afr[mf][2]), "r"(afr[mf][3]),
                          "r"(bfr[nf][0]), "r"(bfr[nf][1]));
                }
        }

        if (t + 1 < T) {
            const int nb = buf ^ 1;
            #pragma unroll
            for (int i = 0; i < 4; i++) {
                uint4 av = make_uint4(f2tf32(a_st[i].x), f2tf32(a_st[i].y),
                                      f2tf32(a_st[i].z), f2tf32(a_st[i].w));
                *(uint4*)&As[nb][aRow * APAD + aCol + 4 * i] = av;
                uint4 bv = make_uint4(f2tf32(b_st[i].x), f2tf32(b_st[i].y),
                                      f2tf32(b_st[i].z), f2tf32(b_st[i].w));
                *(uint4*)&Bs[nb][bRow * BPAD + bCol + 4 * i] = bv;
            }
            __syncthreads();
        }
    }

    // ---- epilogue: c0/c1 -> (row g, col 2tg,2tg+1), c2/c3 -> row g+8 ----
    #pragma unroll
    for (int mf = 0; mf < 4; mf++) {
        #pragma unroll
        for (int half = 0; half < 2; half++) {
            const int row = rowBase + wr * 64 + mf * 16 + g + 8 * half;
            if (row >= M) continue;
            #pragma unroll
            for (int nf = 0; nf < 4; nf++) {
                const int col = colBase + wc * 32 + nf * 8 + 2 * tg;
                float2 v = half ? make_float2(acc[mf][nf][2], acc[mf][nf][3])
                                : make_float2(acc[mf][nf][0], acc[mf][nf][1]);
                if (HAS_BIAS) {
                    const float2 bv = *(const float2*)&bias[col];
                    v.x += bv.x; v.y += bv.y;
                }
                if (HAS_RES) {
                    const float2 rv = *(const float2*)&Res[(size_t)row * N + col];
                    v.x += rv.x; v.y += rv.y;
                }
                *(float2*)&C[(size_t)row * N + col] = v;
            }
        }
    }
}

// --------------------------- Flash self-attention --------------------------
// grid (SEQ/128, B*H), 256 threads. Tile: 128 queries x 64 keys, D=64.
__global__ void __launch_bounds__(256)
flash_self_kernel(const float* __restrict__ Q, const float* __restrict__ K,
                  const float* __restrict__ V, float* __restrict__ O) {
    extern __shared__ float smem[];
    float* Qt = smem;                  // [64][132] : Qt[d][i], i in 0..127
    float* Kt = Qt + 64 * 132;         // [64][68]  : Kt[d][j]
    float* Vs = Kt + 64 * 68;          // [64][68]  : Vs[j][d]
    float* Ps = Vs + 64 * 68;          // [128][68] : Ps[i][j]

    const int bh = blockIdx.y;
    const int b = bh >> 3, h = bh & 7;
    const int q0 = blockIdx.x * 128;
    const int tid = threadIdx.x;
    const int tx = tid & 15, ty = tid >> 4;

    {
        const int li = tid >> 1;
        const int db = (tid & 1) * 32;
        const float* qrow = &Q[((size_t)(b * SEQ + q0 + li)) * DIM + h * HD];
        #pragma unroll
        for (int c = 0; c < 8; c++) {
            const int d4 = db + 4 * c;
            const float4 qv = *(const float4*)&qrow[d4];
            Qt[(d4 + 0) * 132 + li] = qv.x * 0.125f;
            Qt[(d4 + 1) * 132 + li] = qv.y * 0.125f;
            Qt[(d4 + 2) * 132 + li] = qv.z * 0.125f;
            Qt[(d4 + 3) * 132 + li] = qv.w * 0.125f;
        }
    }

    float m[8], l[8], o[8][4];
    #pragma unroll
    for (int r = 0; r < 8; r++) {
        m[r] = -1e30f; l[r] = 0.f;
        #pragma unroll
        for (int c = 0; c < 4; c++) o[r][c] = 0.f;
    }

    for (int kt = 0; kt < SEQ; kt += 64) {
        __syncthreads();
        {
            const int li = tid >> 2;
            const int db = (tid & 3) << 2;
            const size_t base = ((size_t)(b * SEQ + kt + li)) * DIM + h * HD;
            #pragma unroll
            for (int c = 0; c < 4; c++) {
                const int d4 = db + 16 * c;
                const float4 kv = *(const float4*)&K[base + d4];
                Kt[(d4 + 0) * 68 + li] = kv.x;
                Kt[(d4 + 1) * 68 + li] = kv.y;
                Kt[(d4 + 2) * 68 + li] = kv.z;
                Kt[(d4 + 3) * 68 + li] = kv.w;
                const float4 vv = *(const float4*)&V[base + d4];
                *(float4*)&Vs[li * 68 + d4] = vv;
            }
        }
        __syncthreads();

        float s[8][4];
        #pragma unroll
        for (int r = 0; r < 8; r++)
            #pragma unroll
            for (int c = 0; c < 4; c++) s[r][c] = 0.f;

        #pragma unroll 16
        for (int d = 0; d < 64; d++) {
            const float4 a0 = *(const float4*)&Qt[d * 132 + ty * 4];
            const float4 a1 = *(const float4*)&Qt[d * 132 + ty * 4 + 64];
            const float4 bb = *(const float4*)&Kt[d * 68 + tx * 4];
            const float a[8] = {a0.x, a0.y, a0.z, a0.w, a1.x, a1.y, a1.z, a1.w};
            #pragma unroll
            for (int r = 0; r < 8; r++) {
                s[r][0] = fmaf(a[r], bb.x, s[r][0]);
                s[r][1] = fmaf(a[r], bb.y, s[r][1]);
                s[r][2] = fmaf(a[r], bb.z, s[r][2]);
                s[r][3] = fmaf(a[r], bb.w, s[r][3]);
            }
        }

        #pragma unroll
        for (int r = 0; r < 8; r++) {
            float mx = fmaxf(fmaxf(s[r][0], s[r][1]), fmaxf(s[r][2], s[r][3]));
            #pragma unroll
            for (int off = 8; off; off >>= 1)
                mx = fmaxf(mx, __shfl_xor_sync(0xffffffffu, mx, off));
            const float mnew  = fmaxf(m[r], mx);
            const float alpha = __expf(m[r] - mnew);
            float p0 = __expf(s[r][0] - mnew);
            float p1 = __expf(s[r][1] - mnew);
            float p2 = __expf(s[r][2] - mnew);
            float p3 = __expf(s[r][3] - mnew);
            float rs = p0 + p1 + p2 + p3;
            #pragma unroll
            for (int off = 8; off; off >>= 1)
                rs += __shfl_xor_sync(0xffffffffu, rs, off);
            l[r] = l[r] * alpha + rs;
            m[r] = mnew;
            o[r][0] *= alpha; o[r][1] *= alpha; o[r][2] *= alpha; o[r][3] *= alpha;
            const int i = ty * 4 + ((r < 4) ? r : (60 + r));
            *(float4*)&Ps[i * 68 + tx * 4] = make_float4(p0, p1, p2, p3);
        }
        __syncthreads();

        #pragma unroll 8
        for (int j = 0; j < 64; j++) {
            const float4 vv = *(const float4*)&Vs[j * 68 + tx * 4];
            float p[8];
            #pragma unroll
            for (int r = 0; r < 8; r++) {
                const int i = ty * 4 + ((r < 4) ? r : (60 + r));
                p[r] = Ps[i * 68 + j];
            }
            #pragma unroll
            for (int r = 0; r < 8; r++) {
                o[r][0] = fmaf(p[r], vv.x, o[r][0]);
                o[r][1] = fmaf(p[r], vv.y, o[r][1]);
                o[r][2] = fmaf(p[r], vv.z, o[r][2]);
                o[r][3] = fmaf(p[r], vv.w, o[r][3]);
            }
        }
    }

    #pragma unroll
    for (int r = 0; r < 8; r++) {
        const float inv = 1.0f / l[r];
        const int i = ty * 4 + ((r < 4) ? r : (60 + r));
        float4 ov = make_float4(o[r][0] * inv, o[r][1] * inv,
                                o[r][2] * inv, o[r][3] * inv);
        *(float4*)&O[((size_t)(b * SEQ + q0 + i)) * DIM + h * HD + tx * 4] = ov;
    }
}

// --------------------------- Cross attention (T=77) ------------------------
__global__ void __launch_bounds__(256)
cross_attn_kernel(const float* __restrict__ Q, const float* __restrict__ K,
                  const float* __restrict__ V, float* __restrict__ O) {
    __shared__ float Ks[CTXT][65];
    __shared__ float Vs[CTXT][65];

    const int bh = blockIdx.y;
    const int b = bh >> 3, h = bh & 7;
    const int warp = threadIdx.x >> 5, lane = threadIdx.x & 31;

    for (int idx = threadIdx.x; idx < CTXT * HD; idx += 256) {
        const int j = idx >> 6, d = idx & 63;
        const size_t base = ((size_t)(b * CTXT + j)) * DIM + h * HD + d;
        Ks[j][d] = K[base];
        Vs[j][d] = V[base];
    }
    __syncthreads();

    const float scale = 0.125f;
    const int q_base = blockIdx.x * 64 + warp * 8;

    for (int qq = 0; qq < 8; qq++) {
        const int qi = q_base + qq;
        const float* qp = &Q[((size_t)(b * SEQ + qi)) * DIM + h * HD];
        const float q0v = qp[lane];
        const float q1v = qp[lane + 32];

        const int j0 = lane, j1 = lane + 32, j2 = lane + 64;
        float s0 = 0.f, s1 = 0.f, s2 = 0.f;
        #pragma unroll
        for (int d = 0; d < 32; d++) {
            const float qd = __shfl_sync(0xffffffffu, q0v, d);
            s0 = fmaf(qd, Ks[j0][d], s0);
            s1 = fmaf(qd, Ks[j1][d], s1);
            if (j2 < CTXT) s2 = fmaf(qd, Ks[j2][d], s2);
        }
        #pragma unroll
        for (int d = 0; d < 32; d++) {
            const float qd = __shfl_sync(0xffffffffu, q1v, d);
            s0 = fmaf(qd, Ks[j0][d + 32], s0);
            s1 = fmaf(qd, Ks[j1][d + 32], s1);
            if (j2 < CTXT) s2 = fmaf(qd, Ks[j2][d + 32], s2);
        }
        s0 *= scale; s1 *= scale;
        s2 = (j2 < CTXT) ? s2 * scale : -1e30f;

        float mx = fmaxf(fmaxf(s0, s1), s2);
        #pragma unroll
        for (int off = 16; off; off >>= 1)
            mx = fmaxf(mx, __shfl_xor_sync(0xffffffffu, mx, off));

        const float p0 = __expf(s0 - mx);
        const float p1 = __expf(s1 - mx);
        const float p2 = (j2 < CTXT) ? __expf(s2 - mx) : 0.f;
        float sum = p0 + p1 + p2;
        #pragma unroll
        for (int off = 16; off; off >>= 1)
            sum += __shfl_xor_sync(0xffffffffu, sum, off);

        float o0 = 0.f, o1 = 0.f;
        #pragma unroll
        for (int ll = 0; ll < 32; ll++) {
            const float pj = __shfl_sync(0xffffffffu, p0, ll);
            o0 = fmaf(pj, Vs[ll][lane],      o0);
            o1 = fmaf(pj, Vs[ll][lane + 32], o1);
        }
        #pragma unroll
        for (int ll = 0; ll < 32; ll++) {
            const float pj = __shfl_sync(0xffffffffu, p1, ll);
            o0 = fmaf(pj, Vs[32 + ll][lane],      o0);
            o1 = fmaf(pj, Vs[32 + ll][lane + 32], o1);
        }
        #pragma unroll
        for (int ll = 0; ll < 13; ll++) {
            const float pj = __shfl_sync(0xffffffffu, p2, ll);
            o0 = fmaf(pj, Vs[64 + ll][lane],      o0);
            o1 = fmaf(pj, Vs[64 + ll][lane + 32], o1);
        }

        const float inv = 1.0f / sum;
        float* op = &O[((size_t)(b * SEQ + qi)) * DIM + h * HD];
        op[lane]      = o0 * inv;
        op[lane + 32] = o1 * inv;
    }
}

// ------------------------------ GEGLU --------------------------------------
__global__ void geglu_kernel(const float* __restrict__ gg, float* __restrict__ ff) {
    const size_t idx = (size_t)blockIdx.x * 256 + threadIdx.x;
    const size_t mrow = idx >> 11;
    const int    n    = (int)(idx & 2047);
    const float y    = gg[mrow * 4096 + n];
    const float gate = gg[mrow * 4096 + 2048 + n];
    const float t = tanhf(gate * 0.7978845608f * (1.0f + 0.044715f * gate * gate));
    ff[idx] = y * 0.5f * gate * (1.0f + t);
}

// ------------------------------ launch -------------------------------------
extern "C" void kernel_launch(void* const* d_in, const int* in_sizes, int n_in,
                              void* d_out, int out_size) {
    (void)in_sizes; (void)n_in; (void)out_size;
    const float* x       = (const float*)d_in[0];
    const float* context = (const float*)d_in[1];
    const float* ln1_g   = (const float*)d_in[2];
    const float* ln1_b   = (const float*)d_in[3];
    const float* wq1     = (const float*)d_in[4];
    const float* wk1     = (const float*)d_in[5];
    const float* wv1     = (const float*)d_in[6];
    const float* wo1     = (const float*)d_in[7];
    const float* bo1     = (const float*)d_in[8];
    const float* ln2_g   = (const float*)d_in[9];
    const float* ln2_b   = (const float*)d_in[10];
    const float* wq2     = (const float*)d_in[11];
    const float* wk2     = (const float*)d_in[12];
    const float* wv2     = (const float*)d_in[13];
    const float* wo2     = (const float*)d_in[14];
    const float* bo2     = (const float*)d_in[15];
    const float* ln3_g   = (const float*)d_in[16];
    const float* ln3_b   = (const float*)d_in[17];
    const float* geglu_w = (const float*)d_in[18];
    const float* geglu_b = (const float*)d_in[19];
    const float* out_w   = (const float*)d_in[20];
    const float* out_b   = (const float*)d_in[21];
    float* out = (float*)d_out;

    float *xn, *q, *k, *v, *at, *h, *gg, *ff;
    cudaGetSymbolAddress((void**)&xn, g_xn);
    cudaGetSymbolAddress((void**)&q,  g_q);
    cudaGetSymbolAddress((void**)&k,  g_k);
    cudaGetSymbolAddress((void**)&v,  g_v);
    cudaGetSymbolAddress((void**)&at, g_at);
    cudaGetSymbolAddress((void**)&h,  g_h);
    cudaGetSymbolAddress((void**)&gg, g_gg);
    cudaGetSymbolAddress((void**)&ff, g_ff);

    const size_t fa_smem = (64 * 132 + 64 * 68 + 64 * 68 + 128 * 68) * sizeof(float);
    cudaFuncSetAttribute(flash_self_kernel,
                         cudaFuncAttributeMaxDynamicSharedMemorySize, (int)fa_smem);

    const dim3 blk(256);
    const dim3 g512(DIM / 128, ROWS / 128);          // (4, 64)
    const dim3 g4096(4096 / 128, ROWS / 128);        // (32, 64)
    const dim3 gctx(DIM / 128, (CROWS + 127) / 128); // (4, 2)
    const dim3 gattn(SEQ / 128, BATCH * NH);         // (32, 16)
    const dim3 gxattn(SEQ / 64, BATCH * NH);         // (64, 16)

    // ---- stage 1: self-attention ----
    ln_kernel<<<ROWS, blk>>>(x, ln1_g, ln1_b, xn);
    tgemm_kernel<false, false><<<g512, blk>>>(xn, wq1, nullptr, nullptr, q, ROWS, DIM, DIM);
    tgemm_kernel<false, false><<<g512, blk>>>(xn, wk1, nullptr, nullptr, k, ROWS, DIM, DIM);
    tgemm_kernel<false, false><<<g512, blk>>>(xn, wv1, nullptr, nullptr, v, ROWS, DIM, DIM);
    flash_self_kernel<<<gattn, blk, fa_smem>>>(q, k, v, at);
    tgemm_kernel<true, true><<<g512, blk>>>(at, wo1, bo1, x, h, ROWS, DIM, DIM);

    // ---- stage 2: cross-attention ----
    ln_kernel<<<ROWS, blk>>>(h, ln2_g, ln2_b, xn);
    tgemm_kernel<false, false><<<g512, blk>>>(xn, wq2, nullptr, nullptr, q, ROWS, DIM, DIM);
    tgemm_kernel<false, false><<<gctx, blk>>>(context, wk2, nullptr, nullptr, k, CROWS, DIM, DIM);
    tgemm_kernel<false, false><<<gctx, blk>>>(context, wv2, nullptr, nullptr, v, CROWS, DIM, DIM);
    cross_attn_kernel<<<gxattn, blk>>>(q, k, v, at);
    tgemm_kernel<true, true><<<g512, blk>>>(at, wo2, bo2, h, h, ROWS, DIM, DIM);

    // ---- stage 3: GEGLU FFN ----
    ln_kernel<<<ROWS, blk>>>(h, ln3_g, ln3_b, xn);
    tgemm_kernel<true, false><<<g4096, blk>>>(xn, geglu_w, geglu_b, nullptr, gg, ROWS, 4096, DIM);
    geglu_kernel<<<(ROWS * 2048) / 256, blk>>>(gg, ff);
    tgemm_kernel<true, true><<<g512, blk>>>(ff, out_w, out_b, h, out, ROWS, DIM, 2048);
}

// round 10
// speedup vs baseline: 2.4142x; 1.5133x over previous
#include <cuda_runtime.h>
#include <cuda_bf16.h>
#include <cstdint>

// ---------------------------------------------------------------------------
// BasicTransformerBlock (SD-style): self-attn + cross-attn + GEGLU.
// Dense GEMMs + self-attention on tensor cores (tf32 mma.sync, fp32 accum).
// B=2, S=4096, T=77, DIM=512, H=8, D=64.
// ---------------------------------------------------------------------------

#define BATCH 2
#define SEQ   4096
#define CTXT  77
#define DIM   512
#define NH    8
#define HD    64
#define ROWS  (BATCH * SEQ)      // 8192
#define CROWS (BATCH * CTXT)     // 154

// -------------------------- scratch (static, no allocs) --------------------
__device__ float g_xn[ROWS * DIM];
__device__ float g_q [ROWS * DIM];
__device__ float g_k [ROWS * DIM];
__device__ float g_v [ROWS * DIM];
__device__ float g_at[ROWS * DIM];
__device__ float g_h [ROWS * DIM];
__device__ float g_gg[(size_t)ROWS * 4096];
__device__ float g_ff[(size_t)ROWS * 2048];

__device__ __forceinline__ uint32_t f2tf32(float x) {
    uint32_t r;
    asm("cvt.rna.tf32.f32 %0, %1;" : "=r"(r) : "f"(x));
    return r;
}

#define MMA_TF32(acc, a0, a1, a2, a3, b0, b1)                                  \
    asm volatile(                                                              \
        "mma.sync.aligned.m16n8k8.row.col.f32.tf32.tf32.f32 "                  \
        "{%0,%1,%2,%3}, {%4,%5,%6,%7}, {%8,%9}, {%0,%1,%2,%3};\n"              \
        : "+f"(acc[0]), "+f"(acc[1]), "+f"(acc[2]), "+f"(acc[3])               \
        : "r"(a0), "r"(a1), "r"(a2), "r"(a3), "r"(b0), "r"(b1))

// ------------------------------ LayerNorm ----------------------------------
__global__ void ln_kernel(const float* __restrict__ in,
                          const float* __restrict__ gw,
                          const float* __restrict__ bw,
                          float* __restrict__ out) {
    const int row = blockIdx.x;
    const float* x = in + (size_t)row * DIM;
    const int t = threadIdx.x;

    float v0 = x[t];
    float v1 = x[t + 256];
    float s  = v0 + v1;
    float sq = v0 * v0 + v1 * v1;

    #pragma unroll
    for (int off = 16; off; off >>= 1) {
        s  += __shfl_xor_sync(0xffffffffu, s,  off);
        sq += __shfl_xor_sync(0xffffffffu, sq, off);
    }
    __shared__ float ss[8], sqs[8];
    if ((t & 31) == 0) { ss[t >> 5] = s; sqs[t >> 5] = sq; }
    __syncthreads();
    float S = 0.f, SQ = 0.f;
    #pragma unroll
    for (int w = 0; w < 8; w++) { S += ss[w]; SQ += sqs[w]; }

    const float mean = S * (1.0f / DIM);
    const float var  = SQ * (1.0f / DIM) - mean * mean;
    const float inv  = rsqrtf(var + 1e-5f);

    float* o = out + (size_t)row * DIM;
    o[t]       = (v0 - mean) * inv * gw[t]       + bw[t];
    o[t + 256] = (v1 - mean) * inv * gw[t + 256] + bw[t + 256];
}

// ---------------------- TF32 tensor-core GEMM ------------------------------
#define APAD 36    // A frag loads: bank = 4*g + tg -> conflict-free
#define BPAD 136   // B frag loads: bank = 8*tg + g -> conflict-free

template <bool HAS_BIAS, bool HAS_RES>
__global__ void __launch_bounds__(256)
tgemm_kernel(const float* __restrict__ A, const float* __restrict__ B,
             const float* __restrict__ bias, const float* __restrict__ Res,
             float* __restrict__ C, int M, int N, int K) {
    __shared__ uint32_t As[2][128 * APAD];   // [m][k], tf32 bit patterns
    __shared__ uint32_t Bs[2][32 * BPAD];    // [k][n]

    const int tid  = threadIdx.x;
    const int lane = tid & 31;
    const int wid  = tid >> 5;
    const int wr   = wid >> 2;
    const int wc   = wid & 3;
    const int g    = lane >> 2;
    const int tg   = lane & 3;

    const int rowBase = blockIdx.y * 128;
    const int colBase = blockIdx.x * 128;

    const int aRow = tid >> 1;
    const int aCol = (tid & 1) << 4;
    const int bRow = tid >> 3;
    const int bCol = (tid & 7) << 4;

    const int T = K >> 5;

    float4 a_st[4], b_st[4];

    {
        const int grow = rowBase + aRow;
        #pragma unroll
        for (int i = 0; i < 4; i++) {
            a_st[i] = (grow < M) ? *(const float4*)&A[(size_t)grow * K + aCol + 4 * i]
                                 : make_float4(0.f, 0.f, 0.f, 0.f);
            b_st[i] = *(const float4*)&B[(size_t)bRow * N + colBase + bCol + 4 * i];
        }
        #pragma unroll
        for (int i = 0; i < 4; i++) {
            uint4 av = make_uint4(f2tf32(a_st[i].x), f2tf32(a_st[i].y),
                                  f2tf32(a_st[i].z), f2tf32(a_st[i].w));
            *(uint4*)&As[0][aRow * APAD + aCol + 4 * i] = av;
            uint4 bv = make_uint4(f2tf32(b_st[i].x), f2tf32(b_st[i].y),
                                  f2tf32(b_st[i].z), f2tf32(b_st[i].w));
            *(uint4*)&Bs[0][bRow * BPAD + bCol + 4 * i] = bv;
        }
    }
    __syncthreads();

    float acc[4][4][4];
    #pragma unroll
    for (int mf = 0; mf < 4; mf++)
        #pragma unroll
        for (int nf = 0; nf < 4; nf++)
            #pragma unroll
            for (int c = 0; c < 4; c++) acc[mf][nf][c] = 0.f;

    for (int t = 0; t < T; t++) {
        const int buf = t & 1;
        if (t + 1 < T) {
            const int k0 = (t + 1) << 5;
            const int grow = rowBase + aRow;
            #pragma unroll
            for (int i = 0; i < 4; i++) {
                a_st[i] = (grow < M) ? *(const float4*)&A[(size_t)grow * K + k0 + aCol + 4 * i]
                                     : make_float4(0.f, 0.f, 0.f, 0.f);
                b_st[i] = *(const float4*)&B[(size_t)(k0 + bRow) * N + colBase + bCol + 4 * i];
            }
        }

        const uint32_t* as = &As[buf][0];
        const uint32_t* bs = &Bs[buf][0];

        #pragma unroll
        for (int ks = 0; ks < 4; ks++) {
            const int k0 = ks * 8;
            uint32_t afr[4][4], bfr[4][2];
            #pragma unroll
            for (int mf = 0; mf < 4; mf++) {
                const int r0 = (wr * 64 + mf * 16 + g) * APAD + k0 + tg;
                afr[mf][0] = as[r0];
                afr[mf][1] = as[r0 + 8 * APAD];
                afr[mf][2] = as[r0 + 4];
                afr[mf][3] = as[r0 + 8 * APAD + 4];
            }
            #pragma unroll
            for (int nf = 0; nf < 4; nf++) {
                const int c0 = (k0 + tg) * BPAD + wc * 32 + nf * 8 + g;
                bfr[nf][0] = bs[c0];
                bfr[nf][1] = bs[c0 + 4 * BPAD];
            }
            #pragma unroll
            for (int mf = 0; mf < 4; mf++)
                #pragma unroll
                for (int nf = 0; nf < 4; nf++)
                    MMA_TF32(acc[mf][nf], afr[mf][0], afr[mf][1], afr[mf][2], afr[mf][3],
                             bfr[nf][0], bfr[nf][1]);
        }

        if (t + 1 < T) {
            const int nb = buf ^ 1;
            #pragma unroll
            for (int i = 0; i < 4; i++) {
                uint4 av = make_uint4(f2tf32(a_st[i].x), f2tf32(a_st[i].y),
                                      f2tf32(a_st[i].z), f2tf32(a_st[i].w));
                *(uint4*)&As[nb][aRow * APAD + aCol + 4 * i] = av;
                uint4 bv = make_uint4(f2tf32(b_st[i].x), f2tf32(b_st[i].y),
                                      f2tf32(b_st[i].z), f2tf32(b_st[i].w));
                *(uint4*)&Bs[nb][bRow * BPAD + bCol + 4 * i] = bv;
            }
            __syncthreads();
        }
    }

    #pragma unroll
    for (int mf = 0; mf < 4; mf++) {
        #pragma unroll
        for (int half = 0; half < 2; half++) {
            const int row = rowBase + wr * 64 + mf * 16 + g + 8 * half;
            if (row >= M) continue;
            #pragma unroll
            for (int nf = 0; nf < 4; nf++) {
                const int col = colBase + wc * 32 + nf * 8 + 2 * tg;
                float2 v = half ? make_float2(acc[mf][nf][2], acc[mf][nf][3])
                                : make_float2(acc[mf][nf][0], acc[mf][nf][1]);
                if (HAS_BIAS) {
                    const float2 bv = *(const float2*)&bias[col];
                    v.x += bv.x; v.y += bv.y;
                }
                if (HAS_RES) {
                    const float2 rv = *(const float2*)&Res[(size_t)row * N + col];
                    v.x += rv.x; v.y += rv.y;
                }
                *(float2*)&C[(size_t)row * N + col] = v;
            }
        }
    }
}

// ---------------- Flash self-attention on tensor cores (tf32) --------------
// grid (SEQ/128, B*H), 256 threads = 8 warps; warp owns 16 q-rows x 64 keys.
// smem (tf32 words): QP[128*68] (Q staged, then reused for P), Ks[64*68]
// ([key][d], natural col-major B for Q.K^T), Vt[64*68] ([d][key], col-major
// B for P.V). All frag loads: bank = 4g+tg -> conflict-free.
#define FS 68
__global__ void __launch_bounds__(256)
flash_mma_kernel(const float* __restrict__ Q, const float* __restrict__ K,
                 const float* __restrict__ V, float* __restrict__ O) {
    extern __shared__ uint32_t sm[];
    uint32_t* QP = sm;                 // [128][FS] : Qs[i][d] then Ps[i][j]
    uint32_t* Ks = sm + 128 * FS;      // [64][FS]  : K[j][d]
    uint32_t* Vt = Ks + 64 * FS;       // [64][FS]  : Vt[d][j]

    const int bh = blockIdx.y;
    const int b = bh >> 3, h = bh & 7;
    const int q0 = blockIdx.x * 128;
    const int tid = threadIdx.x;
    const int lane = tid & 31;
    const int wid = tid >> 5;
    const int g = lane >> 2, tg = lane & 3;

    // ---- stage Q tile to smem as tf32 (scale folded) ----
    {
        const int li = tid >> 1;             // 0..127
        const int db = (tid & 1) * 32;       // 0 or 32
        const float* qrow = &Q[((size_t)(b * SEQ + q0 + li)) * DIM + h * HD];
        #pragma unroll
        for (int c = 0; c < 8; c++) {
            const int d4 = db + 4 * c;
            const float4 qv = *(const float4*)&qrow[d4];
            uint4 u = make_uint4(f2tf32(qv.x * 0.125f), f2tf32(qv.y * 0.125f),
                                 f2tf32(qv.z * 0.125f), f2tf32(qv.w * 0.125f));
            *(uint4*)&QP[li * FS + d4] = u;
        }
    }
    __syncthreads();

    // ---- pull Q frags into registers (whole warp tile, all 8 k-steps) ----
    const int r0 = wid * 16 + g;             // warp-local q rows r0, r0+8
    uint32_t qf[8][4];
    #pragma unroll
    for (int ks = 0; ks < 8; ks++) {
        qf[ks][0] = QP[r0 * FS + ks * 8 + tg];
        qf[ks][1] = QP[(r0 + 8) * FS + ks * 8 + tg];
        qf[ks][2] = QP[r0 * FS + ks * 8 + tg + 4];
        qf[ks][3] = QP[(r0 + 8) * FS + ks * 8 + tg + 4];
    }

    float m0 = -1e30f, m1 = -1e30f, l0 = 0.f, l1 = 0.f;
    float oacc[8][4];
    #pragma unroll
    for (int nf = 0; nf < 8; nf++)
        #pragma unroll
        for (int c = 0; c < 4; c++) oacc[nf][c] = 0.f;

    for (int kt = 0; kt < SEQ; kt += 64) {
        __syncthreads();   // prior GEMM2 done with Ks/Vt/Ps (and q-frag loads)
        // ---- load K/V tile (64 rows) as tf32 ----
        {
            const int li = tid >> 2;          // 0..63
            const int db = (tid & 3) << 2;    // 0,4,8,12
            const size_t base = ((size_t)(b * SEQ + kt + li)) * DIM + h * HD;
            #pragma unroll
            for (int c = 0; c < 4; c++) {
                const int d4 = db + 16 * c;
                const float4 kv = *(const float4*)&K[base + d4];
                uint4 u = make_uint4(f2tf32(kv.x), f2tf32(kv.y),
                                     f2tf32(kv.z), f2tf32(kv.w));
                *(uint4*)&Ks[li * FS + d4] = u;
                const float4 vv = *(const float4*)&V[base + d4];
                Vt[(d4 + 0) * FS + li] = f2tf32(vv.x);
                Vt[(d4 + 1) * FS + li] = f2tf32(vv.y);
                Vt[(d4 + 2) * FS + li] = f2tf32(vv.z);
                Vt[(d4 + 3) * FS + li] = f2tf32(vv.w);
            }
        }
        __syncthreads();

        // ---- GEMM1: S[16x64] = Qw @ K^T (k = d, 8 steps) ----
        float sacc[8][4];
        #pragma unroll
        for (int nf = 0; nf < 8; nf++)
            #pragma unroll
            for (int c = 0; c < 4; c++) sacc[nf][c] = 0.f;

        #pragma unroll
        for (int ks = 0; ks < 8; ks++) {
            #pragma unroll
            for (int nf = 0; nf < 8; nf++) {
                const int a = (nf * 8 + g) * FS + ks * 8 + tg;
                const uint32_t b0 = Ks[a];
                const uint32_t b1 = Ks[a + 4];
                MMA_TF32(sacc[nf], qf[ks][0], qf[ks][1], qf[ks][2], qf[ks][3], b0, b1);
            }
        }

        // ---- online softmax (rows r0, r0+8; cols all in-warp) ----
        float mx0 = -1e30f, mx1 = -1e30f;
        #pragma unroll
        for (int nf = 0; nf < 8; nf++) {
            mx0 = fmaxf(mx0, fmaxf(sacc[nf][0], sacc[nf][1]));
            mx1 = fmaxf(mx1, fmaxf(sacc[nf][2], sacc[nf][3]));
        }
        mx0 = fmaxf(mx0, __shfl_xor_sync(0xffffffffu, mx0, 1));
        mx0 = fmaxf(mx0, __shfl_xor_sync(0xffffffffu, mx0, 2));
        mx1 = fmaxf(mx1, __shfl_xor_sync(0xffffffffu, mx1, 1));
        mx1 = fmaxf(mx1, __shfl_xor_sync(0xffffffffu, mx1, 2));

        const float mn0 = fmaxf(m0, mx0);
        const float mn1 = fmaxf(m1, mx1);
        const float al0 = __expf(m0 - mn0);
        const float al1 = __expf(m1 - mn1);

        float rs0 = 0.f, rs1 = 0.f;
        #pragma unroll
        for (int nf = 0; nf < 8; nf++) {
            const float p00 = __expf(sacc[nf][0] - mn0);
            const float p01 = __expf(sacc[nf][1] - mn0);
            const float p10 = __expf(sacc[nf][2] - mn1);
            const float p11 = __expf(sacc[nf][3] - mn1);
            rs0 += p00 + p01;
            rs1 += p10 + p11;
            uint2 u0 = make_uint2(f2tf32(p00), f2tf32(p01));
            uint2 u1 = make_uint2(f2tf32(p10), f2tf32(p11));
            *(uint2*)&QP[r0 * FS + nf * 8 + 2 * tg] = u0;
            *(uint2*)&QP[(r0 + 8) * FS + nf * 8 + 2 * tg] = u1;
            oacc[nf][0] *= al0; oacc[nf][1] *= al0;
            oacc[nf][2] *= al1; oacc[nf][3] *= al1;
        }
        rs0 += __shfl_xor_sync(0xffffffffu, rs0, 1);
        rs0 += __shfl_xor_sync(0xffffffffu, rs0, 2);
        rs1 += __shfl_xor_sync(0xffffffffu, rs1, 1);
        rs1 += __shfl_xor_sync(0xffffffffu, rs1, 2);
        l0 = l0 * al0 + rs0;
        l1 = l1 * al1 + rs1;
        m0 = mn0; m1 = mn1;
        __syncthreads();   // P visible to whole warp's frag loads

        // ---- GEMM2: O[16x64] += P[16x64] @ V[64x64] (k = key, 8 steps) ----
        #pragma unroll
        for (int ks = 0; ks < 8; ks++) {
            const uint32_t a0 = QP[r0 * FS + ks * 8 + tg];
            const uint32_t a1 = QP[(r0 + 8) * FS + ks * 8 + tg];
            const uint32_t a2 = QP[r0 * FS + ks * 8 + tg + 4];
            const uint32_t a3 = QP[(r0 + 8) * FS + ks * 8 + tg + 4];
            #pragma unroll
            for (int nf = 0; nf < 8; nf++) {
                const int a = (nf * 8 + g) * FS + ks * 8 + tg;
                const uint32_t b0 = Vt[a];
                const uint32_t b1 = Vt[a + 4];
                MMA_TF32(oacc[nf], a0, a1, a2, a3, b0, b1);
            }
        }
    }

    // ---- epilogue ----
    const float inv0 = 1.0f / l0;
    const float inv1 = 1.0f / l1;
    const size_t base0 = ((size_t)(b * SEQ + q0 + r0)) * DIM + h * HD;
    const size_t base1 = ((size_t)(b * SEQ + q0 + r0 + 8)) * DIM + h * HD;
    #pragma unroll
    for (int nf = 0; nf < 8; nf++) {
        const int col = nf * 8 + 2 * tg;
        *(float2*)&O[base0 + col] = make_float2(oacc[nf][0] * inv0, oacc[nf][1] * inv0);
        *(float2*)&O[base1 + col] = make_float2(oacc[nf][2] * inv1, oacc[nf][3] * inv1);
    }
}

// --------------------------- Cross attention (T=77) ------------------------
__global__ void __launch_bounds__(256)
cross_attn_kernel(const float* __restrict__ Q, const float* __restrict__ K,
                  const float* __restrict__ V, float* __restrict__ O) {
    __shared__ float Ksm[CTXT][65];
    __shared__ float Vsm[CTXT][65];

    const int bh = blockIdx.y;
    const int b = bh >> 3, h = bh & 7;
    const int warp = threadIdx.x >> 5, lane = threadIdx.x & 31;

    for (int idx = threadIdx.x; idx < CTXT * HD; idx += 256) {
        const int j = idx >> 6, d = idx & 63;
        const size_t base = ((size_t)(b * CTXT + j)) * DIM + h * HD + d;
        Ksm[j][d] = K[base];
        Vsm[j][d] = V[base];
    }
    __syncthreads();

    const float scale = 0.125f;
    const int q_base = blockIdx.x * 64 + warp * 8;

    for (int qq = 0; qq < 8; qq++) {
        const int qi = q_base + qq;
        const float* qp = &Q[((size_t)(b * SEQ + qi)) * DIM + h * HD];
        const float q0v = qp[lane];
        const float q1v = qp[lane + 32];

        const int j0 = lane, j1 = lane + 32, j2 = lane + 64;
        float s0 = 0.f, s1 = 0.f, s2 = 0.f;
        #pragma unroll
        for (int d = 0; d < 32; d++) {
            const float qd = __shfl_sync(0xffffffffu, q0v, d);
            s0 = fmaf(qd, Ksm[j0][d], s0);
            s1 = fmaf(qd, Ksm[j1][d], s1);
            if (j2 < CTXT) s2 = fmaf(qd, Ksm[j2][d], s2);
        }
        #pragma unroll
        for (int d = 0; d < 32; d++) {
            const float qd = __shfl_sync(0xffffffffu, q1v, d);
            s0 = fmaf(qd, Ksm[j0][d + 32], s0);
            s1 = fmaf(qd, Ksm[j1][d + 32], s1);
            if (j2 < CTXT) s2 = fmaf(qd, Ksm[j2][d + 32], s2);
        }
        s0 *= scale; s1 *= scale;
        s2 = (j2 < CTXT) ? s2 * scale : -1e30f;

        float mx = fmaxf(fmaxf(s0, s1), s2);
        #pragma unroll
        for (int off = 16; off; off >>= 1)
            mx = fmaxf(mx, __shfl_xor_sync(0xffffffffu, mx, off));

        const float p0 = __expf(s0 - mx);
        const float p1 = __expf(s1 - mx);
        const float p2 = (j2 < CTXT) ? __expf(s2 - mx) : 0.f;
        float sum = p0 + p1 + p2;
        #pragma unroll
        for (int off = 16; off; off >>= 1)
            sum += __shfl_xor_sync(0xffffffffu, sum, off);

        float o0 = 0.f, o1 = 0.f;
        #pragma unroll
        for (int ll = 0; ll < 32; ll++) {
            const float pj = __shfl_sync(0xffffffffu, p0, ll);
            o0 = fmaf(pj, Vsm[ll][lane],      o0);
            o1 = fmaf(pj, Vsm[ll][lane + 32], o1);
        }
        #pragma unroll
        for (int ll = 0; ll < 32; ll++) {
            const float pj = __shfl_sync(0xffffffffu, p1, ll);
            o0 = fmaf(pj, Vsm[32 + ll][lane],      o0);
            o1 = fmaf(pj, Vsm[32 + ll][lane + 32], o1);
        }
        #pragma unroll
        for (int ll = 0; ll < 13; ll++) {
            const float pj = __shfl_sync(0xffffffffu, p2, ll);
            o0 = fmaf(pj, Vsm[64 + ll][lane],      o0);
            o1 = fmaf(pj, Vsm[64 + ll][lane + 32], o1);
        }

        const float inv = 1.0f / sum;
        float* op = &O[((size_t)(b * SEQ + qi)) * DIM + h * HD];
        op[lane]      = o0 * inv;
        op[lane + 32] = o1 * inv;
    }
}

// ------------------------------ GEGLU --------------------------------------
__global__ void geglu_kernel(const float* __restrict__ gg, float* __restrict__ ff) {
    const size_t idx = (size_t)blockIdx.x * 256 + threadIdx.x;
    const size_t mrow = idx >> 11;
    const int    n    = (int)(idx & 2047);
    const float y    = gg[mrow * 4096 + n];
    const float gate = gg[mrow * 4096 + 2048 + n];
    const float t = tanhf(gate * 0.7978845608f * (1.0f + 0.044715f * gate * gate));
    ff[idx] = y * 0.5f * gate * (1.0f + t);
}

// ------------------------------ launch -------------------------------------
extern "C" void kernel_launch(void* const* d_in, const int* in_sizes, int n_in,
                              void* d_out, int out_size) {
    (void)in_sizes; (void)n_in; (void)out_size;
    const float* x       = (const float*)d_in[0];
    const float* context = (const float*)d_in[1];
    const float* ln1_g   = (const float*)d_in[2];
    const float* ln1_b   = (const float*)d_in[3];
    const float* wq1     = (const float*)d_in[4];
    const float* wk1     = (const float*)d_in[5];
    const float* wv1     = (const float*)d_in[6];
    const float* wo1     = (const float*)d_in[7];
    const float* bo1     = (const float*)d_in[8];
    const float* ln2_g   = (const float*)d_in[9];
    const float* ln2_b   = (const float*)d_in[10];
    const float* wq2     = (const float*)d_in[11];
    const float* wk2     = (const float*)d_in[12];
    const float* wv2     = (const float*)d_in[13];
    const float* wo2     = (const float*)d_in[14];
    const float* bo2     = (const float*)d_in[15];
    const float* ln3_g   = (const float*)d_in[16];
    const float* ln3_b   = (const float*)d_in[17];
    const float* geglu_w = (const float*)d_in[18];
    const float* geglu_b = (const float*)d_in[19];
    const float* out_w   = (const float*)d_in[20];
    const float* out_b   = (const float*)d_in[21];
    float* out = (float*)d_out;

    float *xn, *q, *k, *v, *at, *h, *gg, *ff;
    cudaGetSymbolAddress((void**)&xn, g_xn);
    cudaGetSymbolAddress((void**)&q,  g_q);
    cudaGetSymbolAddress((void**)&k,  g_k);
    cudaGetSymbolAddress((void**)&v,  g_v);
    cudaGetSymbolAddress((void**)&at, g_at);
    cudaGetSymbolAddress((void**)&h,  g_h);
    cudaGetSymbolAddress((void**)&gg, g_gg);
    cudaGetSymbolAddress((void**)&ff, g_ff);

    // QP 128*68 + Ks 64*68 + Vt 64*68 = 17408 words = 69632 B
    const size_t fa_smem = (size_t)(128 * FS + 64 * FS + 64 * FS) * 4;
    cudaFuncSetAttribute(flash_mma_kernel,
                         cudaFuncAttributeMaxDynamicSharedMemorySize, (int)fa_smem);

    const dim3 blk(256);
    const dim3 g512(DIM / 128, ROWS / 128);          // (4, 64)
    const dim3 g4096(4096 / 128, ROWS / 128);        // (32, 64)
    const dim3 gctx(DIM / 128, (CROWS + 127) / 128); // (4, 2)
    const dim3 gattn(SEQ / 128, BATCH * NH);         // (32, 16)
    const dim3 gxattn(SEQ / 64, BATCH * NH);         // (64, 16)

    // ---- stage 1: self-attention ----
    ln_kernel<<<ROWS, blk>>>(x, ln1_g, ln1_b, xn);
    tgemm_kernel<false, false><<<g512, blk>>>(xn, wq1, nullptr, nullptr, q, ROWS, DIM, DIM);
    tgemm_kernel<false, false><<<g512, blk>>>(xn, wk1, nullptr, nullptr, k, ROWS, DIM, DIM);
    tgemm_kernel<false, false><<<g512, blk>>>(xn, wv1, nullptr, nullptr, v, ROWS, DIM, DIM);
    flash_mma_kernel<<<gattn, blk, fa_smem>>>(q, k, v, at);
    tgemm_kernel<true, true><<<g512, blk>>>(at, wo1, bo1, x, h, ROWS, DIM, DIM);

    // ---- stage 2: cross-attention ----
    ln_kernel<<<ROWS, blk>>>(h, ln2_g, ln2_b, xn);
    tgemm_kernel<false, false><<<g512, blk>>>(xn, wq2, nullptr, nullptr, q, ROWS, DIM, DIM);
    tgemm_kernel<false, false><<<gctx, blk>>>(context, wk2, nullptr, nullptr, k, CROWS, DIM, DIM);
    tgemm_kernel<false, false><<<gctx, blk>>>(context, wv2, nullptr, nullptr, v, CROWS, DIM, DIM);
    cross_attn_kernel<<<gxattn, blk>>>(q, k, v, at);
    tgemm_kernel<true, true><<<g512, blk>>>(at, wo2, bo2, h, h, ROWS, DIM, DIM);

    // ---- stage 3: GEGLU FFN ----
    ln_kernel<<<ROWS, blk>>>(h, ln3_g, ln3_b, xn);
    tgemm_kernel<true, false><<<g4096, blk>>>(xn, geglu_w, geglu_b, nullptr, gg, ROWS, 4096, DIM);
    geglu_kernel<<<(ROWS * 2048) / 256, blk>>>(gg, ff);
    tgemm_kernel<true, true><<<g512, blk>>>(ff, out_w, out_b, h, out, ROWS, DIM, 2048);
}

// round 11
// speedup vs baseline: 2.8932x; 1.1984x over previous
#include <cuda_runtime.h>
#include <cuda_bf16.h>
#include <cstdint>

// ---------------------------------------------------------------------------
// BasicTransformerBlock (SD-style): self-attn + cross-attn + GEGLU.
// Dense GEMMs + self-attention on tensor cores (tf32 mma.sync, fp32 accum,
// HW truncation fp32->tf32). cp.async pipelines, 2 CTAs/SM on the GEMM.
// B=2, S=4096, T=77, DIM=512, H=8, D=64.
// ---------------------------------------------------------------------------

#define BATCH 2
#define SEQ   4096
#define CTXT  77
#define DIM   512
#define NH    8
#define HD    64
#define ROWS  (BATCH * SEQ)      // 8192
#define CROWS (BATCH * CTXT)     // 154

// -------------------------- scratch (static, no allocs) --------------------
__device__ float g_xn[ROWS * DIM];
__device__ float g_q [ROWS * DIM];
__device__ float g_k [ROWS * DIM];
__device__ float g_v [ROWS * DIM];
__device__ float g_at[ROWS * DIM];
__device__ float g_h [ROWS * DIM];
__device__ float g_gg[(size_t)ROWS * 4096];
__device__ float g_ff[(size_t)ROWS * 2048];

#define MMA_TF32(acc, a0, a1, a2, a3, b0, b1)                                  \
    asm volatile(                                                              \
        "mma.sync.aligned.m16n8k8.row.col.f32.tf32.tf32.f32 "                  \
        "{%0,%1,%2,%3}, {%4,%5,%6,%7}, {%8,%9}, {%0,%1,%2,%3};\n"              \
        : "+f"(acc[0]), "+f"(acc[1]), "+f"(acc[2]), "+f"(acc[3])               \
        : "r"(a0), "r"(a1), "r"(a2), "r"(a3), "r"(b0), "r"(b1))

__device__ __forceinline__ uint32_t smem_u32(const void* p) {
    return (uint32_t)__cvta_generic_to_shared(p);
}
__device__ __forceinline__ void cp_async16(uint32_t dst, const void* src) {
    asm volatile("cp.async.ca.shared.global [%0], [%1], 16;\n"
                 :: "r"(dst), "l"(src));
}
__device__ __forceinline__ void cp_async16_pred(uint32_t dst, const void* src, int sz) {
    asm volatile("cp.async.ca.shared.global [%0], [%1], 16, %2;\n"
                 :: "r"(dst), "l"(src), "r"(sz));
}
#define CP_COMMIT() asm volatile("cp.async.commit_group;\n" ::: "memory")
#define CP_WAIT0()  asm volatile("cp.async.wait_group 0;\n" ::: "memory")

// ------------------------------ LayerNorm ----------------------------------
__global__ void ln_kernel(const float* __restrict__ in,
                          const float* __restrict__ gw,
                          const float* __restrict__ bw,
                          float* __restrict__ out) {
    const int row = blockIdx.x;
    const float* x = in + (size_t)row * DIM;
    const int t = threadIdx.x;

    float v0 = x[t];
    float v1 = x[t + 256];
    float s  = v0 + v1;
    float sq = v0 * v0 + v1 * v1;

    #pragma unroll
    for (int off = 16; off; off >>= 1) {
        s  += __shfl_xor_sync(0xffffffffu, s,  off);
        sq += __shfl_xor_sync(0xffffffffu, sq, off);
    }
    __shared__ float ss[8], sqs[8];
    if ((t & 31) == 0) { ss[t >> 5] = s; sqs[t >> 5] = sq; }
    __syncthreads();
    float S = 0.f, SQ = 0.f;
    #pragma unroll
    for (int w = 0; w < 8; w++) { S += ss[w]; SQ += sqs[w]; }

    const float mean = S * (1.0f / DIM);
    const float var  = SQ * (1.0f / DIM) - mean * mean;
    const float inv  = rsqrtf(var + 1e-5f);

    float* o = out + (size_t)row * DIM;
    o[t]       = (v0 - mean) * inv * gw[t]       + bw[t];
    o[t + 256] = (v1 - mean) * inv * gw[t + 256] + bw[t + 256];
}

// ---------------------- TF32 tensor-core GEMM ------------------------------
// 128x128x32 tile, 8 warps (2x4), warp tile 64x32, m16n8k8 tf32.
// cp.async double-buffered smem (fp32 bits, HW-truncated to tf32 by mma).
#define APAD 36    // A frag loads: bank = 4*g + tg -> conflict-free
#define BPAD 136   // B frag loads: bank = 8*tg + g -> conflict-free

template <bool HAS_BIAS, bool HAS_RES>
__global__ void __launch_bounds__(256, 2)
tgemm_kernel(const float* __restrict__ A, const float* __restrict__ B,
             const float* __restrict__ bias, const float* __restrict__ Res,
             float* __restrict__ C, int M, int N, int K) {
    __shared__ uint32_t As[2 * 128 * APAD];   // [buf][m][k]
    __shared__ uint32_t Bs[2 * 32 * BPAD];    // [buf][k][n]

    const int tid  = threadIdx.x;
    const int lane = tid & 31;
    const int wid  = tid >> 5;
    const int wr   = wid >> 2;
    const int wc   = wid & 3;
    const int g    = lane >> 2;
    const int tg   = lane & 3;

    const int rowBase = blockIdx.y * 128;
    const int colBase = blockIdx.x * 128;

    const int aRow = tid >> 1;          // 0..127
    const int aCol = (tid & 1) << 4;    // 0 or 16
    const int bRow = tid >> 3;          // 0..31
    const int bCol = (tid & 7) << 4;    // 0..112

    const uint32_t asB = smem_u32(As);
    const uint32_t bsB = smem_u32(Bs);

    const int grow = rowBase + aRow;
    const int aok  = (grow < M) ? 16 : 0;
    const float* aBase = A + (size_t)(grow < M ? grow : 0) * K + aCol;
    const float* bBase = B + (size_t)bRow * N + colBase + bCol;

    const int T = K >> 5;

    // ---- stage tile 0 ----
    {
        const uint32_t ad = asB + (uint32_t)(aRow * APAD + aCol) * 4;
        const uint32_t bd = bsB + (uint32_t)(bRow * BPAD + bCol) * 4;
        #pragma unroll
        for (int i = 0; i < 4; i++) cp_async16_pred(ad + 16u * i, aBase + 4 * i, aok);
        #pragma unroll
        for (int i = 0; i < 4; i++) cp_async16(bd + 16u * i, bBase + 4 * i);
        CP_COMMIT();
    }

    float acc[4][4][4];
    #pragma unroll
    for (int mf = 0; mf < 4; mf++)
        #pragma unroll
        for (int nf = 0; nf < 4; nf++)
            #pragma unroll
            for (int c = 0; c < 4; c++) acc[mf][nf][c] = 0.f;

    for (int t = 0; t < T; t++) {
        CP_WAIT0();
        __syncthreads();

        if (t + 1 < T) {
            const int k0 = (t + 1) << 5;
            const int nb = (t + 1) & 1;
            const uint32_t ad = asB + (uint32_t)(nb * 128 * APAD + aRow * APAD + aCol) * 4;
            const uint32_t bd = bsB + (uint32_t)(nb * 32 * BPAD + bRow * BPAD + bCol) * 4;
            #pragma unroll
            for (int i = 0; i < 4; i++) cp_async16_pred(ad + 16u * i, aBase + k0 + 4 * i, aok);
            #pragma unroll
            for (int i = 0; i < 4; i++)
                cp_async16(bd + 16u * i, bBase + (size_t)k0 * N + 4 * i);
            CP_COMMIT();
        }

        const uint32_t* as = As + (t & 1) * 128 * APAD;
        const uint32_t* bs = Bs + (t & 1) * 32 * BPAD;

        #pragma unroll
        for (int ks = 0; ks < 4; ks++) {
            const int k0 = ks * 8;
            uint32_t afr[4][4], bfr[4][2];
            #pragma unroll
            for (int mf = 0; mf < 4; mf++) {
                const int r0 = (wr * 64 + mf * 16 + g) * APAD + k0 + tg;
                afr[mf][0] = as[r0];
                afr[mf][1] = as[r0 + 8 * APAD];
                afr[mf][2] = as[r0 + 4];
                afr[mf][3] = as[r0 + 8 * APAD + 4];
            }
            #pragma unroll
            for (int nf = 0; nf < 4; nf++) {
                const int c0 = (k0 + tg) * BPAD + wc * 32 + nf * 8 + g;
                bfr[nf][0] = bs[c0];
                bfr[nf][1] = bs[c0 + 4 * BPAD];
            }
            #pragma unroll
            for (int mf = 0; mf < 4; mf++)
                #pragma unroll
                for (int nf = 0; nf < 4; nf++)
                    MMA_TF32(acc[mf][nf], afr[mf][0], afr[mf][1], afr[mf][2], afr[mf][3],
                             bfr[nf][0], bfr[nf][1]);
        }
    }

    #pragma unroll
    for (int mf = 0; mf < 4; mf++) {
        #pragma unroll
        for (int half = 0; half < 2; half++) {
            const int row = rowBase + wr * 64 + mf * 16 + g + 8 * half;
            if (row >= M) continue;
            #pragma unroll
            for (int nf = 0; nf < 4; nf++) {
                const int col = colBase + wc * 32 + nf * 8 + 2 * tg;
                float2 v = half ? make_float2(acc[mf][nf][2], acc[mf][nf][3])
                                : make_float2(acc[mf][nf][0], acc[mf][nf][1]);
                if (HAS_BIAS) {
                    const float2 bv = *(const float2*)&bias[col];
                    v.x += bv.x; v.y += bv.y;
                }
                if (HAS_RES) {
                    const float2 rv = *(const float2*)&Res[(size_t)row * N + col];
                    v.x += rv.x; v.y += rv.y;
                }
                *(float2*)&C[(size_t)row * N + col] = v;
            }
        }
    }
}

// ---------------- Flash self-attention on tensor cores (tf32) --------------
// grid (SEQ/128, B*H), 256 threads = 8 warps; warp owns 16 q-rows x 64 keys.
// QP (Q staged then P) is warp-private -> P handoff needs only __syncwarp.
#define FS 68
__global__ void __launch_bounds__(256)
flash_mma_kernel(const float* __restrict__ Q, const float* __restrict__ K,
                 const float* __restrict__ V, float* __restrict__ O) {
    extern __shared__ uint32_t sm[];
    uint32_t* QP = sm;                 // [128][FS] : Qs[i][d] then Ps[i][j]
    uint32_t* Ks = sm + 128 * FS;      // [64][FS]  : K[j][d]
    uint32_t* Vt = Ks + 64 * FS;       // [64][FS]  : Vt[d][j]

    const int bh = blockIdx.y;
    const int b = bh >> 3, h = bh & 7;
    const int q0 = blockIdx.x * 128;
    const int tid = threadIdx.x;
    const int lane = tid & 31;
    const int wid = tid >> 5;
    const int g = lane >> 2, tg = lane & 3;

    // ---- stage Q tile to smem (scale folded; raw fp32 bits) ----
    {
        const int li = tid >> 1;             // 0..127 (warp-private band)
        const int db = (tid & 1) * 32;
        const float* qrow = &Q[((size_t)(b * SEQ + q0 + li)) * DIM + h * HD];
        #pragma unroll
        for (int c = 0; c < 8; c++) {
            const int d4 = db + 4 * c;
            const float4 qv = *(const float4*)&qrow[d4];
            uint4 u = make_uint4(__float_as_uint(qv.x * 0.125f),
                                 __float_as_uint(qv.y * 0.125f),
                                 __float_as_uint(qv.z * 0.125f),
                                 __float_as_uint(qv.w * 0.125f));
            *(uint4*)&QP[li * FS + d4] = u;
        }
    }
    __syncwarp();

    const int r0 = wid * 16 + g;
    uint32_t qf[8][4];
    #pragma unroll
    for (int ks = 0; ks < 8; ks++) {
        qf[ks][0] = QP[r0 * FS + ks * 8 + tg];
        qf[ks][1] = QP[(r0 + 8) * FS + ks * 8 + tg];
        qf[ks][2] = QP[r0 * FS + ks * 8 + tg + 4];
        qf[ks][3] = QP[(r0 + 8) * FS + ks * 8 + tg + 4];
    }

    const uint32_t ksB = smem_u32(Ks);

    float m0 = -1e30f, m1 = -1e30f, l0 = 0.f, l1 = 0.f;
    float oacc[8][4];
    #pragma unroll
    for (int nf = 0; nf < 8; nf++)
        #pragma unroll
        for (int c = 0; c < 4; c++) oacc[nf][c] = 0.f;

    for (int kt = 0; kt < SEQ; kt += 64) {
        __syncthreads();   // prior GEMMs done with Ks/Vt
        {
            const int li = tid >> 2;          // 0..63
            const int db = (tid & 3) << 2;
            const size_t base = ((size_t)(b * SEQ + kt + li)) * DIM + h * HD;
            // K: direct async copy, layout [key][d] matches global
            const uint32_t kd = ksB + (uint32_t)(li * FS + db) * 4;
            #pragma unroll
            for (int c = 0; c < 4; c++)
                cp_async16(kd + 64u * c, &K[base + db + 16 * c]);
            CP_COMMIT();
            // V: transpose through registers (raw bits)
            #pragma unroll
            for (int c = 0; c < 4; c++) {
                const int d4 = db + 16 * c;
                const float4 vv = *(const float4*)&V[base + d4];
                Vt[(d4 + 0) * FS + li] = __float_as_uint(vv.x);
                Vt[(d4 + 1) * FS + li] = __float_as_uint(vv.y);
                Vt[(d4 + 2) * FS + li] = __float_as_uint(vv.z);
                Vt[(d4 + 3) * FS + li] = __float_as_uint(vv.w);
            }
            CP_WAIT0();
        }
        __syncthreads();

        // ---- GEMM1: S[16x64] = Qw @ K^T ----
        float sacc[8][4];
        #pragma unroll
        for (int nf = 0; nf < 8; nf++)
            #pragma unroll
            for (int c = 0; c < 4; c++) sacc[nf][c] = 0.f;

        #pragma unroll
        for (int ks = 0; ks < 8; ks++) {
            #pragma unroll
            for (int nf = 0; nf < 8; nf++) {
                const int a = (nf * 8 + g) * FS + ks * 8 + tg;
                MMA_TF32(sacc[nf], qf[ks][0], qf[ks][1], qf[ks][2], qf[ks][3],
                         Ks[a], Ks[a + 4]);
            }
        }

        // ---- online softmax ----
        float mx0 = -1e30f, mx1 = -1e30f;
        #pragma unroll
        for (int nf = 0; nf < 8; nf++) {
            mx0 = fmaxf(mx0, fmaxf(sacc[nf][0], sacc[nf][1]));
            mx1 = fmaxf(mx1, fmaxf(sacc[nf][2], sacc[nf][3]));
        }
        mx0 = fmaxf(mx0, __shfl_xor_sync(0xffffffffu, mx0, 1));
        mx0 = fmaxf(mx0, __shfl_xor_sync(0xffffffffu, mx0, 2));
        mx1 = fmaxf(mx1, __shfl_xor_sync(0xffffffffu, mx1, 1));
        mx1 = fmaxf(mx1, __shfl_xor_sync(0xffffffffu, mx1, 2));

        const float mn0 = fmaxf(m0, mx0);
        const float mn1 = fmaxf(m1, mx1);
        const float al0 = __expf(m0 - mn0);
        const float al1 = __expf(m1 - mn1);

        float rs0 = 0.f, rs1 = 0.f;
        #pragma unroll
        for (int nf = 0; nf < 8; nf++) {
            const float p00 = __expf(sacc[nf][0] - mn0);
            const float p01 = __expf(sacc[nf][1] - mn0);
            const float p10 = __expf(sacc[nf][2] - mn1);
            const float p11 = __expf(sacc[nf][3] - mn1);
            rs0 += p00 + p01;
            rs1 += p10 + p11;
            *(uint2*)&QP[r0 * FS + nf * 8 + 2 * tg] =
                make_uint2(__float_as_uint(p00), __float_as_uint(p01));
            *(uint2*)&QP[(r0 + 8) * FS + nf * 8 + 2 * tg] =
                make_uint2(__float_as_uint(p10), __float_as_uint(p11));
            oacc[nf][0] *= al0; oacc[nf][1] *= al0;
            oacc[nf][2] *= al1; oacc[nf][3] *= al1;
        }
        rs0 += __shfl_xor_sync(0xffffffffu, rs0, 1);
        rs0 += __shfl_xor_sync(0xffffffffu, rs0, 2);
        rs1 += __shfl_xor_sync(0xffffffffu, rs1, 1);
        rs1 += __shfl_xor_sync(0xffffffffu, rs1, 2);
        l0 = l0 * al0 + rs0;
        l1 = l1 * al1 + rs1;
        m0 = mn0; m1 = mn1;
        __syncwarp();   // P band is warp-private

        // ---- GEMM2: O += P @ V ----
        #pragma unroll
        for (int ks = 0; ks < 8; ks++) {
            const uint32_t a0 = QP[r0 * FS + ks * 8 + tg];
            const uint32_t a1 = QP[(r0 + 8) * FS + ks * 8 + tg];
            const uint32_t a2 = QP[r0 * FS + ks * 8 + tg + 4];
            const uint32_t a3 = QP[(r0 + 8) * FS + ks * 8 + tg + 4];
            #pragma unroll
            for (int nf = 0; nf < 8; nf++) {
                const int a = (nf * 8 + g) * FS + ks * 8 + tg;
                MMA_TF32(oacc[nf], a0, a1, a2, a3, Vt[a], Vt[a + 4]);
            }
        }
    }

    const float inv0 = 1.0f / l0;
    const float inv1 = 1.0f / l1;
    const size_t base0 = ((size_t)(b * SEQ + q0 + r0)) * DIM + h * HD;
    const size_t base1 = ((size_t)(b * SEQ + q0 + r0 + 8)) * DIM + h * HD;
    #pragma unroll
    for (int nf = 0; nf < 8; nf++) {
        const int col = nf * 8 + 2 * tg;
        *(float2*)&O[base0 + col] = make_float2(oacc[nf][0] * inv0, oacc[nf][1] * inv0);
        *(float2*)&O[base1 + col] = make_float2(oacc[nf][2] * inv1, oacc[nf][3] * inv1);
    }
}

// --------------------------- Cross attention (T=77) ------------------------
__global__ void __launch_bounds__(256)
cross_attn_kernel(const float* __restrict__ Q, const float* __restrict__ K,
                  const float* __restrict__ V, float* __restrict__ O) {
    __shared__ float Ksm[CTXT][65];
    __shared__ float Vsm[CTXT][65];

    const int bh = blockIdx.y;
    const int b = bh >> 3, h = bh & 7;
    const int warp = threadIdx.x >> 5, lane = threadIdx.x & 31;

    for (int idx = threadIdx.x; idx < CTXT * HD; idx += 256) {
        const int j = idx >> 6, d = idx & 63;
        const size_t base = ((size_t)(b * CTXT + j)) * DIM + h * HD + d;
        Ksm[j][d] = K[base];
        Vsm[j][d] = V[base];
    }
    __syncthreads();

    const float scale = 0.125f;
    const int q_base = blockIdx.x * 64 + warp * 8;

    for (int qq = 0; qq < 8; qq++) {
        const int qi = q_base + qq;
        const float* qp = &Q[((size_t)(b * SEQ + qi)) * DIM + h * HD];
        const float q0v = qp[lane];
        const float q1v = qp[lane + 32];

        const int j0 = lane, j1 = lane + 32, j2 = lane + 64;
        float s0 = 0.f, s1 = 0.f, s2 = 0.f;
        #pragma unroll
        for (int d = 0; d < 32; d++) {
            const float qd = __shfl_sync(0xffffffffu, q0v, d);
            s0 = fmaf(qd, Ksm[j0][d], s0);
            s1 = fmaf(qd, Ksm[j1][d], s1);
            if (j2 < CTXT) s2 = fmaf(qd, Ksm[j2][d], s2);
        }
        #pragma unroll
        for (int d = 0; d < 32; d++) {
            const float qd = __shfl_sync(0xffffffffu, q1v, d);
            s0 = fmaf(qd, Ksm[j0][d + 32], s0);
            s1 = fmaf(qd, Ksm[j1][d + 32], s1);
            if (j2 < CTXT) s2 = fmaf(qd, Ksm[j2][d + 32], s2);
        }
        s0 *= scale; s1 *= scale;
        s2 = (j2 < CTXT) ? s2 * scale : -1e30f;

        float mx = fmaxf(fmaxf(s0, s1), s2);
        #pragma unroll
        for (int off = 16; off; off >>= 1)
            mx = fmaxf(mx, __shfl_xor_sync(0xffffffffu, mx, off));

        const float p0 = __expf(s0 - mx);
        const float p1 = __expf(s1 - mx);
        const float p2 = (j2 < CTXT) ? __expf(s2 - mx) : 0.f;
        float sum = p0 + p1 + p2;
        #pragma unroll
        for (int off = 16; off; off >>= 1)
            sum += __shfl_xor_sync(0xffffffffu, sum, off);

        float o0 = 0.f, o1 = 0.f;
        #pragma unroll
        for (int ll = 0; ll < 32; ll++) {
            const float pj = __shfl_sync(0xffffffffu, p0, ll);
            o0 = fmaf(pj, Vsm[ll][lane],      o0);
            o1 = fmaf(pj, Vsm[ll][lane + 32], o1);
        }
        #pragma unroll
        for (int ll = 0; ll < 32; ll++) {
            const float pj = __shfl_sync(0xffffffffu, p1, ll);
            o0 = fmaf(pj, Vsm[32 + ll][lane],      o0);
            o1 = fmaf(pj, Vsm[32 + ll][lane + 32], o1);
        }
        #pragma unroll
        for (int ll = 0; ll < 13; ll++) {
            const float pj = __shfl_sync(0xffffffffu, p2, ll);
            o0 = fmaf(pj, Vsm[64 + ll][lane],      o0);
            o1 = fmaf(pj, Vsm[64 + ll][lane + 32], o1);
        }

        const float inv = 1.0f / sum;
        float* op = &O[((size_t)(b * SEQ + qi)) * DIM + h * HD];
        op[lane]      = o0 * inv;
        op[lane + 32] = o1 * inv;
    }
}

// ------------------------------ GEGLU --------------------------------------
__global__ void geglu_kernel(const float* __restrict__ gg, float* __restrict__ ff) {
    const size_t idx = (size_t)blockIdx.x * 256 + threadIdx.x;
    const size_t mrow = idx >> 11;
    const int    n    = (int)(idx & 2047);
    const float y    = gg[mrow * 4096 + n];
    const float gate = gg[mrow * 4096 + 2048 + n];
    const float t = tanhf(gate * 0.7978845608f * (1.0f + 0.044715f * gate * gate));
    ff[idx] = y * 0.5f * gate * (1.0f + t);
}

// ------------------------------ launch -------------------------------------
extern "C" void kernel_launch(void* const* d_in, const int* in_sizes, int n_in,
                              void* d_out, int out_size) {
    (void)in_sizes; (void)n_in; (void)out_size;
    const float* x       = (const float*)d_in[0];
    const float* context = (const float*)d_in[1];
    const float* ln1_g   = (const float*)d_in[2];
    const float* ln1_b   = (const float*)d_in[3];
    const float* wq1     = (const float*)d_in[4];
    const float* wk1     = (const float*)d_in[5];
    const float* wv1     = (const float*)d_in[6];
    const float* wo1     = (const float*)d_in[7];
    const float* bo1     = (const float*)d_in[8];
    const float* ln2_g   = (const float*)d_in[9];
    const float* ln2_b   = (const float*)d_in[10];
    const float* wq2     = (const float*)d_in[11];
    const float* wk2     = (const float*)d_in[12];
    const float* wv2     = (const float*)d_in[13];
    const float* wo2     = (const float*)d_in[14];
    const float* bo2     = (const float*)d_in[15];
    const float* ln3_g   = (const float*)d_in[16];
    const float* ln3_b   = (const float*)d_in[17];
    const float* geglu_w = (const float*)d_in[18];
    const float* geglu_b = (const float*)d_in[19];
    const float* out_w   = (const float*)d_in[20];
    const float* out_b   = (const float*)d_in[21];
    float* out = (float*)d_out;

    float *xn, *q, *k, *v, *at, *h, *gg, *ff;
    cudaGetSymbolAddress((void**)&xn, g_xn);
    cudaGetSymbolAddress((void**)&q,  g_q);
    cudaGetSymbolAddress((void**)&k,  g_k);
    cudaGetSymbolAddress((void**)&v,  g_v);
    cudaGetSymbolAddress((void**)&at, g_at);
    cudaGetSymbolAddress((void**)&h,  g_h);
    cudaGetSymbolAddress((void**)&gg, g_gg);
    cudaGetSymbolAddress((void**)&ff, g_ff);

    const size_t fa_smem = (size_t)(128 * FS + 64 * FS + 64 * FS) * 4;
    cudaFuncSetAttribute(flash_mma_kernel,
                         cudaFuncAttributeMaxDynamicSharedMemorySize, (int)fa_smem);

    const dim3 blk(256);
    const dim3 g512(DIM / 128, ROWS / 128);          // (4, 64)
    const dim3 g4096(4096 / 128, ROWS / 128);        // (32, 64)
    const dim3 gctx(DIM / 128, (CROWS + 127) / 128); // (4, 2)
    const dim3 gattn(SEQ / 128, BATCH * NH);         // (32, 16)
    const dim3 gxattn(SEQ / 64, BATCH * NH);         // (64, 16)

    // ---- stage 1: self-attention ----
    ln_kernel<<<ROWS, blk>>>(x, ln1_g, ln1_b, xn);
    tgemm_kernel<false, false><<<g512, blk>>>(xn, wq1, nullptr, nullptr, q, ROWS, DIM, DIM);
    tgemm_kernel<false, false><<<g512, blk>>>(xn, wk1, nullptr, nullptr, k, ROWS, DIM, DIM);
    tgemm_kernel<false, false><<<g512, blk>>>(xn, wv1, nullptr, nullptr, v, ROWS, DIM, DIM);
    flash_mma_kernel<<<gattn, blk, fa_smem>>>(q, k, v, at);
    tgemm_kernel<true, true><<<g512, blk>>>(at, wo1, bo1, x, h, ROWS, DIM, DIM);

    // ---- stage 2: cross-attention ----
    ln_kernel<<<ROWS, blk>>>(h, ln2_g, ln2_b, xn);
    tgemm_kernel<false, false><<<g512, blk>>>(xn, wq2, nullptr, nullptr, q, ROWS, DIM, DIM);
    tgemm_kernel<false, false><<<gctx, blk>>>(context, wk2, nullptr, nullptr, k, CROWS, DIM, DIM);
    tgemm_kernel<false, false><<<gctx, blk>>>(context, wv2, nullptr, nullptr, v, CROWS, DIM, DIM);
    cross_attn_kernel<<<gxattn, blk>>>(q, k, v, at);
    tgemm_kernel<true, true><<<g512, blk>>>(at, wo2, bo2, h, h, ROWS, DIM, DIM);

    // ---- stage 3: GEGLU FFN ----
    ln_kernel<<<ROWS, blk>>>(h, ln3_g, ln3_b, xn);
    tgemm_kernel<true, false><<<g4096, blk>>>(xn, geglu_w, geglu_b, nullptr, gg, ROWS, 4096, DIM);
    geglu_kernel<<<(ROWS * 2048) / 256, blk>>>(gg, ff);
    tgemm_kernel<true, true><<<g512, blk>>>(ff, out_w, out_b, h, out, ROWS, DIM, 2048);
}

// round 12
// speedup vs baseline: 2.9334x; 1.0139x over previous
#include <cuda_runtime.h>
#include <cuda_bf16.h>
#include <cstdint>

// ---------------------------------------------------------------------------
// BasicTransformerBlock (SD-style): self-attn + cross-attn + GEGLU.
// Dense GEMMs + self-attention on tensor cores (tf32 mma.sync, fp32 accum,
// HW truncation fp32->tf32). cp.async pipelines everywhere, fused QKV launch,
// double-buffered flash K/V. B=2, S=4096, T=77, DIM=512, H=8, D=64.
// ---------------------------------------------------------------------------

#define BATCH 2
#define SEQ   4096
#define CTXT  77
#define DIM   512
#define NH    8
#define HD    64
#define ROWS  (BATCH * SEQ)      // 8192
#define CROWS (BATCH * CTXT)     // 154

// -------------------------- scratch (static, no allocs) --------------------
__device__ float g_xn[ROWS * DIM];
__device__ float g_q [ROWS * DIM];
__device__ float g_k [ROWS * DIM];
__device__ float g_v [ROWS * DIM];
__device__ float g_at[ROWS * DIM];
__device__ float g_h [ROWS * DIM];
__device__ float g_gg[(size_t)ROWS * 4096];
__device__ float g_ff[(size_t)ROWS * 2048];

#define MMA_TF32(acc, a0, a1, a2, a3, b0, b1)                                  \
    asm volatile(                                                              \
        "mma.sync.aligned.m16n8k8.row.col.f32.tf32.tf32.f32 "                  \
        "{%0,%1,%2,%3}, {%4,%5,%6,%7}, {%8,%9}, {%0,%1,%2,%3};\n"              \
        : "+f"(acc[0]), "+f"(acc[1]), "+f"(acc[2]), "+f"(acc[3])               \
        : "r"(a0), "r"(a1), "r"(a2), "r"(a3), "r"(b0), "r"(b1))

__device__ __forceinline__ uint32_t smem_u32(const void* p) {
    return (uint32_t)__cvta_generic_to_shared(p);
}
__device__ __forceinline__ void cp_async16(uint32_t dst, const void* src) {
    asm volatile("cp.async.ca.shared.global [%0], [%1], 16;\n"
                 :: "r"(dst), "l"(src));
}
__device__ __forceinline__ void cp_async16_pred(uint32_t dst, const void* src, int sz) {
    asm volatile("cp.async.ca.shared.global [%0], [%1], 16, %2;\n"
                 :: "r"(dst), "l"(src), "r"(sz));
}
#define CP_COMMIT() asm volatile("cp.async.commit_group;\n" ::: "memory")
#define CP_WAIT0()  asm volatile("cp.async.wait_group 0;\n" ::: "memory")

// ------------------------------ LayerNorm ----------------------------------
__global__ void ln_kernel(const float* __restrict__ in,
                          const float* __restrict__ gw,
                          const float* __restrict__ bw,
                          float* __restrict__ out) {
    const int row = blockIdx.x;
    const float* x = in + (size_t)row * DIM;
    const int t = threadIdx.x;

    float v0 = x[t];
    float v1 = x[t + 256];
    float s  = v0 + v1;
    float sq = v0 * v0 + v1 * v1;

    #pragma unroll
    for (int off = 16; off; off >>= 1) {
        s  += __shfl_xor_sync(0xffffffffu, s,  off);
        sq += __shfl_xor_sync(0xffffffffu, sq, off);
    }
    __shared__ float ss[8], sqs[8];
    if ((t & 31) == 0) { ss[t >> 5] = s; sqs[t >> 5] = sq; }
    __syncthreads();
    float S = 0.f, SQ = 0.f;
    #pragma unroll
    for (int w = 0; w < 8; w++) { S += ss[w]; SQ += sqs[w]; }

    const float mean = S * (1.0f / DIM);
    const float var  = SQ * (1.0f / DIM) - mean * mean;
    const float inv  = rsqrtf(var + 1e-5f);

    float* o = out + (size_t)row * DIM;
    o[t]       = (v0 - mean) * inv * gw[t]       + bw[t];
    o[t + 256] = (v1 - mean) * inv * gw[t + 256] + bw[t + 256];
}

// ---------------------- TF32 tensor-core GEMM ------------------------------
// 128x128x32 tile, 8 warps (2x4), warp tile 64x32, m16n8k8 tf32.
// cp.async double-buffered smem (fp32 bits, HW-truncated to tf32 by mma).
#define APAD 36    // A frag loads: bank = 4*g + tg -> conflict-free
#define BPAD 136   // B frag loads: bank = 8*tg + g -> conflict-free

template <bool HAS_BIAS, bool HAS_RES>
__device__ __forceinline__ void
tgemm_body(uint32_t* As, uint32_t* Bs,
           const float* __restrict__ A, const float* __restrict__ B,
           const float* __restrict__ bias, const float* __restrict__ Res,
           float* __restrict__ C, int M, int N, int K,
           int rowBase, int colBase) {
    const int tid  = threadIdx.x;
    const int lane = tid & 31;
    const int wid  = tid >> 5;
    const int wr   = wid >> 2;
    const int wc   = wid & 3;
    const int g    = lane >> 2;
    const int tg   = lane & 3;

    const int aRow = tid >> 1;          // 0..127
    const int aCol = (tid & 1) << 4;    // 0 or 16
    const int bRow = tid >> 3;          // 0..31
    const int bCol = (tid & 7) << 4;    // 0..112

    const uint32_t asB = smem_u32(As);
    const uint32_t bsB = smem_u32(Bs);

    const int grow = rowBase + aRow;
    const int aok  = (grow < M) ? 16 : 0;
    const float* aBase = A + (size_t)(grow < M ? grow : 0) * K + aCol;
    const float* bBase = B + (size_t)bRow * N + colBase + bCol;

    const int T = K >> 5;

    {
        const uint32_t ad = asB + (uint32_t)(aRow * APAD + aCol) * 4;
        const uint32_t bd = bsB + (uint32_t)(bRow * BPAD + bCol) * 4;
        #pragma unroll
        for (int i = 0; i < 4; i++) cp_async16_pred(ad + 16u * i, aBase + 4 * i, aok);
        #pragma unroll
        for (int i = 0; i < 4; i++) cp_async16(bd + 16u * i, bBase + 4 * i);
        CP_COMMIT();
    }

    float acc[4][4][4];
    #pragma unroll
    for (int mf = 0; mf < 4; mf++)
        #pragma unroll
        for (int nf = 0; nf < 4; nf++)
            #pragma unroll
            for (int c = 0; c < 4; c++) acc[mf][nf][c] = 0.f;

    for (int t = 0; t < T; t++) {
        CP_WAIT0();
        __syncthreads();

        if (t + 1 < T) {
            const int k0 = (t + 1) << 5;
            const int nb = (t + 1) & 1;
            const uint32_t ad = asB + (uint32_t)(nb * 128 * APAD + aRow * APAD + aCol) * 4;
            const uint32_t bd = bsB + (uint32_t)(nb * 32 * BPAD + bRow * BPAD + bCol) * 4;
            #pragma unroll
            for (int i = 0; i < 4; i++) cp_async16_pred(ad + 16u * i, aBase + k0 + 4 * i, aok);
            #pragma unroll
            for (int i = 0; i < 4; i++)
                cp_async16(bd + 16u * i, bBase + (size_t)k0 * N + 4 * i);
            CP_COMMIT();
        }

        const uint32_t* as = As + (t & 1) * 128 * APAD;
        const uint32_t* bs = Bs + (t & 1) * 32 * BPAD;

        #pragma unroll
        for (int ks = 0; ks < 4; ks++) {
            const int k0 = ks * 8;
            uint32_t afr[4][4], bfr[4][2];
            #pragma unroll
            for (int mf = 0; mf < 4; mf++) {
                const int r0 = (wr * 64 + mf * 16 + g) * APAD + k0 + tg;
                afr[mf][0] = as[r0];
                afr[mf][1] = as[r0 + 8 * APAD];
                afr[mf][2] = as[r0 + 4];
                afr[mf][3] = as[r0 + 8 * APAD + 4];
            }
            #pragma unroll
            for (int nf = 0; nf < 4; nf++) {
                const int c0 = (k0 + tg) * BPAD + wc * 32 + nf * 8 + g;
                bfr[nf][0] = bs[c0];
                bfr[nf][1] = bs[c0 + 4 * BPAD];
            }
            #pragma unroll
            for (int mf = 0; mf < 4; mf++)
                #pragma unroll
                for (int nf = 0; nf < 4; nf++)
                    MMA_TF32(acc[mf][nf], afr[mf][0], afr[mf][1], afr[mf][2], afr[mf][3],
                             bfr[nf][0], bfr[nf][1]);
        }
    }

    #pragma unroll
    for (int mf = 0; mf < 4; mf++) {
        #pragma unroll
        for (int half = 0; half < 2; half++) {
            const int row = rowBase + wr * 64 + mf * 16 + g + 8 * half;
            if (row >= M) continue;
            #pragma unroll
            for (int nf = 0; nf < 4; nf++) {
                const int col = colBase + wc * 32 + nf * 8 + 2 * tg;
                float2 v = half ? make_float2(acc[mf][nf][2], acc[mf][nf][3])
                                : make_float2(acc[mf][nf][0], acc[mf][nf][1]);
                if (HAS_BIAS) {
                    const float2 bv = *(const float2*)&bias[col];
                    v.x += bv.x; v.y += bv.y;
                }
                if (HAS_RES) {
                    const float2 rv = *(const float2*)&Res[(size_t)row * N + col];
                    v.x += rv.x; v.y += rv.y;
                }
                *(float2*)&C[(size_t)row * N + col] = v;
            }
        }
    }
}

template <bool HAS_BIAS, bool HAS_RES>
__global__ void __launch_bounds__(256, 2)
tgemm_kernel(const float* __restrict__ A, const float* __restrict__ B,
             const float* __restrict__ bias, const float* __restrict__ Res,
             float* __restrict__ C, int M, int N, int K) {
    __shared__ uint32_t As[2 * 128 * APAD];
    __shared__ uint32_t Bs[2 * 32 * BPAD];
    tgemm_body<HAS_BIAS, HAS_RES>(As, Bs, A, B, bias, Res, C, M, N, K,
                                  blockIdx.y * 128, blockIdx.x * 128);
}

// Fused QKV: one launch, blockIdx.z selects weight/output (shared A).
__global__ void __launch_bounds__(256, 2)
tgemm_qkv_kernel(const float* __restrict__ A,
                 const float* __restrict__ B0, const float* __restrict__ B1,
                 const float* __restrict__ B2,
                 float* __restrict__ C0, float* __restrict__ C1,
                 float* __restrict__ C2, int M, int N, int K) {
    __shared__ uint32_t As[2 * 128 * APAD];
    __shared__ uint32_t Bs[2 * 32 * BPAD];
    const int z = blockIdx.z;
    const float* B = (z == 0) ? B0 : (z == 1) ? B1 : B2;
    float*       C = (z == 0) ? C0 : (z == 1) ? C1 : C2;
    tgemm_body<false, false>(As, Bs, A, B, nullptr, nullptr, C, M, N, K,
                             blockIdx.y * 128, blockIdx.x * 128);
}

// ---------------- Flash self-attention on tensor cores (tf32) --------------
// grid (SEQ/128, B*H), 256 threads = 8 warps; warp owns 16 q-rows x 64 keys.
// K/V double-buffered via cp.async (copy for tile t+1 overlaps compute of t).
// K: [j][d] stride 68 (GEMM1 B-frag bank = 4g+tg). V: [j][d] stride 72
// (GEMM2 B-frag bank = 8tg+g) -> direct async copy, no transpose.
#define FS 68
#define VS 72
__global__ void __launch_bounds__(256)
flash_mma_kernel(const float* __restrict__ Q, const float* __restrict__ K,
                 const float* __restrict__ V, float* __restrict__ O) {
    extern __shared__ uint32_t sm[];
    uint32_t* QP = sm;                       // [128][FS] : Qs then Ps
    uint32_t* Ks = sm + 128 * FS;            // [2][64][FS]
    uint32_t* Vs = Ks + 2 * 64 * FS;         // [2][64][VS]

    const int bh = blockIdx.y;
    const int b = bh >> 3, h = bh & 7;
    const int q0 = blockIdx.x * 128;
    const int tid = threadIdx.x;
    const int lane = tid & 31;
    const int wid = tid >> 5;
    const int g = lane >> 2, tg = lane & 3;

    const uint32_t ksB = smem_u32(Ks);
    const uint32_t vsB = smem_u32(Vs);

    const int cli = tid >> 2;                // copy row 0..63
    const int cdb = (tid & 3) << 2;          // copy d base 0,4,8,12

    // ---- prologue: issue K/V copy for tile 0 ----
    {
        const size_t base = ((size_t)(b * SEQ + cli)) * DIM + h * HD;
        const uint32_t kd = ksB + (uint32_t)(cli * FS + cdb) * 4;
        const uint32_t vd = vsB + (uint32_t)(cli * VS + cdb) * 4;
        #pragma unroll
        for (int c = 0; c < 4; c++) {
            cp_async16(kd + 64u * c, &K[base + cdb + 16 * c]);
            cp_async16(vd + 64u * c, &V[base + cdb + 16 * c]);
        }
        CP_COMMIT();
    }

    // ---- stage Q tile to smem (scale folded; raw fp32 bits) ----
    {
        const int li = tid >> 1;             // 0..127 (warp-private band)
        const int db = (tid & 1) * 32;
        const float* qrow = &Q[((size_t)(b * SEQ + q0 + li)) * DIM + h * HD];
        #pragma unroll
        for (int c = 0; c < 8; c++) {
            const int d4 = db + 4 * c;
            const float4 qv = *(const float4*)&qrow[d4];
            uint4 u = make_uint4(__float_as_uint(qv.x * 0.125f),
                                 __float_as_uint(qv.y * 0.125f),
                                 __float_as_uint(qv.z * 0.125f),
                                 __float_as_uint(qv.w * 0.125f));
            *(uint4*)&QP[li * FS + d4] = u;
        }
    }
    __syncwarp();

    const int r0 = wid * 16 + g;
    uint32_t qf[8][4];
    #pragma unroll
    for (int ks = 0; ks < 8; ks++) {
        qf[ks][0] = QP[r0 * FS + ks * 8 + tg];
        qf[ks][1] = QP[(r0 + 8) * FS + ks * 8 + tg];
        qf[ks][2] = QP[r0 * FS + ks * 8 + tg + 4];
        qf[ks][3] = QP[(r0 + 8) * FS + ks * 8 + tg + 4];
    }

    float m0 = -1e30f, m1 = -1e30f, l0 = 0.f, l1 = 0.f;
    float oacc[8][4];
    #pragma unroll
    for (int nf = 0; nf < 8; nf++)
        #pragma unroll
        for (int c = 0; c < 4; c++) oacc[nf][c] = 0.f;

    const int T = SEQ / 64;
    for (int t = 0; t < T; t++) {
        CP_WAIT0();
        __syncthreads();   // tile t resident; prior tile's buffers free

        if (t + 1 < T) {   // issue copy for tile t+1 into alternate buffer
            const int nb = (t + 1) & 1;
            const size_t base = ((size_t)(b * SEQ + (t + 1) * 64 + cli)) * DIM + h * HD;
            const uint32_t kd = ksB + (uint32_t)(nb * 64 * FS + cli * FS + cdb) * 4;
            const uint32_t vd = vsB + (uint32_t)(nb * 64 * VS + cli * VS + cdb) * 4;
            #pragma unroll
            for (int c = 0; c < 4; c++) {
                cp_async16(kd + 64u * c, &K[base + cdb + 16 * c]);
                cp_async16(vd + 64u * c, &V[base + cdb + 16 * c]);
            }
            CP_COMMIT();
        }

        const uint32_t* Kb = Ks + (t & 1) * 64 * FS;
        const uint32_t* Vb = Vs + (t & 1) * 64 * VS;

        // ---- GEMM1: S[16x64] = Qw @ K^T ----
        float sacc[8][4];
        #pragma unroll
        for (int nf = 0; nf < 8; nf++)
            #pragma unroll
            for (int c = 0; c < 4; c++) sacc[nf][c] = 0.f;

        #pragma unroll
        for (int ks = 0; ks < 8; ks++) {
            #pragma unroll
            for (int nf = 0; nf < 8; nf++) {
                const int a = (nf * 8 + g) * FS + ks * 8 + tg;
                MMA_TF32(sacc[nf], qf[ks][0], qf[ks][1], qf[ks][2], qf[ks][3],
                         Kb[a], Kb[a + 4]);
            }
        }

        // ---- online softmax ----
        float mx0 = -1e30f, mx1 = -1e30f;
        #pragma unroll
        for (int nf = 0; nf < 8; nf++) {
            mx0 = fmaxf(mx0, fmaxf(sacc[nf][0], sacc[nf][1]));
            mx1 = fmaxf(mx1, fmaxf(sacc[nf][2], sacc[nf][3]));
        }
        mx0 = fmaxf(mx0, __shfl_xor_sync(0xffffffffu, mx0, 1));
        mx0 = fmaxf(mx0, __shfl_xor_sync(0xffffffffu, mx0, 2));
        mx1 = fmaxf(mx1, __shfl_xor_sync(0xffffffffu, mx1, 1));
        mx1 = fmaxf(mx1, __shfl_xor_sync(0xffffffffu, mx1, 2));

        const float mn0 = fmaxf(m0, mx0);
        const float mn1 = fmaxf(m1, mx1);
        const float al0 = __expf(m0 - mn0);
        const float al1 = __expf(m1 - mn1);

        float rs0 = 0.f, rs1 = 0.f;
        #pragma unroll
        for (int nf = 0; nf < 8; nf++) {
            const float p00 = __expf(sacc[nf][0] - mn0);
            const float p01 = __expf(sacc[nf][1] - mn0);
            const float p10 = __expf(sacc[nf][2] - mn1);
            const float p11 = __expf(sacc[nf][3] - mn1);
            rs0 += p00 + p01;
            rs1 += p10 + p11;
            *(uint2*)&QP[r0 * FS + nf * 8 + 2 * tg] =
                make_uint2(__float_as_uint(p00), __float_as_uint(p01));
            *(uint2*)&QP[(r0 + 8) * FS + nf * 8 + 2 * tg] =
                make_uint2(__float_as_uint(p10), __float_as_uint(p11));
            oacc[nf][0] *= al0; oacc[nf][1] *= al0;
            oacc[nf][2] *= al1; oacc[nf][3] *= al1;
        }
        rs0 += __shfl_xor_sync(0xffffffffu, rs0, 1);
        rs0 += __shfl_xor_sync(0xffffffffu, rs0, 2);
        rs1 += __shfl_xor_sync(0xffffffffu, rs1, 1);
        rs1 += __shfl_xor_sync(0xffffffffu, rs1, 2);
        l0 = l0 * al0 + rs0;
        l1 = l1 * al1 + rs1;
        m0 = mn0; m1 = mn1;
        __syncwarp();   // P band is warp-private

        // ---- GEMM2: O += P @ V ----
        #pragma unroll
        for (int ks = 0; ks < 8; ks++) {
            const uint32_t a0 = QP[r0 * FS + ks * 8 + tg];
            const uint32_t a1 = QP[(r0 + 8) * FS + ks * 8 + tg];
            const uint32_t a2 = QP[r0 * FS + ks * 8 + tg + 4];
            const uint32_t a3 = QP[(r0 + 8) * FS + ks * 8 + tg + 4];
            #pragma unroll
            for (int nf = 0; nf < 8; nf++) {
                const int a = (ks * 8 + tg) * VS + nf * 8 + g;
                MMA_TF32(oacc[nf], a0, a1, a2, a3, Vb[a], Vb[a + 4 * VS]);
            }
        }
    }

    const float inv0 = 1.0f / l0;
    const float inv1 = 1.0f / l1;
    const size_t base0 = ((size_t)(b * SEQ + q0 + r0)) * DIM + h * HD;
    const size_t base1 = ((size_t)(b * SEQ + q0 + r0 + 8)) * DIM + h * HD;
    #pragma unroll
    for (int nf = 0; nf < 8; nf++) {
        const int col = nf * 8 + 2 * tg;
        *(float2*)&O[base0 + col] = make_float2(oacc[nf][0] * inv0, oacc[nf][1] * inv0);
        *(float2*)&O[base1 + col] = make_float2(oacc[nf][2] * inv1, oacc[nf][3] * inv1);
    }
}

// --------------------------- Cross attention (T=77) ------------------------
__global__ void __launch_bounds__(256)
cross_attn_kernel(const float* __restrict__ Q, const float* __restrict__ K,
                  const float* __restrict__ V, float* __restrict__ O) {
    __shared__ float Ksm[CTXT][65];
    __shared__ float Vsm[CTXT][65];

    const int bh = blockIdx.y;
    const int b = bh >> 3, h = bh & 7;
    const int warp = threadIdx.x >> 5, lane = threadIdx.x & 31;

    for (int idx = threadIdx.x; idx < CTXT * HD; idx += 256) {
        const int j = idx >> 6, d = idx & 63;
        const size_t base = ((size_t)(b * CTXT + j)) * DIM + h * HD + d;
        Ksm[j][d] = K[base];
        Vsm[j][d] = V[base];
    }
    __syncthreads();

    const float scale = 0.125f;
    const int q_base = blockIdx.x * 64 + warp * 8;

    for (int qq = 0; qq < 8; qq++) {
        const int qi = q_base + qq;
        const float* qp = &Q[((size_t)(b * SEQ + qi)) * DIM + h * HD];
        const float q0v = qp[lane];
        const float q1v = qp[lane + 32];

        const int j0 = lane, j1 = lane + 32, j2 = lane + 64;
        float s0 = 0.f, s1 = 0.f, s2 = 0.f;
        #pragma unroll
        for (int d = 0; d < 32; d++) {
            const float qd = __shfl_sync(0xffffffffu, q0v, d);
            s0 = fmaf(qd, Ksm[j0][d], s0);
            s1 = fmaf(qd, Ksm[j1][d], s1);
            if (j2 < CTXT) s2 = fmaf(qd, Ksm[j2][d], s2);
        }
        #pragma unroll
        for (int d = 0; d < 32; d++) {
            const float qd = __shfl_sync(0xffffffffu, q1v, d);
            s0 = fmaf(qd, Ksm[j0][d + 32], s0);
            s1 = fmaf(qd, Ksm[j1][d + 32], s1);
            if (j2 < CTXT) s2 = fmaf(qd, Ksm[j2][d + 32], s2);
        }
        s0 *= scale; s1 *= scale;
        s2 = (j2 < CTXT) ? s2 * scale : -1e30f;

        float mx = fmaxf(fmaxf(s0, s1), s2);
        #pragma unroll
        for (int off = 16; off; off >>= 1)
            mx = fmaxf(mx, __shfl_xor_sync(0xffffffffu, mx, off));

        const float p0 = __expf(s0 - mx);
        const float p1 = __expf(s1 - mx);
        const float p2 = (j2 < CTXT) ? __expf(s2 - mx) : 0.f;
        float sum = p0 + p1 + p2;
        #pragma unroll
        for (int off = 16; off; off >>= 1)
            sum += __shfl_xor_sync(0xffffffffu, sum, off);

        float o0 = 0.f, o1 = 0.f;
        #pragma unroll
        for (int ll = 0; ll < 32; ll++) {
            const float pj = __shfl_sync(0xffffffffu, p0, ll);
            o0 = fmaf(pj, Vsm[ll][lane],      o0);
            o1 = fmaf(pj, Vsm[ll][lane + 32], o1);
        }
        #pragma unroll
        for (int ll = 0; ll < 32; ll++) {
            const float pj = __shfl_sync(0xffffffffu, p1, ll);
            o0 = fmaf(pj, Vsm[32 + ll][lane],      o0);
            o1 = fmaf(pj, Vsm[32 + ll][lane + 32], o1);
        }
        #pragma unroll
        for (int ll = 0; ll < 13; ll++) {
            const float pj = __shfl_sync(0xffffffffu, p2, ll);
            o0 = fmaf(pj, Vsm[64 + ll][lane],      o0);
            o1 = fmaf(pj, Vsm[64 + ll][lane + 32], o1);
        }

        const float inv = 1.0f / sum;
        float* op = &O[((size_t)(b * SEQ + qi)) * DIM + h * HD];
        op[lane]      = o0 * inv;
        op[lane + 32] = o1 * inv;
    }
}

// ------------------------------ GEGLU --------------------------------------
__global__ void geglu_kernel(const float* __restrict__ gg, float* __restrict__ ff) {
    const size_t idx = (size_t)blockIdx.x * 256 + threadIdx.x;
    const size_t mrow = idx >> 11;
    const int    n    = (int)(idx & 2047);
    const float y    = gg[mrow * 4096 + n];
    const float gate = gg[mrow * 4096 + 2048 + n];
    const float t = tanhf(gate * 0.7978845608f * (1.0f + 0.044715f * gate * gate));
    ff[idx] = y * 0.5f * gate * (1.0f + t);
}

// ------------------------------ launch -------------------------------------
extern "C" void kernel_launch(void* const* d_in, const int* in_sizes, int n_in,
                              void* d_out, int out_size) {
    (void)in_sizes; (void)n_in; (void)out_size;
    const float* x       = (const float*)d_in[0];
    const float* context = (const float*)d_in[1];
    const float* ln1_g   = (const float*)d_in[2];
    const float* ln1_b   = (const float*)d_in[3];
    const float* wq1     = (const float*)d_in[4];
    const float* wk1     = (const float*)d_in[5];
    const float* wv1     = (const float*)d_in[6];
    const float* wo1     = (const float*)d_in[7];
    const float* bo1     = (const float*)d_in[8];
    const float* ln2_g   = (const float*)d_in[9];
    const float* ln2_b   = (const float*)d_in[10];
    const float* wq2     = (const float*)d_in[11];
    const float* wk2     = (const float*)d_in[12];
    const float* wv2     = (const float*)d_in[13];
    const float* wo2     = (const float*)d_in[14];
    const float* bo2     = (const float*)d_in[15];
    const float* ln3_g   = (const float*)d_in[16];
    const float* ln3_b   = (const float*)d_in[17];
    const float* geglu_w = (const float*)d_in[18];
    const float* geglu_b = (const float*)d_in[19];
    const float* out_w   = (const float*)d_in[20];
    const float* out_b   = (const float*)d_in[21];
    float* out = (float*)d_out;

    float *xn, *q, *k, *v, *at, *h, *gg, *ff;
    cudaGetSymbolAddress((void**)&xn, g_xn);
    cudaGetSymbolAddress((void**)&q,  g_q);
    cudaGetSymbolAddress((void**)&k,  g_k);
    cudaGetSymbolAddress((void**)&v,  g_v);
    cudaGetSymbolAddress((void**)&at, g_at);
    cudaGetSymbolAddress((void**)&h,  g_h);
    cudaGetSymbolAddress((void**)&gg, g_gg);
    cudaGetSymbolAddress((void**)&ff, g_ff);

    // QP 128*68 + Ks 2*64*68 + Vs 2*64*72 = 26624 words = 106496 B
    const size_t fa_smem = (size_t)(128 * FS + 2 * 64 * FS + 2 * 64 * VS) * 4;
    cudaFuncSetAttribute(flash_mma_kernel,
                         cudaFuncAttributeMaxDynamicSharedMemorySize, (int)fa_smem);

    const dim3 blk(256);
    const dim3 gqkv(DIM / 128, ROWS / 128, 3);       // (4, 64, 3)
    const dim3 g512(DIM / 128, ROWS / 128);          // (4, 64)
    const dim3 g4096(4096 / 128, ROWS / 128);        // (32, 64)
    const dim3 gctx(DIM / 128, (CROWS + 127) / 128); // (4, 2)
    const dim3 gattn(SEQ / 128, BATCH * NH);         // (32, 16)
    const dim3 gxattn(SEQ / 64, BATCH * NH);         // (64, 16)

    // ---- stage 1: self-attention ----
    ln_kernel<<<ROWS, blk>>>(x, ln1_g, ln1_b, xn);
    tgemm_qkv_kernel<<<gqkv, blk>>>(xn, wq1, wk1, wv1, q, k, v, ROWS, DIM, DIM);
    flash_mma_kernel<<<gattn, blk, fa_smem>>>(q, k, v, at);
    tgemm_kernel<true, true><<<g512, blk>>>(at, wo1, bo1, x, h, ROWS, DIM, DIM);

    // ---- stage 2: cross-attention ----
    ln_kernel<<<ROWS, blk>>>(h, ln2_g, ln2_b, xn);
    tgemm_kernel<false, false><<<g512, blk>>>(xn, wq2, nullptr, nullptr, q, ROWS, DIM, DIM);
    tgemm_kernel<false, false><<<gctx, blk>>>(context, wk2, nullptr, nullptr, k, CROWS, DIM, DIM);
    tgemm_kernel<false, false><<<gctx, blk>>>(context, wv2, nullptr, nullptr, v, CROWS, DIM, DIM);
    cross_attn_kernel<<<gxattn, blk>>>(q, k, v, at);
    tgemm_kernel<true, true><<<g512, blk>>>(at, wo2, bo2, h, h, ROWS, DIM, DIM);

    // ---- stage 3: GEGLU FFN ----
    ln_kernel<<<ROWS, blk>>>(h, ln3_g, ln3_b, xn);
    tgemm_kernel<true, false><<<g4096, blk>>>(xn, geglu_w, geglu_b, nullptr, gg, ROWS, 4096, DIM);
    geglu_kernel<<<(ROWS * 2048) / 256, blk>>>(gg, ff);
    tgemm_kernel<true, true><<<g512, blk>>>(ff, out_w, out_b, h, out, ROWS, DIM, 2048);
}

// round 13
// speedup vs baseline: 3.0307x; 1.0332x over previous
#include <cuda_runtime.h>
#include <cuda_bf16.h>
#include <cstdint>

// ---------------------------------------------------------------------------
// BasicTransformerBlock (SD-style): self-attn + cross-attn + GEGLU.
// Dense GEMMs + self-attention on tensor cores (tf32 mma.sync, fp32 accum).
// cp.async pipelines + (ks,mf)-granular fragment double-buffering.
// B=2, S=4096, T=77, DIM=512, H=8, D=64.
// ---------------------------------------------------------------------------

#define BATCH 2
#define SEQ   4096
#define CTXT  77
#define DIM   512
#define NH    8
#define HD    64
#define ROWS  (BATCH * SEQ)      // 8192
#define CROWS (BATCH * CTXT)     // 154

// -------------------------- scratch (static, no allocs) --------------------
__device__ float g_xn[ROWS * DIM];
__device__ float g_q [ROWS * DIM];
__device__ float g_k [ROWS * DIM];
__device__ float g_v [ROWS * DIM];
__device__ float g_at[ROWS * DIM];
__device__ float g_h [ROWS * DIM];
__device__ float g_gg[(size_t)ROWS * 4096];
__device__ float g_ff[(size_t)ROWS * 2048];

#define MMA_TF32(acc, a0, a1, a2, a3, b0, b1)                                  \
    asm volatile(                                                              \
        "mma.sync.aligned.m16n8k8.row.col.f32.tf32.tf32.f32 "                  \
        "{%0,%1,%2,%3}, {%4,%5,%6,%7}, {%8,%9}, {%0,%1,%2,%3};\n"              \
        : "+f"(acc[0]), "+f"(acc[1]), "+f"(acc[2]), "+f"(acc[3])               \
        : "r"(a0), "r"(a1), "r"(a2), "r"(a3), "r"(b0), "r"(b1))

__device__ __forceinline__ uint32_t smem_u32(const void* p) {
    return (uint32_t)__cvta_generic_to_shared(p);
}
__device__ __forceinline__ void cp_async16(uint32_t dst, const void* src) {
    asm volatile("cp.async.ca.shared.global [%0], [%1], 16;\n"
                 :: "r"(dst), "l"(src));
}
__device__ __forceinline__ void cp_async16_pred(uint32_t dst, const void* src, int sz) {
    asm volatile("cp.async.ca.shared.global [%0], [%1], 16, %2;\n"
                 :: "r"(dst), "l"(src), "r"(sz));
}
#define CP_COMMIT() asm volatile("cp.async.commit_group;\n" ::: "memory")
#define CP_WAIT0()  asm volatile("cp.async.wait_group 0;\n" ::: "memory")

// ------------------------------ LayerNorm ----------------------------------
__global__ void ln_kernel(const float* __restrict__ in,
                          const float* __restrict__ gw,
                          const float* __restrict__ bw,
                          float* __restrict__ out) {
    const int row = blockIdx.x;
    const float* x = in + (size_t)row * DIM;
    const int t = threadIdx.x;

    float v0 = x[t];
    float v1 = x[t + 256];
    float s  = v0 + v1;
    float sq = v0 * v0 + v1 * v1;

    #pragma unroll
    for (int off = 16; off; off >>= 1) {
        s  += __shfl_xor_sync(0xffffffffu, s,  off);
        sq += __shfl_xor_sync(0xffffffffu, sq, off);
    }
    __shared__ float ss[8], sqs[8];
    if ((t & 31) == 0) { ss[t >> 5] = s; sqs[t >> 5] = sq; }
    __syncthreads();
    float S = 0.f, SQ = 0.f;
    #pragma unroll
    for (int w = 0; w < 8; w++) { S += ss[w]; SQ += sqs[w]; }

    const float mean = S * (1.0f / DIM);
    const float var  = SQ * (1.0f / DIM) - mean * mean;
    const float inv  = rsqrtf(var + 1e-5f);

    float* o = out + (size_t)row * DIM;
    o[t]       = (v0 - mean) * inv * gw[t]       + bw[t];
    o[t + 256] = (v1 - mean) * inv * gw[t + 256] + bw[t + 256];
}

// ---------------------- TF32 tensor-core GEMM ------------------------------
// 128x128x32 tile, 8 warps (2x4), warp tile 64x32, m16n8k8 tf32.
// cp.async double-buffered smem + register fragment double-buffering.
#define APAD 36    // A frag loads: bank = 4*g + tg -> conflict-free
#define BPAD 136   // B frag loads: bank = 8*tg + g -> conflict-free

template <bool HAS_BIAS, bool HAS_RES>
__device__ __forceinline__ void
tgemm_body(uint32_t* As, uint32_t* Bs,
           const float* __restrict__ A, const float* __restrict__ B,
           const float* __restrict__ bias, const float* __restrict__ Res,
           float* __restrict__ C, int M, int N, int K,
           int rowBase, int colBase) {
    const int tid  = threadIdx.x;
    const int lane = tid & 31;
    const int wid  = tid >> 5;
    const int wr   = wid >> 2;
    const int wc   = wid & 3;
    const int g    = lane >> 2;
    const int tg   = lane & 3;

    const int aRow = tid >> 1;          // 0..127
    const int aCol = (tid & 1) << 4;    // 0 or 16
    const int bRow = tid >> 3;          // 0..31
    const int bCol = (tid & 7) << 4;    // 0..112

    const uint32_t asB = smem_u32(As);
    const uint32_t bsB = smem_u32(Bs);

    const int grow = rowBase + aRow;
    const int aok  = (grow < M) ? 16 : 0;
    const float* aBase = A + (size_t)(grow < M ? grow : 0) * K + aCol;
    const float* bBase = B + (size_t)bRow * N + colBase + bCol;

    const int T = K >> 5;

    {
        const uint32_t ad = asB + (uint32_t)(aRow * APAD + aCol) * 4;
        const uint32_t bd = bsB + (uint32_t)(bRow * BPAD + bCol) * 4;
        #pragma unroll
        for (int i = 0; i < 4; i++) cp_async16_pred(ad + 16u * i, aBase + 4 * i, aok);
        #pragma unroll
        for (int i = 0; i < 4; i++) cp_async16(bd + 16u * i, bBase + 4 * i);
        CP_COMMIT();
    }

    float acc[4][4][4];
    #pragma unroll
    for (int mf = 0; mf < 4; mf++)
        #pragma unroll
        for (int nf = 0; nf < 4; nf++)
            #pragma unroll
            for (int c = 0; c < 4; c++) acc[mf][nf][c] = 0.f;

    // fragment load helpers (compile-time indices)
#define LOAD_AFR(dst, mf_, ks_) {                                              \
        const int r_ = (wr * 64 + (mf_) * 16 + g) * APAD + (ks_) * 8 + tg;     \
        (dst)[0] = as[r_];                                                     \
        (dst)[1] = as[r_ + 8 * APAD];                                          \
        (dst)[2] = as[r_ + 4];                                                 \
        (dst)[3] = as[r_ + 8 * APAD + 4]; }
#define LOAD_BFR(dst, ks_) {                                                   \
        const int c_ = ((ks_) * 8 + tg) * BPAD + wc * 32 + g;                  \
        _Pragma("unroll")                                                      \
        for (int nf_ = 0; nf_ < 4; nf_++) {                                    \
            (dst)[2 * nf_]     = bs[c_ + nf_ * 8];                             \
            (dst)[2 * nf_ + 1] = bs[c_ + nf_ * 8 + 4 * BPAD]; } }

    for (int t = 0; t < T; t++) {
        CP_WAIT0();
        __syncthreads();

        if (t + 1 < T) {
            const int k0 = (t + 1) << 5;
            const int nb = (t + 1) & 1;
            const uint32_t ad = asB + (uint32_t)(nb * 128 * APAD + aRow * APAD + aCol) * 4;
            const uint32_t bd = bsB + (uint32_t)(nb * 32 * BPAD + bRow * BPAD + bCol) * 4;
            #pragma unroll
            for (int i = 0; i < 4; i++) cp_async16_pred(ad + 16u * i, aBase + k0 + 4 * i, aok);
            #pragma unroll
            for (int i = 0; i < 4; i++)
                cp_async16(bd + 16u * i, bBase + (size_t)k0 * N + 4 * i);
            CP_COMMIT();
        }

        const uint32_t* as = As + (t & 1) * 128 * APAD;
        const uint32_t* bs = Bs + (t & 1) * 32 * BPAD;

        uint32_t afr[2][4], bfr[2][8];
        LOAD_BFR(bfr[0], 0);
        LOAD_AFR(afr[0], 0, 0);

        #pragma unroll
        for (int ks = 0; ks < 4; ks++) {
            const int kb = ks & 1;
            #pragma unroll
            for (int mf = 0; mf < 4; mf++) {
                const int cur = (ks * 4 + mf) & 1;
                const int nxt = cur ^ 1;
                if (mf < 3) {
                    LOAD_AFR(afr[nxt], mf + 1, ks);
                } else if (ks < 3) {
                    LOAD_AFR(afr[nxt], 0, ks + 1);
                    LOAD_BFR(bfr[kb ^ 1], ks + 1);
                }
                #pragma unroll
                for (int nf = 0; nf < 4; nf++)
                    MMA_TF32(acc[mf][nf],
                             afr[cur][0], afr[cur][1], afr[cur][2], afr[cur][3],
                             bfr[kb][2 * nf], bfr[kb][2 * nf + 1]);
            }
        }
    }
#undef LOAD_AFR
#undef LOAD_BFR

    #pragma unroll
    for (int mf = 0; mf < 4; mf++) {
        #pragma unroll
        for (int half = 0; half < 2; half++) {
            const int row = rowBase + wr * 64 + mf * 16 + g + 8 * half;
            if (row >= M) continue;
            #pragma unroll
            for (int nf = 0; nf < 4; nf++) {
                const int col = colBase + wc * 32 + nf * 8 + 2 * tg;
                float2 v = half ? make_float2(acc[mf][nf][2], acc[mf][nf][3])
                                : make_float2(acc[mf][nf][0], acc[mf][nf][1]);
                if (HAS_BIAS) {
                    const float2 bv = *(const float2*)&bias[col];
                    v.x += bv.x; v.y += bv.y;
                }
                if (HAS_RES) {
                    const float2 rv = *(const float2*)&Res[(size_t)row * N + col];
                    v.x += rv.x; v.y += rv.y;
                }
                *(float2*)&C[(size_t)row * N + col] = v;
            }
        }
    }
}

template <bool HAS_BIAS, bool HAS_RES>
__global__ void __launch_bounds__(256, 2)
tgemm_kernel(const float* __restrict__ A, const float* __restrict__ B,
             const float* __restrict__ bias, const float* __restrict__ Res,
             float* __restrict__ C, int M, int N, int K) {
    __shared__ uint32_t As[2 * 128 * APAD];
    __shared__ uint32_t Bs[2 * 32 * BPAD];
    tgemm_body<HAS_BIAS, HAS_RES>(As, Bs, A, B, bias, Res, C, M, N, K,
                                  blockIdx.y * 128, blockIdx.x * 128);
}

// Fused QKV: one launch, blockIdx.z selects weight/output (shared A).
__global__ void __launch_bounds__(256, 2)
tgemm_qkv_kernel(const float* __restrict__ A,
                 const float* __restrict__ B0, const float* __restrict__ B1,
                 const float* __restrict__ B2,
                 float* __restrict__ C0, float* __restrict__ C1,
                 float* __restrict__ C2, int M, int N, int K) {
    __shared__ uint32_t As[2 * 128 * APAD];
    __shared__ uint32_t Bs[2 * 32 * BPAD];
    const int z = blockIdx.z;
    const float* B = (z == 0) ? B0 : (z == 1) ? B1 : B2;
    float*       C = (z == 0) ? C0 : (z == 1) ? C1 : C2;
    tgemm_body<false, false>(As, Bs, A, B, nullptr, nullptr, C, M, N, K,
                             blockIdx.y * 128, blockIdx.x * 128);
}

// Fused stage-2 projections: z=0 -> Q2 (M=ROWS), z=1/2 -> K2/V2 (M=CROWS).
__global__ void __launch_bounds__(256, 2)
tgemm_s2_kernel(const float* __restrict__ Axn, const float* __restrict__ Actx,
                const float* __restrict__ Bq, const float* __restrict__ Bk,
                const float* __restrict__ Bv,
                float* __restrict__ Cq, float* __restrict__ Ck,
                float* __restrict__ Cv) {
    __shared__ uint32_t As[2 * 128 * APAD];
    __shared__ uint32_t Bs[2 * 32 * BPAD];
    const int z = blockIdx.z;
    if (z > 0 && (int)blockIdx.y * 128 >= CROWS) return;
    const float* A = (z == 0) ? Axn : Actx;
    const float* B = (z == 0) ? Bq : (z == 1) ? Bk : Bv;
    float*       C = (z == 0) ? Cq : (z == 1) ? Ck : Cv;
    const int    M = (z == 0) ? ROWS : CROWS;
    tgemm_body<false, false>(As, Bs, A, B, nullptr, nullptr, C, M, DIM, DIM,
                             blockIdx.y * 128, blockIdx.x * 128);
}

// ---------------- Flash self-attention on tensor cores (tf32) --------------
// grid (SEQ/128, B*H), 256 threads = 8 warps; warp owns 16 q-rows x 64 keys.
// K/V double-buffered via cp.async; B-fragment prefetch inside both GEMMs.
#define FS 68
#define VS 72
__global__ void __launch_bounds__(256)
flash_mma_kernel(const float* __restrict__ Q, const float* __restrict__ K,
                 const float* __restrict__ V, float* __restrict__ O) {
    extern __shared__ uint32_t sm[];
    uint32_t* QP = sm;                       // [128][FS] : Qs then Ps
    uint32_t* Ks = sm + 128 * FS;            // [2][64][FS]
    uint32_t* Vs = Ks + 2 * 64 * FS;         // [2][64][VS]

    const int bh = blockIdx.y;
    const int b = bh >> 3, h = bh & 7;
    const int q0 = blockIdx.x * 128;
    const int tid = threadIdx.x;
    const int lane = tid & 31;
    const int wid = tid >> 5;
    const int g = lane >> 2, tg = lane & 3;

    const uint32_t ksB = smem_u32(Ks);
    const uint32_t vsB = smem_u32(Vs);

    const int cli = tid >> 2;                // copy row 0..63
    const int cdb = (tid & 3) << 2;          // copy d base 0,4,8,12

    // ---- prologue: issue K/V copy for tile 0 ----
    {
        const size_t base = ((size_t)(b * SEQ + cli)) * DIM + h * HD;
        const uint32_t kd = ksB + (uint32_t)(cli * FS + cdb) * 4;
        const uint32_t vd = vsB + (uint32_t)(cli * VS + cdb) * 4;
        #pragma unroll
        for (int c = 0; c < 4; c++) {
            cp_async16(kd + 64u * c, &K[base + cdb + 16 * c]);
            cp_async16(vd + 64u * c, &V[base + cdb + 16 * c]);
        }
        CP_COMMIT();
    }

    // ---- stage Q tile to smem (scale folded; raw fp32 bits) ----
    {
        const int li = tid >> 1;             // 0..127 (warp-private band)
        const int db = (tid & 1) * 32;
        const float* qrow = &Q[((size_t)(b * SEQ + q0 + li)) * DIM + h * HD];
        #pragma unroll
        for (int c = 0; c < 8; c++) {
            const int d4 = db + 4 * c;
            const float4 qv = *(const float4*)&qrow[d4];
            uint4 u = make_uint4(__float_as_uint(qv.x * 0.125f),
                                 __float_as_uint(qv.y * 0.125f),
                                 __float_as_uint(qv.z * 0.125f),
                                 __float_as_uint(qv.w * 0.125f));
            *(uint4*)&QP[li * FS + d4] = u;
        }
    }
    __syncwarp();

    const int r0 = wid * 16 + g;
    uint32_t qf[8][4];
    #pragma unroll
    for (int ks = 0; ks < 8; ks++) {
        qf[ks][0] = QP[r0 * FS + ks * 8 + tg];
        qf[ks][1] = QP[(r0 + 8) * FS + ks * 8 + tg];
        qf[ks][2] = QP[r0 * FS + ks * 8 + tg + 4];
        qf[ks][3] = QP[(r0 + 8) * FS + ks * 8 + tg + 4];
    }

    float m0 = -1e30f, m1 = -1e30f, l0 = 0.f, l1 = 0.f;
    float oacc[8][4];
    #pragma unroll
    for (int nf = 0; nf < 8; nf++)
        #pragma unroll
        for (int c = 0; c < 4; c++) oacc[nf][c] = 0.f;

    const int T = SEQ / 64;
    for (int t = 0; t < T; t++) {
        CP_WAIT0();
        __syncthreads();   // tile t resident; prior tile's buffers free

        if (t + 1 < T) {   // issue copy for tile t+1 into alternate buffer
            const int nb = (t + 1) & 1;
            const size_t base = ((size_t)(b * SEQ + (t + 1) * 64 + cli)) * DIM + h * HD;
            const uint32_t kd = ksB + (uint32_t)(nb * 64 * FS + cli * FS + cdb) * 4;
            const uint32_t vd = vsB + (uint32_t)(nb * 64 * VS + cli * VS + cdb) * 4;
            #pragma unroll
            for (int c = 0; c < 4; c++) {
                cp_async16(kd + 64u * c, &K[base + cdb + 16 * c]);
                cp_async16(vd + 64u * c, &V[base + cdb + 16 * c]);
            }
            CP_COMMIT();
        }

        const uint32_t* Kb = Ks + (t & 1) * 64 * FS;
        const uint32_t* Vb = Vs + (t & 1) * 64 * VS;

        // ---- GEMM1: S[16x64] = Qw @ K^T (B-frag prefetch pipeline) ----
        float sacc[8][4];
        #pragma unroll
        for (int nf = 0; nf < 8; nf++)
            #pragma unroll
            for (int c = 0; c < 4; c++) sacc[nf][c] = 0.f;

        {
            uint32_t kf[2][2];
            { const int a = g * FS + tg; kf[0][0] = Kb[a]; kf[0][1] = Kb[a + 4]; }
            #pragma unroll
            for (int ks = 0; ks < 8; ks++) {
                #pragma unroll
                for (int nf = 0; nf < 8; nf++) {
                    const int cur = (ks * 8 + nf) & 1;
                    if (!(ks == 7 && nf == 7)) {
                        const int nn = (nf < 7) ? nf + 1 : 0;
                        const int kk = (nf < 7) ? ks : ks + 1;
                        const int a = (nn * 8 + g) * FS + kk * 8 + tg;
                        kf[cur ^ 1][0] = Kb[a];
                        kf[cur ^ 1][1] = Kb[a + 4];
                    }
                    MMA_TF32(sacc[nf], qf[ks][0], qf[ks][1], qf[ks][2], qf[ks][3],
                             kf[cur][0], kf[cur][1]);
                }
            }
        }

        // ---- online softmax ----
        float mx0 = -1e30f, mx1 = -1e30f;
        #pragma unroll
        for (int nf = 0; nf < 8; nf++) {
            mx0 = fmaxf(mx0, fmaxf(sacc[nf][0], sacc[nf][1]));
            mx1 = fmaxf(mx1, fmaxf(sacc[nf][2], sacc[nf][3]));
        }
        mx0 = fmaxf(mx0, __shfl_xor_sync(0xffffffffu, mx0, 1));
        mx0 = fmaxf(mx0, __shfl_xor_sync(0xffffffffu, mx0, 2));
        mx1 = fmaxf(mx1, __shfl_xor_sync(0xffffffffu, mx1, 1));
        mx1 = fmaxf(mx1, __shfl_xor_sync(0xffffffffu, mx1, 2));

        const float mn0 = fmaxf(m0, mx0);
        const float mn1 = fmaxf(m1, mx1);
        const float al0 = __expf(m0 - mn0);
        const float al1 = __expf(m1 - mn1);

        float rs0 = 0.f, rs1 = 0.f;
        #pragma unroll
        for (int nf = 0; nf < 8; nf++) {
            const float p00 = __expf(sacc[nf][0] - mn0);
            const float p01 = __expf(sacc[nf][1] - mn0);
            const float p10 = __expf(sacc[nf][2] - mn1);
            const float p11 = __expf(sacc[nf][3] - mn1);
            rs0 += p00 + p01;
            rs1 += p10 + p11;
            *(uint2*)&QP[r0 * FS + nf * 8 + 2 * tg] =
                make_uint2(__float_as_uint(p00), __float_as_uint(p01));
            *(uint2*)&QP[(r0 + 8) * FS + nf * 8 + 2 * tg] =
                make_uint2(__float_as_uint(p10), __float_as_uint(p11));
            oacc[nf][0] *= al0; oacc[nf][1] *= al0;
            oacc[nf][2] *= al1; oacc[nf][3] *= al1;
        }
        rs0 += __shfl_xor_sync(0xffffffffu, rs0, 1);
        rs0 += __shfl_xor_sync(0xffffffffu, rs0, 2);
        rs1 += __shfl_xor_sync(0xffffffffu, rs1, 1);
        rs1 += __shfl_xor_sync(0xffffffffu, rs1, 2);
        l0 = l0 * al0 + rs0;
        l1 = l1 * al1 + rs1;
        m0 = mn0; m1 = mn1;
        __syncwarp();   // P band is warp-private

        // ---- GEMM2: O += P @ V (V-frag prefetch pipeline) ----
        {
            uint32_t vf[2][2];
            { const int a = tg * VS + g; vf[0][0] = Vb[a]; vf[0][1] = Vb[a + 4 * VS]; }
            #pragma unroll
            for (int ks = 0; ks < 8; ks++) {
                const uint32_t a0 = QP[r0 * FS + ks * 8 + tg];
                const uint32_t a1 = QP[(r0 + 8) * FS + ks * 8 + tg];
                const uint32_t a2 = QP[r0 * FS + ks * 8 + tg + 4];
                const uint32_t a3 = QP[(r0 + 8) * FS + ks * 8 + tg + 4];
                #pragma unroll
                for (int nf = 0; nf < 8; nf++) {
                    const int cur = (ks * 8 + nf) & 1;
                    if (!(ks == 7 && nf == 7)) {
                        const int nn = (nf < 7) ? nf + 1 : 0;
                        const int kk = (nf < 7) ? ks : ks + 1;
                        const int a = (kk * 8 + tg) * VS + nn * 8 + g;
                        vf[cur ^ 1][0] = Vb[a];
                        vf[cur ^ 1][1] = Vb[a + 4 * VS];
                    }
                    MMA_TF32(oacc[nf], a0, a1, a2, a3, vf[cur][0], vf[cur][1]);
                }
            }
        }
    }

    const float inv0 = 1.0f / l0;
    const float inv1 = 1.0f / l1;
    const size_t base0 = ((size_t)(b * SEQ + q0 + r0)) * DIM + h * HD;
    const size_t base1 = ((size_t)(b * SEQ + q0 + r0 + 8)) * DIM + h * HD;
    #pragma unroll
    for (int nf = 0; nf < 8; nf++) {
        const int col = nf * 8 + 2 * tg;
        *(float2*)&O[base0 + col] = make_float2(oacc[nf][0] * inv0, oacc[nf][1] * inv0);
        *(float2*)&O[base1 + col] = make_float2(oacc[nf][2] * inv1, oacc[nf][3] * inv1);
    }
}

// --------------------------- Cross attention (T=77) ------------------------
__global__ void __launch_bounds__(256)
cross_attn_kernel(const float* __restrict__ Q, const float* __restrict__ K,
                  const float* __restrict__ V, float* __restrict__ O) {
    __shared__ float Ksm[CTXT][65];
    __shared__ float Vsm[CTXT][65];

    const int bh = blockIdx.y;
    const int b = bh >> 3, h = bh & 7;
    const int warp = threadIdx.x >> 5, lane = threadIdx.x & 31;

    for (int idx = threadIdx.x; idx < CTXT * HD; idx += 256) {
        const int j = idx >> 6, d = idx & 63;
        const size_t base = ((size_t)(b * CTXT + j)) * DIM + h * HD + d;
        Ksm[j][d] = K[base];
        Vsm[j][d] = V[base];
    }
    __syncthreads();

    const float scale = 0.125f;
    const int q_base = blockIdx.x * 64 + warp * 8;

    for (int qq = 0; qq < 8; qq++) {
        const int qi = q_base + qq;
        const float* qp = &Q[((size_t)(b * SEQ + qi)) * DIM + h * HD];
        const float q0v = qp[lane];
        const float q1v = qp[lane + 32];

        const int j0 = lane, j1 = lane + 32, j2 = lane + 64;
        float s0 = 0.f, s1 = 0.f, s2 = 0.f;
        #pragma unroll
        for (int d = 0; d < 32; d++) {
            const float qd = __shfl_sync(0xffffffffu, q0v, d);
            s0 = fmaf(qd, Ksm[j0][d], s0);
            s1 = fmaf(qd, Ksm[j1][d], s1);
            if (j2 < CTXT) s2 = fmaf(qd, Ksm[j2][d], s2);
        }
        #pragma unroll
        for (int d = 0; d < 32; d++) {
            const float qd = __shfl_sync(0xffffffffu, q1v, d);
            s0 = fmaf(qd, Ksm[j0][d + 32], s0);
            s1 = fmaf(qd, Ksm[j1][d + 32], s1);
            if (j2 < CTXT) s2 = fmaf(qd, Ksm[j2][d + 32], s2);
        }
        s0 *= scale; s1 *= scale;
        s2 = (j2 < CTXT) ? s2 * scale : -1e30f;

        float mx = fmaxf(fmaxf(s0, s1), s2);
        #pragma unroll
        for (int off = 16; off; off >>= 1)
            mx = fmaxf(mx, __shfl_xor_sync(0xffffffffu, mx, off));

        const float p0 = __expf(s0 - mx);
        const float p1 = __expf(s1 - mx);
        const float p2 = (j2 < CTXT) ? __expf(s2 - mx) : 0.f;
        float sum = p0 + p1 + p2;
        #pragma unroll
        for (int off = 16; off; off >>= 1)
            sum += __shfl_xor_sync(0xffffffffu, sum, off);

        float o0 = 0.f, o1 = 0.f;
        #pragma unroll
        for (int ll = 0; ll < 32; ll++) {
            const float pj = __shfl_sync(0xffffffffu, p0, ll);
            o0 = fmaf(pj, Vsm[ll][lane],      o0);
            o1 = fmaf(pj, Vsm[ll][lane + 32], o1);
        }
        #pragma unroll
        for (int ll = 0; ll < 32; ll++) {
            const float pj = __shfl_sync(0xffffffffu, p1, ll);
            o0 = fmaf(pj, Vsm[32 + ll][lane],      o0);
            o1 = fmaf(pj, Vsm[32 + ll][lane + 32], o1);
        }
        #pragma unroll
        for (int ll = 0; ll < 13; ll++) {
            const float pj = __shfl_sync(0xffffffffu, p2, ll);
            o0 = fmaf(pj, Vsm[64 + ll][lane],      o0);
            o1 = fmaf(pj, Vsm[64 + ll][lane + 32], o1);
        }

        const float inv = 1.0f / sum;
        float* op = &O[((size_t)(b * SEQ + qi)) * DIM + h * HD];
        op[lane]      = o0 * inv;
        op[lane + 32] = o1 * inv;
    }
}

// ------------------------------ GEGLU --------------------------------------
__global__ void geglu_kernel(const float* __restrict__ gg, float* __restrict__ ff) {
    const size_t idx = (size_t)blockIdx.x * 256 + threadIdx.x;
    const size_t mrow = idx >> 11;
    const int    n    = (int)(idx & 2047);
    const float y    = gg[mrow * 4096 + n];
    const float gate = gg[mrow * 4096 + 2048 + n];
    const float t = tanhf(gate * 0.7978845608f * (1.0f + 0.044715f * gate * gate));
    ff[idx] = y * 0.5f * gate * (1.0f + t);
}

// ------------------------------ launch -------------------------------------
extern "C" void kernel_launch(void* const* d_in, const int* in_sizes, int n_in,
                              void* d_out, int out_size) {
    (void)in_sizes; (void)n_in; (void)out_size;
    const float* x       = (const float*)d_in[0];
    const float* context = (const float*)d_in[1];
    const float* ln1_g   = (const float*)d_in[2];
    const float* ln1_b   = (const float*)d_in[3];
    const float* wq1     = (const float*)d_in[4];
    const float* wk1     = (const float*)d_in[5];
    const float* wv1     = (const float*)d_in[6];
    const float* wo1     = (const float*)d_in[7];
    const float* bo1     = (const float*)d_in[8];
    const float* ln2_g   = (const float*)d_in[9];
    const float* ln2_b   = (const float*)d_in[10];
    const float* wq2     = (const float*)d_in[11];
    const float* wk2     = (const float*)d_in[12];
    const float* wv2     = (const float*)d_in[13];
    const float* wo2     = (const float*)d_in[14];
    const float* bo2     = (const float*)d_in[15];
    const float* ln3_g   = (const float*)d_in[16];
    const float* ln3_b   = (const float*)d_in[17];
    const float* geglu_w = (const float*)d_in[18];
    const float* geglu_b = (const float*)d_in[19];
    const float* out_w   = (const float*)d_in[20];
    const float* out_b   = (const float*)d_in[21];
    float* out = (float*)d_out;

    float *xn, *q, *k, *v, *at, *h, *gg, *ff;
    cudaGetSymbolAddress((void**)&xn, g_xn);
    cudaGetSymbolAddress((void**)&q,  g_q);
    cudaGetSymbolAddress((void**)&k,  g_k);
    cudaGetSymbolAddress((void**)&v,  g_v);
    cudaGetSymbolAddress((void**)&at, g_at);
    cudaGetSymbolAddress((void**)&h,  g_h);
    cudaGetSymbolAddress((void**)&gg, g_gg);
    cudaGetSymbolAddress((void**)&ff, g_ff);

    const size_t fa_smem = (size_t)(128 * FS + 2 * 64 * FS + 2 * 64 * VS) * 4;
    cudaFuncSetAttribute(flash_mma_kernel,
                         cudaFuncAttributeMaxDynamicSharedMemorySize, (int)fa_smem);

    const dim3 blk(256);
    const dim3 gqkv(DIM / 128, ROWS / 128, 3);       // (4, 64, 3)
    const dim3 g512(DIM / 128, ROWS / 128);          // (4, 64)
    const dim3 g4096(4096 / 128, ROWS / 128);        // (32, 64)
    const dim3 gattn(SEQ / 128, BATCH * NH);         // (32, 16)
    const dim3 gxattn(SEQ / 64, BATCH * NH);         // (64, 16)

    // ---- stage 1: self-attention ----
    ln_kernel<<<ROWS, blk>>>(x, ln1_g, ln1_b, xn);
    tgemm_qkv_kernel<<<gqkv, blk>>>(xn, wq1, wk1, wv1, q, k, v, ROWS, DIM, DIM);
    flash_mma_kernel<<<gattn, blk, fa_smem>>>(q, k, v, at);
    tgemm_kernel<true, true><<<g512, blk>>>(at, wo1, bo1, x, h, ROWS, DIM, DIM);

    // ---- stage 2: cross-attention ----
    ln_kernel<<<ROWS, blk>>>(h, ln2_g, ln2_b, xn);
    tgemm_s2_kernel<<<gqkv, blk>>>(xn, context, wq2, wk2, wv2, q, k, v);
    cross_attn_kernel<<<gxattn, blk>>>(q, k, v, at);
    tgemm_kernel<true, true><<<g512, blk>>>(at, wo2, bo2, h, h, ROWS, DIM, DIM);

    // ---- stage 3: GEGLU FFN ----
    ln_kernel<<<ROWS, blk>>>(h, ln3_g, ln3_b, xn);
    tgemm_kernel<true, false><<<g4096, blk>>>(xn, geglu_w, geglu_b, nullptr, gg, ROWS, 4096, DIM);
    geglu_kernel<<<(ROWS * 2048) / 256, blk>>>(gg, ff);
    tgemm_kernel<true, true><<<g512, blk>>>(ff, out_w, out_b, h, out, ROWS, DIM, 2048);
}

// round 14
// speedup vs baseline: 3.8478x; 1.2696x over previous
#include <cuda_runtime.h>
#include <cuda.h>
#include <cuda_bf16.h>
#include <cstdint>

// ---------------------------------------------------------------------------
// BasicTransformerBlock (SD-style): self-attn + cross-attn + GEGLU.
// Dense GEMMs + self-attention on tensor cores (tf32 mma.sync, fp32 accum).
// ALL tile loads via TMA (UTMALDG) + mbarrier double buffering — removes the
// LDGSTS issue-rate ceiling (8 cyc/op) that bound rounds 11-13.
// B=2, S=4096, T=77, DIM=512, H=8, D=64.
// ---------------------------------------------------------------------------

#define BATCH 2
#define SEQ   4096
#define CTXT  77
#define DIM   512
#define NH    8
#define HD    64
#define ROWS  (BATCH * SEQ)      // 8192
#define CROWS (BATCH * CTXT)     // 154

// -------------------------- scratch (static, no allocs) --------------------
__device__ float g_xn[ROWS * DIM];
__device__ float g_q [ROWS * DIM];
__device__ float g_k [ROWS * DIM];
__device__ float g_v [ROWS * DIM];
__device__ float g_at[ROWS * DIM];
__device__ float g_h [ROWS * DIM];
__device__ float g_gg[(size_t)ROWS * 4096];
__device__ float g_ff[(size_t)ROWS * 2048];

#define MMA_TF32(acc, a0, a1, a2, a3, b0, b1)                                  \
    asm volatile(                                                              \
        "mma.sync.aligned.m16n8k8.row.col.f32.tf32.tf32.f32 "                  \
        "{%0,%1,%2,%3}, {%4,%5,%6,%7}, {%8,%9}, {%0,%1,%2,%3};\n"              \
        : "+f"(acc[0]), "+f"(acc[1]), "+f"(acc[2]), "+f"(acc[3])               \
        : "r"(a0), "r"(a1), "r"(a2), "r"(a3), "r"(b0), "r"(b1))

__device__ __forceinline__ uint32_t smem_u32(const void* p) {
    return (uint32_t)__cvta_generic_to_shared(p);
}

#define MBARRIER_INIT(addr, count)                                             \
    asm volatile("mbarrier.init.shared.b64 [%0], %1;"                          \
                 :: "r"(addr), "r"(count) : "memory")
#define MBARRIER_EXPECT_TX(addr, bytes)                                        \
    asm volatile("mbarrier.arrive.expect_tx.shared.b64 _, [%0], %1;"           \
                 :: "r"(addr), "r"(bytes) : "memory")

__device__ __forceinline__ void mbar_wait(uint32_t mbar, uint32_t phase) {
    asm volatile(
        "{\n\t.reg .pred P;\n\t"
        "WAIT_%=:\n\t"
        "mbarrier.try_wait.parity.acquire.cta.shared::cta.b64 P, [%0], %1, 0x989680;\n\t"
        "@!P bra WAIT_%=;\n\t}"
        :: "r"(mbar), "r"(phase) : "memory");
}

#define TMA2D(dst, map, x, y, mb)                                              \
    asm volatile(                                                              \
        "cp.async.bulk.tensor.2d.shared::cta.global.tile.mbarrier::complete_tx::bytes " \
        "[%0], [%1, {%2, %3}], [%4];"                                          \
        :: "r"(dst), "l"(map), "r"(x), "r"(y), "r"(mb) : "memory")

// ------------------------------ LayerNorm ----------------------------------
__global__ void ln_kernel(const float* __restrict__ in,
                          const float* __restrict__ gw,
                          const float* __restrict__ bw,
                          float* __restrict__ out) {
    const int row = blockIdx.x;
    const float* x = in + (size_t)row * DIM;
    const int t = threadIdx.x;

    float v0 = x[t];
    float v1 = x[t + 256];
    float s  = v0 + v1;
    float sq = v0 * v0 + v1 * v1;

    #pragma unroll
    for (int off = 16; off; off >>= 1) {
        s  += __shfl_xor_sync(0xffffffffu, s,  off);
        sq += __shfl_xor_sync(0xffffffffu, sq, off);
    }
    __shared__ float ss[8], sqs[8];
    if ((t & 31) == 0) { ss[t >> 5] = s; sqs[t >> 5] = sq; }
    __syncthreads();
    float S = 0.f, SQ = 0.f;
    #pragma unroll
    for (int w = 0; w < 8; w++) { S += ss[w]; SQ += sqs[w]; }

    const float mean = S * (1.0f / DIM);
    const float var  = SQ * (1.0f / DIM) - mean * mean;
    const float inv  = rsqrtf(var + 1e-5f);

    float* o = out + (size_t)row * DIM;
    o[t]       = (v0 - mean) * inv * gw[t]       + bw[t];
    o[t + 256] = (v1 - mean) * inv * gw[t + 256] + bw[t + 256];
}

// ---------------------- TF32 tensor-core GEMM (TMA) ------------------------
// 128x128x32 tile, 8 warps (2x4), warp tile 64x32, m16n8k8 tf32.
// A tile: one TMA box (32k x 128m), SW128 -> As[m][k'] at m*128B, swizzled.
// B tile: 4 TMA boxes (32n x 32k) -> Bs[chunk][k'][n'] 4KB chunks.
// smem per CTA: 2 stages x (16KB A + 16KB B) + 2 mbarriers + 1KB align pad.

// A frag: bank = (8ks|tg) ^ 4g -> conflict-free.
#define LOAD_AFR(dst, mf_, ks_) {                                              \
    const uint8_t* ap_ = asP + (wr * 64 + (mf_) * 16 + g) * 128;               \
    const int kb_ = ((ks_) * 8 + tg) * 4;                                      \
    const int gx_ = g << 4;                                                    \
    (dst)[0] = *(const uint32_t*)(ap_ + (kb_ ^ gx_));                          \
    (dst)[1] = *(const uint32_t*)(ap_ + 1024 + (kb_ ^ gx_));                   \
    (dst)[2] = *(const uint32_t*)(ap_ + ((kb_ + 16) ^ gx_));                   \
    (dst)[3] = *(const uint32_t*)(ap_ + 1024 + ((kb_ + 16) ^ gx_)); }
// B frag: 2-way conflict (inherent to SW128), negligible.
#define LOAD_BFR(dst, ks_) {                                                   \
    const uint8_t* b0_ = bsP + ((ks_) * 8 + tg) * 128;                         \
    const int tx0_ = tg << 4, tx1_ = (tg + 4) << 4;                            \
    _Pragma("unroll")                                                          \
    for (int nf_ = 0; nf_ < 4; nf_++) {                                        \
        const int nb_ = (nf_ * 8 + g) * 4;                                     \
        (dst)[2 * nf_]     = *(const uint32_t*)(b0_ + (nb_ ^ tx0_));           \
        (dst)[2 * nf_ + 1] = *(const uint32_t*)(b0_ + 512 + (nb_ ^ tx1_)); } }

template <bool HAS_BIAS, bool HAS_RES>
__device__ __forceinline__ void
tgemm_body(uint8_t* smraw, const CUtensorMap* mapA, const CUtensorMap* mapB,
           const float* __restrict__ bias, const float* __restrict__ Res,
           float* __restrict__ C, int M, int N, int K,
           int rowBase, int colBase) {
    const int tid  = threadIdx.x;
    const int lane = tid & 31;
    const int wid  = tid >> 5;
    const int wr   = wid >> 2;
    const int wc   = wid & 3;
    const int g    = lane >> 2;
    const int tg   = lane & 3;

    const uint32_t raw  = smem_u32(smraw);
    const uint32_t base = (raw + 1023) & ~1023u;
    uint8_t* bp = smraw + (base - raw);
    const uint32_t mbar = base + 65536;

    if (tid == 0) {
        MBARRIER_INIT(mbar, 1);
        MBARRIER_INIT(mbar + 8, 1);
    }
    __syncthreads();

    const int T = K >> 5;

    if (tid == 0) {
        #pragma unroll
        for (int s = 0; s < 2; s++) {
            const uint32_t mb = mbar + s * 8;
            MBARRIER_EXPECT_TX(mb, 32768);
            const int k0 = s << 5;
            TMA2D(base + s * 16384, mapA, k0, rowBase, mb);
            #pragma unroll
            for (int c = 0; c < 4; c++)
                TMA2D(base + 32768 + s * 16384 + c * 4096, mapB,
                      colBase + 32 * c, k0, mb);
        }
    }

    float acc[4][4][4];
    #pragma unroll
    for (int mf = 0; mf < 4; mf++)
        #pragma unroll
        for (int nf = 0; nf < 4; nf++)
            #pragma unroll
            for (int c = 0; c < 4; c++) acc[mf][nf][c] = 0.f;

    for (int t = 0; t < T; t++) {
        mbar_wait(mbar + (t & 1) * 8, (t >> 1) & 1);

        const uint8_t* asP = bp + (t & 1) * 16384;
        const uint8_t* bsP = bp + 32768 + (t & 1) * 16384 + wc * 4096;

        uint32_t afr[2][4], bfr[2][8];
        LOAD_BFR(bfr[0], 0);
        LOAD_AFR(afr[0], 0, 0);

        #pragma unroll
        for (int ks = 0; ks < 4; ks++) {
            const int kb = ks & 1;
            #pragma unroll
            for (int mf = 0; mf < 4; mf++) {
                const int cur = (ks * 4 + mf) & 1;
                const int nxt = cur ^ 1;
                if (mf < 3) {
                    LOAD_AFR(afr[nxt], mf + 1, ks);
                } else if (ks < 3) {
                    LOAD_AFR(afr[nxt], 0, ks + 1);
                    LOAD_BFR(bfr[kb ^ 1], ks + 1);
                }
                #pragma unroll
                for (int nf = 0; nf < 4; nf++)
                    MMA_TF32(acc[mf][nf],
                             afr[cur][0], afr[cur][1], afr[cur][2], afr[cur][3],
                             bfr[kb][2 * nf], bfr[kb][2 * nf + 1]);
            }
        }

        __syncthreads();   // all warps done with stage (t&1)
        if (t + 2 < T && tid == 0) {
            const int s = t & 1;
            const uint32_t mb = mbar + s * 8;
            MBARRIER_EXPECT_TX(mb, 32768);
            const int k0 = (t + 2) << 5;
            TMA2D(base + s * 16384, mapA, k0, rowBase, mb);
            #pragma unroll
            for (int c = 0; c < 4; c++)
                TMA2D(base + 32768 + s * 16384 + c * 4096, mapB,
                      colBase + 32 * c, k0, mb);
        }
    }

    #pragma unroll
    for (int mf = 0; mf < 4; mf++) {
        #pragma unroll
        for (int half = 0; half < 2; half++) {
            const int row = rowBase + wr * 64 + mf * 16 + g + 8 * half;
            if (row >= M) continue;
            #pragma unroll
            for (int nf = 0; nf < 4; nf++) {
                const int col = colBase + wc * 32 + nf * 8 + 2 * tg;
                float2 v = half ? make_float2(acc[mf][nf][2], acc[mf][nf][3])
                                : make_float2(acc[mf][nf][0], acc[mf][nf][1]);
                if (HAS_BIAS) {
                    const float2 bv = *(const float2*)&bias[col];
                    v.x += bv.x; v.y += bv.y;
                }
                if (HAS_RES) {
                    const float2 rv = *(const float2*)&Res[(size_t)row * N + col];
                    v.x += rv.x; v.y += rv.y;
                }
                *(float2*)&C[(size_t)row * N + col] = v;
            }
        }
    }
}

#define TG_SMEM (65536 + 16 + 1024)

template <bool HAS_BIAS, bool HAS_RES>
__global__ void __launch_bounds__(256, 2)
tgemm_kernel(const __grid_constant__ CUtensorMap mA,
             const __grid_constant__ CUtensorMap mB,
             const float* __restrict__ bias, const float* __restrict__ Res,
             float* __restrict__ C, int M, int N, int K) {
    __shared__ uint8_t smraw[TG_SMEM];
    tgemm_body<HAS_BIAS, HAS_RES>(smraw, &mA, &mB, bias, Res, C, M, N, K,
                                  blockIdx.y * 128, blockIdx.x * 128);
}

// Fused QKV: one launch, blockIdx.z selects weight/output (shared A).
__global__ void __launch_bounds__(256, 2)
tgemm_qkv_kernel(const __grid_constant__ CUtensorMap mA,
                 const __grid_constant__ CUtensorMap mB0,
                 const __grid_constant__ CUtensorMap mB1,
                 const __grid_constant__ CUtensorMap mB2,
                 float* __restrict__ C0, float* __restrict__ C1,
                 float* __restrict__ C2, int M, int N, int K) {
    __shared__ uint8_t smraw[TG_SMEM];
    const int z = blockIdx.z;
    const CUtensorMap* mB = (z == 0) ? &mB0 : (z == 1) ? &mB1 : &mB2;
    float* C = (z == 0) ? C0 : (z == 1) ? C1 : C2;
    tgemm_body<false, false>(smraw, &mA, mB, nullptr, nullptr, C, M, N, K,
                             blockIdx.y * 128, blockIdx.x * 128);
}

// Fused stage-2 projections: z=0 -> Q2 (M=ROWS), z=1/2 -> K2/V2 (M=CROWS).
__global__ void __launch_bounds__(256, 2)
tgemm_s2_kernel(const __grid_constant__ CUtensorMap mAxn,
                const __grid_constant__ CUtensorMap mActx,
                const __grid_constant__ CUtensorMap mBq,
                const __grid_constant__ CUtensorMap mBk,
                const __grid_constant__ CUtensorMap mBv,
                float* __restrict__ Cq, float* __restrict__ Ck,
                float* __restrict__ Cv) {
    __shared__ uint8_t smraw[TG_SMEM];
    const int z = blockIdx.z;
    if (z > 0 && (int)blockIdx.y * 128 >= CROWS) return;
    const CUtensorMap* mA = (z == 0) ? &mAxn : &mActx;
    const CUtensorMap* mB = (z == 0) ? &mBq : (z == 1) ? &mBk : &mBv;
    float* C = (z == 0) ? Cq : (z == 1) ? Ck : Cv;
    const int M = (z == 0) ? ROWS : CROWS;
    tgemm_body<false, false>(smraw, mA, mB, nullptr, nullptr, C, M, DIM, DIM,
                             blockIdx.y * 128, blockIdx.x * 128);
}

// ---------------- Flash self-attention on tensor cores (tf32) --------------
// grid (SEQ/128, B*H), 256 threads = 8 warps; warp owns 16 q-rows x 64 keys.
// K/V tiles via TMA (2 SW128 boxes of 32d x 64keys each), double-buffered.
// smem: Ks 2x16KB | Vs 2x16KB | QP 128x68 words | 2 mbarriers (+1KB pad).
#define FS 68
#define KFRAG(dst, ks_, nf_) {                                                 \
    const uint8_t* p_ = ksP + (((ks_) >= 4) ? 8192 : 0) + ((nf_) * 8 + g) * 128; \
    const int d4_ = (((ks_) & 3) * 8 + tg) * 4;                                \
    const int gx_ = g << 4;                                                    \
    (dst)[0] = *(const uint32_t*)(p_ + (d4_ ^ gx_));                           \
    (dst)[1] = *(const uint32_t*)(p_ + ((d4_ + 16) ^ gx_)); }
#define VFRAG(dst, ks_, nf_) {                                                 \
    const uint8_t* p_ = vsP + (((nf_) >= 4) ? 8192 : 0) + ((ks_) * 8 + tg) * 128; \
    const int d4_ = (((nf_) & 3) * 8 + g) * 4;                                 \
    (dst)[0] = *(const uint32_t*)(p_ + (d4_ ^ (tg << 4)));                     \
    (dst)[1] = *(const uint32_t*)(p_ + 512 + (d4_ ^ ((tg + 4) << 4))); }

__global__ void __launch_bounds__(256)
flash_mma_kernel(const __grid_constant__ CUtensorMap mK,
                 const __grid_constant__ CUtensorMap mV,
                 const float* __restrict__ Q, float* __restrict__ O) {
    extern __shared__ uint8_t fsm[];
    const uint32_t raw  = smem_u32(fsm);
    const uint32_t base = (raw + 1023) & ~1023u;
    uint8_t* bp = fsm + (base - raw);
    uint32_t* QP = (uint32_t*)(bp + 65536);       // [128][FS]
    const uint32_t mbar = base + 65536 + 34816;

    const int bh = blockIdx.y;
    const int b = bh >> 3, h = bh & 7;
    const int q0 = blockIdx.x * 128;
    const int tid = threadIdx.x;
    const int lane = tid & 31;
    const int wid = tid >> 5;
    const int g = lane >> 2, tg = lane & 3;

    if (tid == 0) {
        MBARRIER_INIT(mbar, 1);
        MBARRIER_INIT(mbar + 8, 1);
    }
    __syncthreads();

    // ---- prologue: TMA for tiles 0,1 ----
    if (tid == 0) {
        #pragma unroll
        for (int s = 0; s < 2; s++) {
            const uint32_t mb = mbar + s * 8;
            MBARRIER_EXPECT_TX(mb, 32768);
            const int y = b * SEQ + s * 64;
            #pragma unroll
            for (int c = 0; c < 2; c++) {
                TMA2D(base + s * 16384 + c * 8192,         &mK, h * HD + 32 * c, y, mb);
                TMA2D(base + 32768 + s * 16384 + c * 8192, &mV, h * HD + 32 * c, y, mb);
            }
        }
    }

    // ---- stage Q tile to smem (scale folded; raw fp32 bits) ----
    {
        const int li = tid >> 1;             // 0..127 (warp-private band)
        const int db = (tid & 1) * 32;
        const float* qrow = &Q[((size_t)(b * SEQ + q0 + li)) * DIM + h * HD];
        #pragma unroll
        for (int c = 0; c < 8; c++) {
            const int d4 = db + 4 * c;
            const float4 qv = *(const float4*)&qrow[d4];
            uint4 u = make_uint4(__float_as_uint(qv.x * 0.125f),
                                 __float_as_uint(qv.y * 0.125f),
                                 __float_as_uint(qv.z * 0.125f),
                                 __float_as_uint(qv.w * 0.125f));
            *(uint4*)&QP[li * FS + d4] = u;
        }
    }
    __syncwarp();

    const int r0 = wid * 16 + g;
    uint32_t qf[8][4];
    #pragma unroll
    for (int ks = 0; ks < 8; ks++) {
        qf[ks][0] = QP[r0 * FS + ks * 8 + tg];
        qf[ks][1] = QP[(r0 + 8) * FS + ks * 8 + tg];
        qf[ks][2] = QP[r0 * FS + ks * 8 + tg + 4];
        qf[ks][3] = QP[(r0 + 8) * FS + ks * 8 + tg + 4];
    }

    float m0 = -1e30f, m1 = -1e30f, l0 = 0.f, l1 = 0.f;
    float oacc[8][4];
    #pragma unroll
    for (int nf = 0; nf < 8; nf++)
        #pragma unroll
        for (int c = 0; c < 4; c++) oacc[nf][c] = 0.f;

    const int T = SEQ / 64;
    for (int t = 0; t < T; t++) {
        mbar_wait(mbar + (t & 1) * 8, (t >> 1) & 1);

        const uint8_t* ksP = bp + (t & 1) * 16384;
        const uint8_t* vsP = bp + 32768 + (t & 1) * 16384;

        // ---- GEMM1: S[16x64] = Qw @ K^T (frag prefetch pipeline) ----
        float sacc[8][4];
        #pragma unroll
        for (int nf = 0; nf < 8; nf++)
            #pragma unroll
            for (int c = 0; c < 4; c++) sacc[nf][c] = 0.f;

        {
            uint32_t kf[2][2];
            KFRAG(kf[0], 0, 0);
            #pragma unroll
            for (int ks = 0; ks < 8; ks++) {
                #pragma unroll
                for (int nf = 0; nf < 8; nf++) {
                    const int cur = (ks * 8 + nf) & 1;
                    if (!(ks == 7 && nf == 7)) {
                        const int nn = (nf < 7) ? nf + 1 : 0;
                        const int kk = (nf < 7) ? ks : ks + 1;
                        KFRAG(kf[cur ^ 1], kk, nn);
                    }
                    MMA_TF32(sacc[nf], qf[ks][0], qf[ks][1], qf[ks][2], qf[ks][3],
                             kf[cur][0], kf[cur][1]);
                }
            }
        }

        // ---- online softmax ----
        float mx0 = -1e30f, mx1 = -1e30f;
        #pragma unroll
        for (int nf = 0; nf < 8; nf++) {
            mx0 = fmaxf(mx0, fmaxf(sacc[nf][0], sacc[nf][1]));
            mx1 = fmaxf(mx1, fmaxf(sacc[nf][2], sacc[nf][3]));
        }
        mx0 = fmaxf(mx0, __shfl_xor_sync(0xffffffffu, mx0, 1));
        mx0 = fmaxf(mx0, __shfl_xor_sync(0xffffffffu, mx0, 2));
        mx1 = fmaxf(mx1, __shfl_xor_sync(0xffffffffu, mx1, 1));
        mx1 = fmaxf(mx1, __shfl_xor_sync(0xffffffffu, mx1, 2));

        const float mn0 = fmaxf(m0, mx0);
        const float mn1 = fmaxf(m1, mx1);
        const float al0 = __expf(m0 - mn0);
        const float al1 = __expf(m1 - mn1);

        float rs0 = 0.f, rs1 = 0.f;
        #pragma unroll
        for (int nf = 0; nf < 8; nf++) {
            const float p00 = __expf(sacc[nf][0] - mn0);
            const float p01 = __expf(sacc[nf][1] - mn0);
            const float p10 = __expf(sacc[nf][2] - mn1);
            const float p11 = __expf(sacc[nf][3] - mn1);
            rs0 += p00 + p01;
            rs1 += p10 + p11;
            *(uint2*)&QP[r0 * FS + nf * 8 + 2 * tg] =
                make_uint2(__float_as_uint(p00), __float_as_uint(p01));
            *(uint2*)&QP[(r0 + 8) * FS + nf * 8 + 2 * tg] =
                make_uint2(__float_as_uint(p10), __float_as_uint(p11));
            oacc[nf][0] *= al0; oacc[nf][1] *= al0;
            oacc[nf][2] *= al1; oacc[nf][3] *= al1;
        }
        rs0 += __shfl_xor_sync(0xffffffffu, rs0, 1);
        rs0 += __shfl_xor_sync(0xffffffffu, rs0, 2);
        rs1 += __shfl_xor_sync(0xffffffffu, rs1, 1);
        rs1 += __shfl_xor_sync(0xffffffffu, rs1, 2);
        l0 = l0 * al0 + rs0;
        l1 = l1 * al1 + rs1;
        m0 = mn0; m1 = mn1;
        __syncwarp();   // P band is warp-private

        // ---- GEMM2: O += P @ V (frag prefetch pipeline) ----
        {
            uint32_t vf[2][2];
            VFRAG(vf[0], 0, 0);
            #pragma unroll
            for (int ks = 0; ks < 8; ks++) {
                const uint32_t a0 = QP[r0 * FS + ks * 8 + tg];
                const uint32_t a1 = QP[(r0 + 8) * FS + ks * 8 + tg];
                const uint32_t a2 = QP[r0 * FS + ks * 8 + tg + 4];
                const uint32_t a3 = QP[(r0 + 8) * FS + ks * 8 + tg + 4];
                #pragma unroll
                for (int nf = 0; nf < 8; nf++) {
                    const int cur = (ks * 8 + nf) & 1;
                    if (!(ks == 7 && nf == 7)) {
                        const int nn = (nf < 7) ? nf + 1 : 0;
                        const int kk = (nf < 7) ? ks : ks + 1;
                        VFRAG(vf[cur ^ 1], kk, nn);
                    }
                    MMA_TF32(oacc[nf], a0, a1, a2, a3, vf[cur][0], vf[cur][1]);
                }
            }
        }

        __syncthreads();   // all warps done with stage (t&1)
        if (t + 2 < T && tid == 0) {
            const int s = t & 1;
            const uint32_t mb = mbar + s * 8;
            MBARRIER_EXPECT_TX(mb, 32768);
            const int y = b * SEQ + (t + 2) * 64;
            #pragma unroll
            for (int c = 0; c < 2; c++) {
                TMA2D(base + s * 16384 + c * 8192,         &mK, h * HD + 32 * c, y, mb);
                TMA2D(base + 32768 + s * 16384 + c * 8192, &mV, h * HD + 32 * c, y, mb);
            }
        }
    }

    const float inv0 = 1.0f / l0;
    const float inv1 = 1.0f / l1;
    const size_t base0 = ((size_t)(b * SEQ + q0 + r0)) * DIM + h * HD;
    const size_t base1 = ((size_t)(b * SEQ + q0 + r0 + 8)) * DIM + h * HD;
    #pragma unroll
    for (int nf = 0; nf < 8; nf++) {
        const int col = nf * 8 + 2 * tg;
        *(float2*)&O[base0 + col] = make_float2(oacc[nf][0] * inv0, oacc[nf][1] * inv0);
        *(float2*)&O[base1 + col] = make_float2(oacc[nf][2] * inv1, oacc[nf][3] * inv1);
    }
}

// --------------------------- Cross attention (T=77) ------------------------
__global__ void __launch_bounds__(256)
cross_attn_kernel(const float* __restrict__ Q, const float* __restrict__ K,
                  const float* __restrict__ V, float* __restrict__ O) {
    __shared__ float Ksm[CTXT][65];
    __shared__ float Vsm[CTXT][65];

    const int bh = blockIdx.y;
    const int b = bh >> 3, h = bh & 7;
    const int warp = threadIdx.x >> 5, lane = threadIdx.x & 31;

    for (int idx = threadIdx.x; idx < CTXT * HD; idx += 256) {
        const int j = idx >> 6, d = idx & 63;
        const size_t base = ((size_t)(b * CTXT + j)) * DIM + h * HD + d;
        Ksm[j][d] = K[base];
        Vsm[j][d] = V[base];
    }
    __syncthreads();

    const float scale = 0.125f;
    const int q_base = blockIdx.x * 64 + warp * 8;

    for (int qq = 0; qq < 8; qq++) {
        const int qi = q_base + qq;
        const float* qp = &Q[((size_t)(b * SEQ + qi)) * DIM + h * HD];
        const float q0v = qp[lane];
        const float q1v = qp[lane + 32];

        const int j0 = lane, j1 = lane + 32, j2 = lane + 64;
        float s0 = 0.f, s1 = 0.f, s2 = 0.f;
        #pragma unroll
        for (int d = 0; d < 32; d++) {
            const float qd = __shfl_sync(0xffffffffu, q0v, d);
            s0 = fmaf(qd, Ksm[j0][d], s0);
            s1 = fmaf(qd, Ksm[j1][d], s1);
            if (j2 < CTXT) s2 = fmaf(qd, Ksm[j2][d], s2);
        }
        #pragma unroll
        for (int d = 0; d < 32; d++) {
            const float qd = __shfl_sync(0xffffffffu, q1v, d);
            s0 = fmaf(qd, Ksm[j0][d + 32], s0);
            s1 = fmaf(qd, Ksm[j1][d + 32], s1);
            if (j2 < CTXT) s2 = fmaf(qd, Ksm[j2][d + 32], s2);
        }
        s0 *= scale; s1 *= scale;
        s2 = (j2 < CTXT) ? s2 * scale : -1e30f;

        float mx = fmaxf(fmaxf(s0, s1), s2);
        #pragma unroll
        for (int off = 16; off; off >>= 1)
            mx = fmaxf(mx, __shfl_xor_sync(0xffffffffu, mx, off));

        const float p0 = __expf(s0 - mx);
        const float p1 = __expf(s1 - mx);
        const float p2 = (j2 < CTXT) ? __expf(s2 - mx) : 0.f;
        float sum = p0 + p1 + p2;
        #pragma unroll
        for (int off = 16; off; off >>= 1)
            sum += __shfl_xor_sync(0xffffffffu, sum, off);

        float o0 = 0.f, o1 = 0.f;
        #pragma unroll
        for (int ll = 0; ll < 32; ll++) {
            const float pj = __shfl_sync(0xffffffffu, p0, ll);
            o0 = fmaf(pj, Vsm[ll][lane],      o0);
            o1 = fmaf(pj, Vsm[ll][lane + 32], o1);
        }
        #pragma unroll
        for (int ll = 0; ll < 32; ll++) {
            const float pj = __shfl_sync(0xffffffffu, p1, ll);
            o0 = fmaf(pj, Vsm[32 + ll][lane],      o0);
            o1 = fmaf(pj, Vsm[32 + ll][lane + 32], o1);
        }
        #pragma unroll
        for (int ll = 0; ll < 13; ll++) {
            const float pj = __shfl_sync(0xffffffffu, p2, ll);
            o0 = fmaf(pj, Vsm[64 + ll][lane],      o0);
            o1 = fmaf(pj, Vsm[64 + ll][lane + 32], o1);
        }

        const float inv = 1.0f / sum;
        float* op = &O[((size_t)(b * SEQ + qi)) * DIM + h * HD];
        op[lane]      = o0 * inv;
        op[lane + 32] = o1 * inv;
    }
}

// ------------------------------ GEGLU --------------------------------------
__global__ void geglu_kernel(const float* __restrict__ gg, float* __restrict__ ff) {
    const size_t idx = (size_t)blockIdx.x * 256 + threadIdx.x;
    const size_t mrow = idx >> 11;
    const int    n    = (int)(idx & 2047);
    const float y    = gg[mrow * 4096 + n];
    const float gate = gg[mrow * 4096 + 2048 + n];
    const float t = tanhf(gate * 0.7978845608f * (1.0f + 0.044715f * gate * gate));
    ff[idx] = y * 0.5f * gate * (1.0f + t);
}

// ------------------------------ host helpers --------------------------------
typedef CUresult (*TmEncodeFn)(CUtensorMap*, CUtensorMapDataType, cuuint32_t,
                               void*, const cuuint64_t*, const cuuint64_t*,
                               const cuuint32_t*, const cuuint32_t*,
                               CUtensorMapInterleave, CUtensorMapSwizzle,
                               CUtensorMapL2promotion, CUtensorMapFloatOOBfill);

static void build_map(TmEncodeFn enc, CUtensorMap* m, const void* ptr,
                      unsigned long long d0, unsigned long long d1,
                      unsigned b0, unsigned b1) {
    cuuint64_t dims[2]    = {d0, d1};
    cuuint64_t strides[1] = {d0 * 4};
    cuuint32_t box[2]     = {b0, b1};
    cuuint32_t es[2]      = {1, 1};
    enc(m, CU_TENSOR_MAP_DATA_TYPE_FLOAT32, 2, const_cast<void*>(ptr),
        dims, strides, box, es, CU_TENSOR_MAP_INTERLEAVE_NONE,
        CU_TENSOR_MAP_SWIZZLE_128B, CU_TENSOR_MAP_L2_PROMOTION_L2_128B,
        CU_TENSOR_MAP_FLOAT_OOB_FILL_NONE);
}

// ------------------------------ launch -------------------------------------
extern "C" void kernel_launch(void* const* d_in, const int* in_sizes, int n_in,
                              void* d_out, int out_size) {
    (void)in_sizes; (void)n_in; (void)out_size;
    const float* x       = (const float*)d_in[0];
    const float* context = (const float*)d_in[1];
    const float* ln1_g   = (const float*)d_in[2];
    const float* ln1_b   = (const float*)d_in[3];
    const float* wq1     = (const float*)d_in[4];
    const float* wk1     = (const float*)d_in[5];
    const float* wv1     = (const float*)d_in[6];
    const float* wo1     = (const float*)d_in[7];
    const float* bo1     = (const float*)d_in[8];
    const float* ln2_g   = (const float*)d_in[9];
    const float* ln2_b   = (const float*)d_in[10];
    const float* wq2     = (const float*)d_in[11];
    const float* wk2     = (const float*)d_in[12];
    const float* wv2     = (const float*)d_in[13];
    const float* wo2     = (const float*)d_in[14];
    const float* bo2     = (const float*)d_in[15];
    const float* ln3_g   = (const float*)d_in[16];
    const float* ln3_b   = (const float*)d_in[17];
    const float* geglu_w = (const float*)d_in[18];
    const float* geglu_b = (const float*)d_in[19];
    const float* out_w   = (const float*)d_in[20];
    const float* out_b   = (const float*)d_in[21];
    float* out = (float*)d_out;

    float *xn, *q, *k, *v, *at, *h, *gg, *ff;
    cudaGetSymbolAddress((void**)&xn, g_xn);
    cudaGetSymbolAddress((void**)&q,  g_q);
    cudaGetSymbolAddress((void**)&k,  g_k);
    cudaGetSymbolAddress((void**)&v,  g_v);
    cudaGetSymbolAddress((void**)&at, g_at);
    cudaGetSymbolAddress((void**)&h,  g_h);
    cudaGetSymbolAddress((void**)&gg, g_gg);
    cudaGetSymbolAddress((void**)&ff, g_ff);

    // tensormap encode via driver entry point (no libcuda link needed)
    void* encp = nullptr;
    cudaDriverEntryPointQueryResult qres;
    cudaGetDriverEntryPoint("cuTensorMapEncodeTiled", &encp,
                            cudaEnableDefault, &qres);
    TmEncodeFn enc = (TmEncodeFn)encp;

    // A maps: dims (K, M), box (32, 128)
    CUtensorMap mXn, mAt, mCtx, mFf;
    build_map(enc, &mXn,  xn,      512,  ROWS,  32, 128);
    build_map(enc, &mAt,  at,      512,  ROWS,  32, 128);
    build_map(enc, &mCtx, context, 512,  CROWS, 32, 128);
    build_map(enc, &mFf,  ff,      2048, ROWS,  32, 128);
    // B maps: dims (N, K), box (32, 32)
    CUtensorMap mWq1, mWk1, mWv1, mWo1, mWq2, mWk2, mWv2, mWo2, mWgg, mWout;
    build_map(enc, &mWq1, wq1,     512,  512,  32, 32);
    build_map(enc, &mWk1, wk1,     512,  512,  32, 32);
    build_map(enc, &mWv1, wv1,     512,  512,  32, 32);
    build_map(enc, &mWo1, wo1,     512,  512,  32, 32);
    build_map(enc, &mWq2, wq2,     512,  512,  32, 32);
    build_map(enc, &mWk2, wk2,     512,  512,  32, 32);
    build_map(enc, &mWv2, wv2,     512,  512,  32, 32);
    build_map(enc, &mWo2, wo2,     512,  512,  32, 32);
    build_map(enc, &mWgg, geglu_w, 4096, 512,  32, 32);
    build_map(enc, &mWout, out_w,  512,  2048, 32, 32);
    // flash K/V maps: dims (DIM, ROWS), box (32, 64)
    CUtensorMap mKt, mVt;
    build_map(enc, &mKt, k, 512, ROWS, 32, 64);
    build_map(enc, &mVt, v, 512, ROWS, 32, 64);

    // flash dyn smem: Ks 32KB + Vs 32KB + QP 34816 + mbar 16 + pad 1024
    const size_t fa_smem = 65536 + 34816 + 16 + 1024;
    cudaFuncSetAttribute(flash_mma_kernel,
                         cudaFuncAttributeMaxDynamicSharedMemorySize, (int)fa_smem);

    const dim3 blk(256);
    const dim3 gqkv(DIM / 128, ROWS / 128, 3);       // (4, 64, 3)
    const dim3 g512(DIM / 128, ROWS / 128);          // (4, 64)
    const dim3 g4096(4096 / 128, ROWS / 128);        // (32, 64)
    const dim3 gattn(SEQ / 128, BATCH * NH);         // (32, 16)
    const dim3 gxattn(SEQ / 64, BATCH * NH);         // (64, 16)

    // ---- stage 1: self-attention ----
    ln_kernel<<<ROWS, blk>>>(x, ln1_g, ln1_b, xn);
    tgemm_qkv_kernel<<<gqkv, blk>>>(mXn, mWq1, mWk1, mWv1, q, k, v, ROWS, DIM, DIM);
    flash_mma_kernel<<<gattn, blk, fa_smem>>>(mKt, mVt, q, at);
    tgemm_kernel<true, true><<<g512, blk>>>(mAt, mWo1, bo1, x, h, ROWS, DIM, DIM);

    // ---- stage 2: cross-attention ----
    ln_kernel<<<ROWS, blk>>>(h, ln2_g, ln2_b, xn);
    tgemm_s2_kernel<<<gqkv, blk>>>(mXn, mCtx, mWq2, mWk2, mWv2, q, k, v);
    cross_attn_kernel<<<gxattn, blk>>>(q, k, v, at);
    tgemm_kernel<true, true><<<g512, blk>>>(mAt, mWo2, bo2, h, h, ROWS, DIM, DIM);

    // ---- stage 3: GEGLU FFN ----
    ln_kernel<<<ROWS, blk>>>(h, ln3_g, ln3_b, xn);
    tgemm_kernel<true, false><<<g4096, blk>>>(mXn, mWgg, geglu_b, nullptr, gg, ROWS, 4096, DIM);
    geglu_kernel<<<(ROWS * 2048) / 256, blk>>>(gg, ff);
    tgemm_kernel<true, true><<<g512, blk>>>(mFf, mWout, out_b, h, out, ROWS, DIM, 2048);
}